// round 10
// baseline (speedup 1.0000x reference)
#include <cuda_runtime.h>
#include <cuda_bf16.h>
#include <cstdint>

#define Bq 2
#define Sq 2048
#define Rq 128
#define Eq 2048
#define Hq 16
#define Dq 128
#define Lq (Sq + Rq)   // 2176

// ---------------- scratch (device globals, no allocations) ----------------
__device__ __nv_bfloat16 g_xbf[(size_t)Bq * Sq * Eq];      // quantized acts as bf16 ints
__device__ __nv_bfloat16 g_wbf[3][(size_t)Eq * Eq];        // ternary weights as bf16
__device__ __nv_bfloat16 g_rt3[(size_t)Bq * Rq * 3 * Eq];  // reasoning tokens split [hi|hi|lo]
__device__ __nv_bfloat16 g_kw3[(size_t)Eq * 3 * Eq];       // k_w split [hi|lo|hi]
__device__ __nv_bfloat16 g_vw3[(size_t)Eq * 3 * Eq];       // v_w split
__device__ __nv_bfloat16 g_ow3[(size_t)Eq * 3 * Eq];       // out_w split
__device__ __nv_bfloat16 g_ao3[(size_t)Bq * Sq * 3 * Eq];  // attn out split [hi|hi|lo]
__device__ __nv_bfloat16 g_qh[(size_t)Bq * Sq * Eq];       // Q hi
__device__ __nv_bfloat16 g_ql[(size_t)Bq * Sq * Eq];       // Q lo
__device__ __nv_bfloat16 g_kh[(size_t)Bq * Lq * Eq];       // K hi
__device__ __nv_bfloat16 g_kl[(size_t)Bq * Lq * Eq];       // K lo
__device__ __nv_bfloat16 g_vth[(size_t)Bq * Hq * Dq * Lq]; // V^T hi [B,H,D,L]
__device__ __nv_bfloat16 g_vtl[(size_t)Bq * Hq * Dq * Lq]; // V^T lo
__device__ float g_rows[(size_t)Bq * Sq];                  // per-row act scale s
__device__ float g_vb[(size_t)Bq * Lq * Eq];               // V fp32
__device__ float g_part[3 * 1024];
__device__ float g_scale[3];

// ---------------- PTX helpers ----------------
typedef unsigned long long ull;
__device__ __forceinline__ uint32_t smem_u32(const void* p) {
    uint32_t a;
    asm("{ .reg .u64 t; cvta.to.shared.u64 t, %1; cvt.u32.u64 %0, t; }" : "=r"(a) : "l"(p));
    return a;
}
__device__ __forceinline__ void ldmx4(uint32_t* r, uint32_t addr) {
    asm volatile("ldmatrix.sync.aligned.m8n8.x4.shared.b16 {%0,%1,%2,%3}, [%4];"
                 : "=r"(r[0]), "=r"(r[1]), "=r"(r[2]), "=r"(r[3]) : "r"(addr));
}
__device__ __forceinline__ void mma16816(float* c, const uint32_t* a, const uint32_t* b) {
    asm volatile("mma.sync.aligned.m16n8k16.row.col.f32.bf16.bf16.f32 "
                 "{%0,%1,%2,%3}, {%4,%5,%6,%7}, {%8,%9}, {%0,%1,%2,%3};"
                 : "+f"(c[0]), "+f"(c[1]), "+f"(c[2]), "+f"(c[3])
                 : "r"(a[0]), "r"(a[1]), "r"(a[2]), "r"(a[3]), "r"(b[0]), "r"(b[1]));
}
__device__ __forceinline__ void cpa16(uint32_t dst, const void* src) {
    asm volatile("cp.async.cg.shared.global [%0], [%1], 16;" :: "r"(dst), "l"(src) : "memory");
}
__device__ __forceinline__ void cpa_commit() {
    asm volatile("cp.async.commit_group;" ::: "memory");
}
__device__ __forceinline__ void cpa_wait0() {
    asm volatile("cp.async.wait_group 0;" ::: "memory");
}
__device__ __forceinline__ void cpa_wait1() {
    asm volatile("cp.async.wait_group 1;" ::: "memory");
}
// smem rows of 32 bf16 (64B); 16B group g stored at g ^ ((row>>1)&3)
__device__ __forceinline__ uint32_t swoff(int r, int g) {
    return (uint32_t)(r * 64 + ((g ^ ((r >> 1) & 3)) << 4));
}
// per-lane address offset for B-side ldmatrix.x4 (2 consecutive n-frags of 8 rows)
__device__ __forceinline__ uint32_t boff4(int base_row, int lane) {
    int r = base_row + ((lane >> 4) << 3) + (lane & 7);
    int g = (lane >> 3) & 1;
    return swoff(r, g);
}
// pack two fp32 into bf16x2 hi + residual lo
__device__ __forceinline__ void hl2(float x, float y, uint32_t& h, uint32_t& l) {
    __nv_bfloat162 hh, ll;
    hh.x = __float2bfloat16(x);
    hh.y = __float2bfloat16(y);
    ll.x = __float2bfloat16(x - __bfloat162float(hh.x));
    ll.y = __float2bfloat16(y - __bfloat162float(hh.y));
    h = *(uint32_t*)&hh;
    l = *(uint32_t*)&ll;
}

// ---------------- weight mean(|w|) : stage 1 ----------------
__global__ void reduce_abs_kernel(const float* __restrict__ w0, const float* __restrict__ w1,
                                  const float* __restrict__ w2, float* __restrict__ part) {
    const float* w = (blockIdx.y == 0) ? w0 : ((blockIdx.y == 1) ? w1 : w2);
    int t = threadIdx.x;
    size_t base = (size_t)blockIdx.x * 4096;
    float s = 0.f;
#pragma unroll
    for (int i = 0; i < 16; i++) s += fabsf(w[base + t + i * 256]);
    __shared__ float red[256];
    red[t] = s;
    __syncthreads();
    for (int o = 128; o > 0; o >>= 1) {
        if (t < o) red[t] += red[t + o];
        __syncthreads();
    }
    if (t == 0) part[blockIdx.y * 1024 + blockIdx.x] = red[0];
}

__global__ void finalize_scale_kernel(const float* __restrict__ part, float* __restrict__ scale) {
    int w = blockIdx.x;
    int t = threadIdx.x;
    float s = part[w * 1024 + t] + part[w * 1024 + t + 256] +
              part[w * 1024 + t + 512] + part[w * 1024 + t + 768];
    __shared__ float red[256];
    red[t] = s;
    __syncthreads();
    for (int o = 128; o > 0; o >>= 1) {
        if (t < o) red[t] += red[t + o];
        __syncthreads();
    }
    if (t == 0) {
        float mean = red[0] * (1.0f / ((float)Eq * (float)Eq));
        scale[w] = fmaxf(mean, 1e-5f);
    }
}

// ---------------- merged weight prep: ternary (q/k/v) + split3 mode-1 (k/v/o) ----------------
__global__ void prep_weights(const float* __restrict__ qw, const float* __restrict__ kw,
                             const float* __restrict__ vw, const float* __restrict__ ow,
                             __nv_bfloat16* __restrict__ wq,
                             __nv_bfloat16* __restrict__ kw3, __nv_bfloat16* __restrict__ vw3,
                             __nv_bfloat16* __restrict__ ow3,
                             const float* __restrict__ scale) {
    int wi = blockIdx.y;
    const float* w = (wi == 0) ? qw : ((wi == 1) ? kw : ((wi == 2) ? vw : ow));
    float inv = (wi < 3) ? __frcp_rn(scale[wi]) : 0.f;
    size_t e0 = ((size_t)blockIdx.x * 256 + threadIdx.x) * 8;
    size_t row = e0 >> 11, col = e0 & 2047;
    __nv_bfloat16* wo = (wi < 3) ? (wq + (size_t)wi * Eq * Eq + e0) : nullptr;
    __nv_bfloat16* y = (wi == 1) ? kw3 : ((wi == 2) ? vw3 : ((wi == 3) ? ow3 : nullptr));
    __nv_bfloat16* yr = y ? (y + row * (size_t)(3 * Eq)) : nullptr;
#pragma unroll
    for (int i = 0; i < 8; i += 4) {
        float4 v = *(const float4*)&w[e0 + i];
        float f[4] = {v.x, v.y, v.z, v.w};
#pragma unroll
        for (int j = 0; j < 4; j++) {
            if (wo)
                wo[i + j] = __float2bfloat16(fminf(fmaxf(rintf(f[j] * inv), -1.f), 1.f));
            if (yr) {
                __nv_bfloat16 hi = __float2bfloat16(f[j]);
                __nv_bfloat16 lo = __float2bfloat16(f[j] - __bfloat162float(hi));
                yr[col + i + j] = hi;
                yr[Eq + col + i + j] = lo;
                yr[2 * Eq + col + i + j] = hi;
            }
        }
    }
}

// ---------------- per-token absmax quantization (warp per row, no syncs) ----------------
__global__ void quant_act_bf16(const float* __restrict__ x, __nv_bfloat16* __restrict__ xq,
                               float* __restrict__ rows) {
    int w = (blockIdx.x * blockDim.x + threadIdx.x) >> 5;  // one warp per row
    int lane = threadIdx.x & 31;
    const float* xr = x + (size_t)w * Eq;
    float4 v[16];
    float mx = 0.f;
#pragma unroll
    for (int i = 0; i < 16; i++) {
        v[i] = *(const float4*)&xr[i * 128 + lane * 4];
        mx = fmaxf(mx, fmaxf(fmaxf(fabsf(v[i].x), fabsf(v[i].y)),
                             fmaxf(fabsf(v[i].z), fabsf(v[i].w))));
    }
#pragma unroll
    for (int o = 16; o > 0; o >>= 1) mx = fmaxf(mx, __shfl_xor_sync(0xffffffffu, mx, o));
    float s = __fdiv_rn(127.0f, fmaxf(mx, 1e-5f));
    if (lane == 0) rows[w] = s;
    __nv_bfloat16* xo = xq + (size_t)w * Eq;
#pragma unroll
    for (int i = 0; i < 16; i++) {
        __nv_bfloat162 p0, p1;
        p0.x = __float2bfloat16(fminf(fmaxf(rintf(v[i].x * s), -128.f), 127.f));
        p0.y = __float2bfloat16(fminf(fmaxf(rintf(v[i].y * s), -128.f), 127.f));
        p1.x = __float2bfloat16(fminf(fmaxf(rintf(v[i].z * s), -128.f), 127.f));
        p1.y = __float2bfloat16(fminf(fmaxf(rintf(v[i].w * s), -128.f), 127.f));
        *(__nv_bfloat162*)&xo[i * 128 + lane * 4] = p0;
        *(__nv_bfloat162*)&xo[i * 128 + lane * 4 + 2] = p1;
    }
}

// ---------------- fp32 -> split-bf16 K-tripling, A side [hi|hi|lo] ----------------
__global__ void split3a(const float* __restrict__ X, __nv_bfloat16* __restrict__ Y) {
    size_t i = (size_t)blockIdx.x * 256 + threadIdx.x;
    size_t row = i >> 11, col = i & 2047;
    float x = X[i];
    __nv_bfloat16 hi = __float2bfloat16(x);
    __nv_bfloat16 lo = __float2bfloat16(x - __bfloat162float(hi));
    __nv_bfloat16* yr = Y + row * (size_t)(3 * Eq);
    yr[col] = hi;
    yr[Eq + col] = hi;
    yr[2 * Eq + col] = lo;
}

// ---------------- V fp32 [B,L,E] -> V^T hi/lo [B,H,D,L] ----------------
__global__ void transpose_v(const float* __restrict__ V, __nv_bfloat16* __restrict__ Th,
                            __nv_bfloat16* __restrict__ Tl) {
    __shared__ float s[32][33];
    int l0 = blockIdx.x * 32;
    int e0 = blockIdx.y * 32;
    int b = blockIdx.z;
    int t = threadIdx.x;
    int h = e0 >> 7, d0 = e0 & 127;
#pragma unroll
    for (int i = 0; i < 4; i++) {
        int idx = t + i * 256;
        int lr = idx >> 5, lc = idx & 31;
        s[lr][lc] = V[((size_t)(b * Lq + l0 + lr)) * Eq + e0 + lc];
    }
    __syncthreads();
#pragma unroll
    for (int i = 0; i < 4; i++) {
        int idx = t + i * 256;
        int dr = idx >> 5, dc = idx & 31;
        float f = s[dc][dr];
        __nv_bfloat16 hi = __float2bfloat16(f);
        __nv_bfloat16 lo = __float2bfloat16(f - __bfloat162float(hi));
        size_t o = ((size_t)((b * Hq + h) * Dq + d0 + dr)) * Lq + l0 + dc;
        Th[o] = hi;
        Tl[o] = lo;
    }
}

// ---------------- HMMA bf16 GEMM: 128x256 tile, warp 64x64, cp.async 3-stage ----------------
struct GArgs {
    const __nv_bfloat16* A;
    const __nv_bfloat16* B;
    float* C;
    const float* rowscale;
    const float* wsp;
    const float* bias;
    int K, Nout, rbi, rbo, roff, ylim;
    __nv_bfloat16* Hout;
    __nv_bfloat16* Lout;
};

// dynamic smem: 3 stages x (A 16K | B 32K) = 144 KB
#define STAGE_BYTES 49152
#define SMEM_GEMM6 (3 * STAGE_BYTES)

__global__ __launch_bounds__(256, 1) void hmma_gemm6(GArgs ga0, GArgs ga1, GArgs ga2,
                                                     GArgs ga3, GArgs ga4) {
    int z = blockIdx.z;
    GArgs ga = (z == 0) ? ga0 : ((z == 1) ? ga1 : ((z == 2) ? ga2 : ((z == 3) ? ga3 : ga4)));
    if ((int)blockIdx.y >= ga.ylim) return;
    extern __shared__ __align__(128) uint8_t dsm[];
    uint32_t sb = smem_u32(dsm);
    int t = threadIdx.x;
    int lane = t & 31, wid = t >> 5;
    int m0 = blockIdx.y * 128, n0 = blockIdx.x * 256;
    int warp_m = wid & 1, warp_n = wid >> 1;   // warp tile 64x64
    const int K = ga.K;

    // cp.async mapping: A 128 rows x 128B (1024 groups), B 256 rows x 128B (2048 groups)
    const uint8_t* asrc[4];
    uint32_t gdstA[4];
#pragma unroll
    for (int i = 0; i < 4; i++) {
        int idx = t + i * 256;
        int r = idx >> 3, g = idx & 7;
        gdstA[i] = (g >> 2) * 8192 + swoff(r, g & 3);
        asrc[i] = (const uint8_t*)(ga.A + (size_t)(m0 + r) * K) + g * 16;
    }
    const uint8_t* bsrc[8];
    uint32_t gdstB[8];
#pragma unroll
    for (int i = 0; i < 8; i++) {
        int idx = t + i * 256;
        int r = idx >> 3, g = idx & 7;
        gdstB[i] = (g >> 2) * 16384 + swoff(r, g & 3);
        bsrc[i] = (const uint8_t*)(ga.B + (size_t)(n0 + r) * K) + g * 16;
    }

    uint32_t aaddr[4], baddr4[4];
#pragma unroll
    for (int mi = 0; mi < 4; mi++)
        aaddr[mi] = swoff(warp_m * 64 + mi * 16 + (lane & 15), lane >> 4);
#pragma unroll
    for (int ni2 = 0; ni2 < 4; ni2++)
        baddr4[ni2] = boff4(warp_n * 64 + ni2 * 16, lane);

    const int NK = K >> 6;
    {
#pragma unroll
        for (int i = 0; i < 4; i++) cpa16(sb + gdstA[i], asrc[i]);
#pragma unroll
        for (int i = 0; i < 8; i++) cpa16(sb + 16384 + gdstB[i], bsrc[i]);
        cpa_commit();
    }

    float c[4][8][4];
#pragma unroll
    for (int mi = 0; mi < 4; mi++)
#pragma unroll
        for (int ni = 0; ni < 8; ni++)
#pragma unroll
            for (int k = 0; k < 4; k++) c[mi][ni][k] = 0.f;

    int s = 0;
    for (int kt = 0; kt < NK; ++kt) {
        if (kt + 1 < NK) {
            int sn = (s + 1 == 3) ? 0 : s + 1;
            uint32_t base = sb + sn * STAGE_BYTES;
            size_t koff = (size_t)(kt + 1) * 128;
#pragma unroll
            for (int i = 0; i < 4; i++) cpa16(base + gdstA[i], asrc[i] + koff);
#pragma unroll
            for (int i = 0; i < 8; i++) cpa16(base + 16384 + gdstB[i], bsrc[i] + koff);
            cpa_commit();
            cpa_wait1();
        } else {
            cpa_wait0();
        }
        __syncthreads();

        uint32_t Ab = sb + s * STAGE_BYTES;
        uint32_t Bb = Ab + 16384;
#pragma unroll
        for (int ch = 0; ch < 2; ch++)
#pragma unroll
            for (int ks = 0; ks < 2; ks++) {
                uint32_t kx = ks * 32;
                uint32_t a[4][4], b[4][4];
#pragma unroll
                for (int mi = 0; mi < 4; mi++)
                    ldmx4(a[mi], Ab + ch * 8192 + (aaddr[mi] ^ kx));
#pragma unroll
                for (int ni2 = 0; ni2 < 4; ni2++)
                    ldmx4(b[ni2], Bb + ch * 16384 + (baddr4[ni2] ^ kx));
#pragma unroll
                for (int mi = 0; mi < 4; mi++)
#pragma unroll
                    for (int ni = 0; ni < 8; ni++)
                        mma16816(c[mi][ni], a[mi], &b[ni >> 1][(ni & 1) * 2]);
            }
        s = (s + 1 == 3) ? 0 : s + 1;
    }

    float ws = ga.wsp ? *ga.wsp : 1.0f;
    int g = lane >> 2, tg = lane & 3;
#pragma unroll
    for (int mi = 0; mi < 4; mi++) {
        int mA = m0 + warp_m * 64 + mi * 16 + g;
        int mB = mA + 8;
        float fA = ga.rowscale ? (ws / ga.rowscale[mA]) : 1.0f;
        float fB = ga.rowscale ? (ws / ga.rowscale[mB]) : 1.0f;
        int oA = (mA / ga.rbi) * ga.rbo + ga.roff + (mA % ga.rbi);
        int oB = (mB / ga.rbi) * ga.rbo + ga.roff + (mB % ga.rbi);
        if (ga.Hout) {
            __nv_bfloat16* hA = ga.Hout + (size_t)oA * ga.Nout;
            __nv_bfloat16* hB = ga.Hout + (size_t)oB * ga.Nout;
            __nv_bfloat16* lA = ga.Lout + (size_t)oA * ga.Nout;
            __nv_bfloat16* lB = ga.Lout + (size_t)oB * ga.Nout;
#pragma unroll
            for (int ni = 0; ni < 8; ni++) {
                int col = n0 + warp_n * 64 + ni * 8 + tg * 2;
                uint32_t h0, l0v, h1, l1v;
                hl2(c[mi][ni][0] * fA, c[mi][ni][1] * fA, h0, l0v);
                hl2(c[mi][ni][2] * fB, c[mi][ni][3] * fB, h1, l1v);
                *(uint32_t*)&hA[col] = h0;
                *(uint32_t*)&lA[col] = l0v;
                *(uint32_t*)&hB[col] = h1;
                *(uint32_t*)&lB[col] = l1v;
            }
        } else {
            float* crA = ga.C + (size_t)oA * ga.Nout;
            float* crB = ga.C + (size_t)oB * ga.Nout;
#pragma unroll
            for (int ni = 0; ni < 8; ni++) {
                int col = n0 + warp_n * 64 + ni * 8 + tg * 2;
                float b0 = 0.f, b1 = 0.f;
                if (ga.bias) { b0 = ga.bias[col]; b1 = ga.bias[col + 1]; }
                float2 vA, vB;
                vA.x = c[mi][ni][0] * fA + b0;
                vA.y = c[mi][ni][1] * fA + b1;
                vB.x = c[mi][ni][2] * fB + b0;
                vB.y = c[mi][ni][3] * fB + b1;
                *(float2*)&crA[col] = vA;
                *(float2*)&crB[col] = vB;
            }
        }
    }
}

// ---------------- FA2-style HMMA flash attention, 3-stage KV, Q in registers ----------------
// smem: 3 stages x 64K (KH 16K | KL 16K | VH 16K | VL 16K). Q preloaded via stage 2.
#define SMEM_ATTN4 (3 * 65536)   // 196608

__global__ __launch_bounds__(256, 1) void attn_mma3(
    const __nv_bfloat16* __restrict__ Qh, const __nv_bfloat16* __restrict__ Ql,
    const __nv_bfloat16* __restrict__ Kh, const __nv_bfloat16* __restrict__ Kl,
    const __nv_bfloat16* __restrict__ Vth, const __nv_bfloat16* __restrict__ Vtl,
    __nv_bfloat16* __restrict__ O3) {
    extern __shared__ char smg[];
    uint32_t sb = smem_u32(smg);
    int t = threadIdx.x;
    int lane = t & 31, wid = t >> 5;
    int qb = blockIdx.x * 128;
    int h = blockIdx.y;
    int b = blockIdx.z;

    const int wm = wid;
    const uint32_t a_off = swoff(wm * 16 + (lane & 15), lane >> 4);
    uint32_t k4[4], v4[8];
#pragma unroll
    for (int ni2 = 0; ni2 < 4; ni2++) k4[ni2] = boff4(ni2 * 16, lane);
#pragma unroll
    for (int ni2 = 0; ni2 < 8; ni2++) v4[ni2] = boff4(ni2 * 16, lane);
    const int g4 = lane >> 2, tg = lane & 3;
    const float SCALE = 0.08838834764831845f;

    // ---- issue Q into stage 2 (group 0) ----
    uint32_t qbase = sb + 2 * 65536;
    {
        const __nv_bfloat16* Qhg = Qh + ((size_t)(b * Sq + qb)) * Eq + h * Dq;
        const __nv_bfloat16* Qlg = Ql + ((size_t)(b * Sq + qb)) * Eq + h * Dq;
#pragma unroll
        for (int i = 0; i < 8; i++) {
            int idx = t + i * 256;
            int r = idx >> 4, g = idx & 15;
            uint32_t dst = (g >> 2) * 8192 + swoff(r, g & 3);
            cpa16(qbase + dst, Qhg + (size_t)r * Eq + g * 8);
            cpa16(qbase + 32768 + dst, Qlg + (size_t)r * Eq + g * 8);
        }
        cpa_commit();
    }

    const __nv_bfloat16* Khb = Kh + ((size_t)(b * Lq)) * Eq + h * Dq;
    const __nv_bfloat16* Klb = Kl + ((size_t)(b * Lq)) * Eq + h * Dq;
    const __nv_bfloat16* Vhb = Vth + ((size_t)((b * Hq + h) * Dq)) * Lq;
    const __nv_bfloat16* Vlb = Vtl + ((size_t)((b * Hq + h) * Dq)) * Lq;

    auto issueKV = [&](int kt) {
        uint32_t base = sb + (kt % 3) * 65536;
        const __nv_bfloat16* KhT = Khb + (size_t)(kt * 64) * Eq;
        const __nv_bfloat16* KlT = Klb + (size_t)(kt * 64) * Eq;
#pragma unroll
        for (int i = 0; i < 4; i++) {
            int idx = t + i * 256;
            int r = idx >> 4, g = idx & 15;
            uint32_t dst = (g >> 2) * 4096 + swoff(r, g & 3);
            cpa16(base + dst, KhT + (size_t)r * Eq + g * 8);
            cpa16(base + 16384 + dst, KlT + (size_t)r * Eq + g * 8);
        }
        const __nv_bfloat16* VhT = Vhb + kt * 64;
        const __nv_bfloat16* VlT = Vlb + kt * 64;
#pragma unroll
        for (int i = 0; i < 4; i++) {
            int idx = t + i * 256;
            int r = idx >> 3, g = idx & 7;
            uint32_t dst = (g >> 2) * 8192 + swoff(r, g & 3);
            cpa16(base + 32768 + dst, VhT + (size_t)r * Lq + g * 8);
            cpa16(base + 49152 + dst, VlT + (size_t)r * Lq + g * 8);
        }
        cpa_commit();
    };
    issueKV(0);          // group 1
    cpa_wait1();         // Q (group 0) complete
    __syncthreads();

    // ---- Q hi/lo fragments -> registers (freed stage 2 for KV tile 2) ----
    uint32_t qfh[4][2][4], qfl[4][2][4];
#pragma unroll
    for (int ch = 0; ch < 4; ch++)
#pragma unroll
        for (int ks = 0; ks < 2; ks++) {
            ldmx4(qfh[ch][ks], qbase + ch * 8192 + (a_off ^ (ks * 32)));
            ldmx4(qfl[ch][ks], qbase + 32768 + ch * 8192 + (a_off ^ (ks * 32)));
        }

    float m0 = -1e30f, m1 = -1e30f, l0 = 0.f, l1 = 0.f;
    float co[16][4];
#pragma unroll
    for (int i = 0; i < 16; i++)
#pragma unroll
        for (int j = 0; j < 4; j++) co[i][j] = 0.f;

    const int NT = Lq / 64;  // 34
    for (int kt = 0; kt < NT; ++kt) {
        if (kt + 1 < NT) { issueKV(kt + 1); cpa_wait1(); }
        else cpa_wait0();
        __syncthreads();   // the ONLY sync per iteration
        uint32_t kvb = sb + (kt % 3) * 65536;

        // ---- S = Qh.Kh + Qh.Kl + Ql.Kh ----
        float cs[8][4];
#pragma unroll
        for (int i = 0; i < 8; i++)
#pragma unroll
            for (int j = 0; j < 4; j++) cs[i][j] = 0.f;
#pragma unroll
        for (int ch = 0; ch < 4; ch++)
#pragma unroll
            for (int ks = 0; ks < 2; ks++) {
                uint32_t kx = ks * 32;
#pragma unroll
                for (int ni2 = 0; ni2 < 4; ni2++) {
                    uint32_t bh[4], bl[4];
                    uint32_t ba = kvb + ch * 4096 + (k4[ni2] ^ kx);
                    ldmx4(bh, ba);
                    ldmx4(bl, ba + 16384);
                    mma16816(cs[2 * ni2], qfh[ch][ks], bh);
                    mma16816(cs[2 * ni2], qfh[ch][ks], bl);
                    mma16816(cs[2 * ni2], qfl[ch][ks], bh);
                    mma16816(cs[2 * ni2 + 1], qfh[ch][ks], bh + 2);
                    mma16816(cs[2 * ni2 + 1], qfh[ch][ks], bl + 2);
                    mma16816(cs[2 * ni2 + 1], qfl[ch][ks], bh + 2);
                }
            }

        // ---- in-register softmax ----
        float tm0 = -1e30f, tm1 = -1e30f;
#pragma unroll
        for (int ni = 0; ni < 8; ni++) {
            cs[ni][0] *= SCALE; cs[ni][1] *= SCALE;
            cs[ni][2] *= SCALE; cs[ni][3] *= SCALE;
            tm0 = fmaxf(tm0, fmaxf(cs[ni][0], cs[ni][1]));
            tm1 = fmaxf(tm1, fmaxf(cs[ni][2], cs[ni][3]));
        }
        tm0 = fmaxf(tm0, __shfl_xor_sync(0xffffffffu, tm0, 1));
        tm0 = fmaxf(tm0, __shfl_xor_sync(0xffffffffu, tm0, 2));
        tm1 = fmaxf(tm1, __shfl_xor_sync(0xffffffffu, tm1, 1));
        tm1 = fmaxf(tm1, __shfl_xor_sync(0xffffffffu, tm1, 2));
        float nm0 = fmaxf(m0, tm0), nm1 = fmaxf(m1, tm1);
        float al0 = __expf(m0 - nm0), al1 = __expf(m1 - nm1);
        m0 = nm0; m1 = nm1;

        float rs0 = 0.f, rs1 = 0.f;
#pragma unroll
        for (int ni = 0; ni < 8; ni++) {
            cs[ni][0] = __expf(cs[ni][0] - m0); rs0 += cs[ni][0];
            cs[ni][1] = __expf(cs[ni][1] - m0); rs0 += cs[ni][1];
            cs[ni][2] = __expf(cs[ni][2] - m1); rs1 += cs[ni][2];
            cs[ni][3] = __expf(cs[ni][3] - m1); rs1 += cs[ni][3];
        }
        rs0 += __shfl_xor_sync(0xffffffffu, rs0, 1);
        rs0 += __shfl_xor_sync(0xffffffffu, rs0, 2);
        rs1 += __shfl_xor_sync(0xffffffffu, rs1, 1);
        rs1 += __shfl_xor_sync(0xffffffffu, rs1, 2);
        l0 = l0 * al0 + rs0;
        l1 = l1 * al1 + rs1;

        // ---- P hi/lo A-fragments ----
        uint32_t phf[4][4], plf[4][4];
#pragma unroll
        for (int ck = 0; ck < 4; ck++) {
            hl2(cs[2 * ck][0], cs[2 * ck][1], phf[ck][0], plf[ck][0]);
            hl2(cs[2 * ck][2], cs[2 * ck][3], phf[ck][1], plf[ck][1]);
            hl2(cs[2 * ck + 1][0], cs[2 * ck + 1][1], phf[ck][2], plf[ck][2]);
            hl2(cs[2 * ck + 1][2], cs[2 * ck + 1][3], phf[ck][3], plf[ck][3]);
        }

        // ---- rescale O ----
#pragma unroll
        for (int ni = 0; ni < 16; ni++) {
            co[ni][0] *= al0; co[ni][1] *= al0;
            co[ni][2] *= al1; co[ni][3] *= al1;
        }

        // ---- O += Ph.Vh + Ph.Vl + Pl.Vh ----
#pragma unroll
        for (int ck = 0; ck < 4; ck++) {
#pragma unroll
            for (int ni2 = 0; ni2 < 8; ni2++) {
                uint32_t bh[4], bl[4];
                uint32_t ba = kvb + 32768 + (ck >> 1) * 8192 + (v4[ni2] ^ ((ck & 1) * 32));
                ldmx4(bh, ba);
                ldmx4(bl, ba + 16384);
                mma16816(co[2 * ni2], phf[ck], bh);
                mma16816(co[2 * ni2], phf[ck], bl);
                mma16816(co[2 * ni2], plf[ck], bh);
                mma16816(co[2 * ni2 + 1], phf[ck], bh + 2);
                mma16816(co[2 * ni2 + 1], phf[ck], bl + 2);
                mma16816(co[2 * ni2 + 1], plf[ck], bh + 2);
            }
        }
    }

    // ---- epilogue: write O split [hi|hi|lo] ----
    float il0 = 1.0f / l0, il1 = 1.0f / l1;
    int r0 = wm * 16 + g4, r1 = r0 + 8;
    __nv_bfloat16* O0 = O3 + ((size_t)(b * Sq + qb + r0)) * (3 * Eq) + h * Dq;
    __nv_bfloat16* O1 = O3 + ((size_t)(b * Sq + qb + r1)) * (3 * Eq) + h * Dq;
#pragma unroll
    for (int ni = 0; ni < 16; ni++) {
        int col = ni * 8 + tg * 2;
        uint32_t h0, lo0, h1, lo1;
        hl2(co[ni][0] * il0, co[ni][1] * il0, h0, lo0);
        hl2(co[ni][2] * il1, co[ni][3] * il1, h1, lo1);
        *(uint32_t*)(O0 + col) = h0;
        *(uint32_t*)(O0 + Eq + col) = h0;
        *(uint32_t*)(O0 + 2 * Eq + col) = lo0;
        *(uint32_t*)(O1 + col) = h1;
        *(uint32_t*)(O1 + Eq + col) = h1;
        *(uint32_t*)(O1 + 2 * Eq + col) = lo1;
    }
}

// ---------------- host launcher ----------------
extern "C" void kernel_launch(void* const* d_in, const int* in_sizes, int n_in,
                              void* d_out, int out_size) {
    const float* x  = (const float*)d_in[0];
    const float* rt = (const float*)d_in[1];
    const float* qw = (const float*)d_in[2];
    const float* kw = (const float*)d_in[3];
    const float* vw = (const float*)d_in[4];
    const float* ow = (const float*)d_in[5];
    const float* ob = (const float*)d_in[6];
    float* out = (float*)d_out;

    __nv_bfloat16 *xbf, *wbf, *rt3, *kw3, *vw3, *ow3, *ao3, *qh, *ql, *kh, *kl, *vth, *vtl;
    float *rows, *vb, *part, *scale;
    cudaGetSymbolAddress((void**)&xbf, g_xbf);
    cudaGetSymbolAddress((void**)&wbf, g_wbf);
    cudaGetSymbolAddress((void**)&rt3, g_rt3);
    cudaGetSymbolAddress((void**)&kw3, g_kw3);
    cudaGetSymbolAddress((void**)&vw3, g_vw3);
    cudaGetSymbolAddress((void**)&ow3, g_ow3);
    cudaGetSymbolAddress((void**)&ao3, g_ao3);
    cudaGetSymbolAddress((void**)&qh, g_qh);
    cudaGetSymbolAddress((void**)&ql, g_ql);
    cudaGetSymbolAddress((void**)&kh, g_kh);
    cudaGetSymbolAddress((void**)&kl, g_kl);
    cudaGetSymbolAddress((void**)&vth, g_vth);
    cudaGetSymbolAddress((void**)&vtl, g_vtl);
    cudaGetSymbolAddress((void**)&rows, g_rows);
    cudaGetSymbolAddress((void**)&vb, g_vb);
    cudaGetSymbolAddress((void**)&part, g_part);
    cudaGetSymbolAddress((void**)&scale, g_scale);

    cudaFuncSetAttribute(attn_mma3, cudaFuncAttributeMaxDynamicSharedMemorySize, SMEM_ATTN4);
    cudaFuncSetAttribute(hmma_gemm6, cudaFuncAttributeMaxDynamicSharedMemorySize, SMEM_GEMM6);

    // 1) weight scales
    reduce_abs_kernel<<<dim3(1024, 3), 256>>>(qw, kw, vw, part);
    finalize_scale_kernel<<<3, 256>>>(part, scale);
    // 2) merged weight prep (ternary q/k/v + splits k/v/o) + act quant + rt split
    prep_weights<<<dim3(2048, 4), 256>>>(qw, kw, vw, ow, wbf, kw3, vw3, ow3, scale);
    quant_act_bf16<<<(Bq * Sq) / 8, 256>>>(x, xbf, rows);
    split3a<<<(Bq * Rq * Eq) / 256, 256>>>(rt, rt3);
    // 3) QKV + reasoning projections in ONE launch (z = 0..4)
    size_t EE = (size_t)Eq * Eq;
    GArgs gQ = { xbf, wbf + 0 * EE, nullptr, rows, scale + 0, nullptr,
                 Eq, Eq, Sq, Sq, 0, 32, qh, ql };
    GArgs gK = { xbf, wbf + 1 * EE, nullptr, rows, scale + 1, nullptr,
                 Eq, Eq, Sq, Lq, 0, 32, kh, kl };
    GArgs gV = { xbf, wbf + 2 * EE, vb, rows, scale + 2, nullptr,
                 Eq, Eq, Sq, Lq, 0, 32, nullptr, nullptr };
    GArgs gRK = { rt3, kw3, nullptr, nullptr, nullptr, nullptr,
                  3 * Eq, Eq, Rq, Lq, Sq, 2, kh, kl };
    GArgs gRV = { rt3, vw3, vb, nullptr, nullptr, nullptr,
                  3 * Eq, Eq, Rq, Lq, Sq, 2, nullptr, nullptr };
    hmma_gemm6<<<dim3(8, 32, 5), 256, SMEM_GEMM6>>>(gQ, gK, gV, gRK, gRV);
    // 4) transpose+split V
    transpose_v<<<dim3(Lq / 32, Eq / 32, Bq), 256>>>(vb, vth, vtl);
    // 5) attention (3-stage KV pipeline, Q in registers) -> writes [hi|hi|lo]
    attn_mma3<<<dim3(Sq / 128, Hq, Bq), 256, SMEM_ATTN4>>>(qh, ql, kh, kl, vth, vtl, ao3);
    // 6) output projection + bias
    GArgs gO = { ao3, ow3, out, nullptr, nullptr, ob,
                 3 * Eq, Eq, Bq * Sq, Bq * Sq, 0, 32, nullptr, nullptr };
    hmma_gemm6<<<dim3(8, 32, 1), 256, SMEM_GEMM6>>>(gO, gO, gO, gO, gO);
}

// round 11
// speedup vs baseline: 1.0692x; 1.0692x over previous
#include <cuda_runtime.h>
#include <cuda_bf16.h>
#include <cstdint>

#define Bq 2
#define Sq 2048
#define Rq 128
#define Eq 2048
#define Hq 16
#define Dq 128
#define Lq (Sq + Rq)   // 2176

// ---------------- scratch (device globals, no allocations) ----------------
__device__ __nv_bfloat16 g_xbf[(size_t)Bq * Sq * Eq];      // quantized acts as bf16 ints
__device__ __nv_bfloat16 g_wbf[3][(size_t)Eq * Eq];        // ternary weights as bf16
__device__ __nv_bfloat16 g_rt3[(size_t)Bq * Rq * 3 * Eq];  // reasoning tokens split [hi|hi|lo]
__device__ __nv_bfloat16 g_kw3[(size_t)Eq * 3 * Eq];       // k_w split [hi|lo|hi]
__device__ __nv_bfloat16 g_vw3[(size_t)Eq * 3 * Eq];       // v_w split
__device__ __nv_bfloat16 g_ow3[(size_t)Eq * 3 * Eq];       // out_w split
__device__ __nv_bfloat16 g_ao3[(size_t)Bq * Sq * 3 * Eq];  // attn out split [hi|hi|lo]
__device__ __nv_bfloat16 g_qh[(size_t)Bq * Sq * Eq];       // Q hi (pre-scaled by 1/sqrt(D))
__device__ __nv_bfloat16 g_ql[(size_t)Bq * Sq * Eq];       // Q lo
__device__ __nv_bfloat16 g_kh[(size_t)Bq * Lq * Eq];       // K hi
__device__ __nv_bfloat16 g_kl[(size_t)Bq * Lq * Eq];       // K lo
__device__ __nv_bfloat16 g_vth[(size_t)Bq * Hq * Dq * Lq]; // V^T hi [B,H,D,L]
__device__ __nv_bfloat16 g_vtl[(size_t)Bq * Hq * Dq * Lq]; // V^T lo
__device__ float g_rows[(size_t)Bq * Sq];                  // per-row act scale s
__device__ float g_vb[(size_t)Bq * Lq * Eq];               // V fp32
__device__ float g_part[3 * 1024];
__device__ float g_scale[3];

// ---------------- PTX helpers ----------------
typedef unsigned long long ull;
__device__ __forceinline__ uint32_t smem_u32(const void* p) {
    uint32_t a;
    asm("{ .reg .u64 t; cvta.to.shared.u64 t, %1; cvt.u32.u64 %0, t; }" : "=r"(a) : "l"(p));
    return a;
}
__device__ __forceinline__ void ldmx4(uint32_t* r, uint32_t addr) {
    asm volatile("ldmatrix.sync.aligned.m8n8.x4.shared.b16 {%0,%1,%2,%3}, [%4];"
                 : "=r"(r[0]), "=r"(r[1]), "=r"(r[2]), "=r"(r[3]) : "r"(addr));
}
__device__ __forceinline__ void mma16816(float* c, const uint32_t* a, const uint32_t* b) {
    asm volatile("mma.sync.aligned.m16n8k16.row.col.f32.bf16.bf16.f32 "
                 "{%0,%1,%2,%3}, {%4,%5,%6,%7}, {%8,%9}, {%0,%1,%2,%3};"
                 : "+f"(c[0]), "+f"(c[1]), "+f"(c[2]), "+f"(c[3])
                 : "r"(a[0]), "r"(a[1]), "r"(a[2]), "r"(a[3]), "r"(b[0]), "r"(b[1]));
}
__device__ __forceinline__ void cpa16(uint32_t dst, const void* src) {
    asm volatile("cp.async.cg.shared.global [%0], [%1], 16;" :: "r"(dst), "l"(src) : "memory");
}
__device__ __forceinline__ void cpa_commit() {
    asm volatile("cp.async.commit_group;" ::: "memory");
}
__device__ __forceinline__ void cpa_wait0() {
    asm volatile("cp.async.wait_group 0;" ::: "memory");
}
__device__ __forceinline__ void cpa_wait1() {
    asm volatile("cp.async.wait_group 1;" ::: "memory");
}
// smem rows of 32 bf16 (64B); 16B group g stored at g ^ ((row>>1)&3)
__device__ __forceinline__ uint32_t swoff(int r, int g) {
    return (uint32_t)(r * 64 + ((g ^ ((r >> 1) & 3)) << 4));
}
// per-lane address offset for B-side ldmatrix.x4 (2 consecutive n-frags of 8 rows)
__device__ __forceinline__ uint32_t boff4(int base_row, int lane) {
    int r = base_row + ((lane >> 4) << 3) + (lane & 7);
    int g = (lane >> 3) & 1;
    return swoff(r, g);
}
// pack two fp32 into bf16x2 hi + residual lo
__device__ __forceinline__ void hl2(float x, float y, uint32_t& h, uint32_t& l) {
    __nv_bfloat162 hh, ll;
    hh.x = __float2bfloat16(x);
    hh.y = __float2bfloat16(y);
    ll.x = __float2bfloat16(x - __bfloat162float(hh.x));
    ll.y = __float2bfloat16(y - __bfloat162float(hh.y));
    h = *(uint32_t*)&hh;
    l = *(uint32_t*)&ll;
}

// ---------------- weight mean(|w|) : stage 1 ----------------
__global__ void reduce_abs_kernel(const float* __restrict__ w0, const float* __restrict__ w1,
                                  const float* __restrict__ w2, float* __restrict__ part) {
    const float* w = (blockIdx.y == 0) ? w0 : ((blockIdx.y == 1) ? w1 : w2);
    int t = threadIdx.x;
    size_t base = (size_t)blockIdx.x * 4096;
    float s = 0.f;
#pragma unroll
    for (int i = 0; i < 16; i++) s += fabsf(w[base + t + i * 256]);
    __shared__ float red[256];
    red[t] = s;
    __syncthreads();
    for (int o = 128; o > 0; o >>= 1) {
        if (t < o) red[t] += red[t + o];
        __syncthreads();
    }
    if (t == 0) part[blockIdx.y * 1024 + blockIdx.x] = red[0];
}

__global__ void finalize_scale_kernel(const float* __restrict__ part, float* __restrict__ scale) {
    int w = blockIdx.x;
    int t = threadIdx.x;
    float s = part[w * 1024 + t] + part[w * 1024 + t + 256] +
              part[w * 1024 + t + 512] + part[w * 1024 + t + 768];
    __shared__ float red[256];
    red[t] = s;
    __syncthreads();
    for (int o = 128; o > 0; o >>= 1) {
        if (t < o) red[t] += red[t + o];
        __syncthreads();
    }
    if (t == 0) {
        float mean = red[0] * (1.0f / ((float)Eq * (float)Eq));
        scale[w] = fmaxf(mean, 1e-5f);
    }
}

// ---------------- merged weight prep: ternary (q/k/v) + split3 mode-1 (k/v/o) ----------------
__global__ void prep_weights(const float* __restrict__ qw, const float* __restrict__ kw,
                             const float* __restrict__ vw, const float* __restrict__ ow,
                             __nv_bfloat16* __restrict__ wq,
                             __nv_bfloat16* __restrict__ kw3, __nv_bfloat16* __restrict__ vw3,
                             __nv_bfloat16* __restrict__ ow3,
                             const float* __restrict__ scale) {
    int wi = blockIdx.y;
    const float* w = (wi == 0) ? qw : ((wi == 1) ? kw : ((wi == 2) ? vw : ow));
    float inv = (wi < 3) ? __frcp_rn(scale[wi]) : 0.f;
    size_t e0 = ((size_t)blockIdx.x * 256 + threadIdx.x) * 8;
    size_t row = e0 >> 11, col = e0 & 2047;
    __nv_bfloat16* wo = (wi < 3) ? (wq + (size_t)wi * Eq * Eq + e0) : nullptr;
    __nv_bfloat16* y = (wi == 1) ? kw3 : ((wi == 2) ? vw3 : ((wi == 3) ? ow3 : nullptr));
    __nv_bfloat16* yr = y ? (y + row * (size_t)(3 * Eq)) : nullptr;
#pragma unroll
    for (int i = 0; i < 8; i += 4) {
        float4 v = *(const float4*)&w[e0 + i];
        float f[4] = {v.x, v.y, v.z, v.w};
#pragma unroll
        for (int j = 0; j < 4; j++) {
            if (wo)
                wo[i + j] = __float2bfloat16(fminf(fmaxf(rintf(f[j] * inv), -1.f), 1.f));
            if (yr) {
                __nv_bfloat16 hi = __float2bfloat16(f[j]);
                __nv_bfloat16 lo = __float2bfloat16(f[j] - __bfloat162float(hi));
                yr[col + i + j] = hi;
                yr[Eq + col + i + j] = lo;
                yr[2 * Eq + col + i + j] = hi;
            }
        }
    }
}

// ---------------- per-token absmax quantization (warp per row, no syncs) ----------------
__global__ void quant_act_bf16(const float* __restrict__ x, __nv_bfloat16* __restrict__ xq,
                               float* __restrict__ rows) {
    int w = (blockIdx.x * blockDim.x + threadIdx.x) >> 5;  // one warp per row
    int lane = threadIdx.x & 31;
    const float* xr = x + (size_t)w * Eq;
    float4 v[16];
    float mx = 0.f;
#pragma unroll
    for (int i = 0; i < 16; i++) {
        v[i] = *(const float4*)&xr[i * 128 + lane * 4];
        mx = fmaxf(mx, fmaxf(fmaxf(fabsf(v[i].x), fabsf(v[i].y)),
                             fmaxf(fabsf(v[i].z), fabsf(v[i].w))));
    }
#pragma unroll
    for (int o = 16; o > 0; o >>= 1) mx = fmaxf(mx, __shfl_xor_sync(0xffffffffu, mx, o));
    float s = __fdiv_rn(127.0f, fmaxf(mx, 1e-5f));
    if (lane == 0) rows[w] = s;
    __nv_bfloat16* xo = xq + (size_t)w * Eq;
#pragma unroll
    for (int i = 0; i < 16; i++) {
        __nv_bfloat162 p0, p1;
        p0.x = __float2bfloat16(fminf(fmaxf(rintf(v[i].x * s), -128.f), 127.f));
        p0.y = __float2bfloat16(fminf(fmaxf(rintf(v[i].y * s), -128.f), 127.f));
        p1.x = __float2bfloat16(fminf(fmaxf(rintf(v[i].z * s), -128.f), 127.f));
        p1.y = __float2bfloat16(fminf(fmaxf(rintf(v[i].w * s), -128.f), 127.f));
        *(__nv_bfloat162*)&xo[i * 128 + lane * 4] = p0;
        *(__nv_bfloat162*)&xo[i * 128 + lane * 4 + 2] = p1;
    }
}

// ---------------- fp32 -> split-bf16 K-tripling, A side [hi|hi|lo] ----------------
__global__ void split3a(const float* __restrict__ X, __nv_bfloat16* __restrict__ Y) {
    size_t i = (size_t)blockIdx.x * 256 + threadIdx.x;
    size_t row = i >> 11, col = i & 2047;
    float x = X[i];
    __nv_bfloat16 hi = __float2bfloat16(x);
    __nv_bfloat16 lo = __float2bfloat16(x - __bfloat162float(hi));
    __nv_bfloat16* yr = Y + row * (size_t)(3 * Eq);
    yr[col] = hi;
    yr[Eq + col] = hi;
    yr[2 * Eq + col] = lo;
}

// ---------------- V fp32 [B,L,E] -> V^T hi/lo [B,H,D,L] ----------------
__global__ void transpose_v(const float* __restrict__ V, __nv_bfloat16* __restrict__ Th,
                            __nv_bfloat16* __restrict__ Tl) {
    __shared__ float s[32][33];
    int l0 = blockIdx.x * 32;
    int e0 = blockIdx.y * 32;
    int b = blockIdx.z;
    int t = threadIdx.x;
    int h = e0 >> 7, d0 = e0 & 127;
#pragma unroll
    for (int i = 0; i < 4; i++) {
        int idx = t + i * 256;
        int lr = idx >> 5, lc = idx & 31;
        s[lr][lc] = V[((size_t)(b * Lq + l0 + lr)) * Eq + e0 + lc];
    }
    __syncthreads();
#pragma unroll
    for (int i = 0; i < 4; i++) {
        int idx = t + i * 256;
        int dr = idx >> 5, dc = idx & 31;
        float f = s[dc][dr];
        __nv_bfloat16 hi = __float2bfloat16(f);
        __nv_bfloat16 lo = __float2bfloat16(f - __bfloat162float(hi));
        size_t o = ((size_t)((b * Hq + h) * Dq + d0 + dr)) * Lq + l0 + dc;
        Th[o] = hi;
        Tl[o] = lo;
    }
}

// ---------------- HMMA bf16 GEMM: cp.async 3-stage, BK=64, 2 CTAs/SM, z-batched ----------------
struct GArgs {
    const __nv_bfloat16* A;
    const __nv_bfloat16* B;
    float* C;
    const float* rowscale;
    const float* wsp;
    const float* bias;
    int K, Nout, rbi, rbo, roff, ylim;
    __nv_bfloat16* Hout;
    __nv_bfloat16* Lout;
    float cmul;   // extra constant multiplier folded into the epilogue
};

// dynamic smem: 3 stages x (A 16K | B 16K) = 96 KB
#define SMEM_GEMM5 98304

__global__ __launch_bounds__(256, 2) void hmma_gemm5(GArgs ga0, GArgs ga1, GArgs ga2,
                                                     GArgs ga3, GArgs ga4) {
    int z = blockIdx.z;
    GArgs ga = (z == 0) ? ga0 : ((z == 1) ? ga1 : ((z == 2) ? ga2 : ((z == 3) ? ga3 : ga4)));
    if ((int)blockIdx.y >= ga.ylim) return;
    extern __shared__ __align__(128) uint8_t dsm[];
    uint32_t sb = smem_u32(dsm);
    int t = threadIdx.x;
    int lane = t & 31, wid = t >> 5;
    int m0 = blockIdx.y * 128, n0 = blockIdx.x * 128;
    int warp_m = wid & 1, warp_n = wid >> 1;
    const int K = ga.K;

    // cp.async mapping: tile 128 rows x 128 B (2 chunks of 64 B); 1024 groups of 16 B
    const uint8_t* asrc[4];
    const uint8_t* bsrc[4];
    uint32_t gdst[4];
#pragma unroll
    for (int i = 0; i < 4; i++) {
        int idx = t + i * 256;
        int r = idx >> 3, g = idx & 7;
        gdst[i] = (g >> 2) * 8192 + swoff(r, g & 3);
        asrc[i] = (const uint8_t*)(ga.A + (size_t)(m0 + r) * K) + g * 16;
        bsrc[i] = (const uint8_t*)(ga.B + (size_t)(n0 + r) * K) + g * 16;
    }

    uint32_t aaddr[4], baddr4[2];
#pragma unroll
    for (int mi = 0; mi < 4; mi++)
        aaddr[mi] = swoff(warp_m * 64 + mi * 16 + (lane & 15), lane >> 4);
#pragma unroll
    for (int ni2 = 0; ni2 < 2; ni2++)
        baddr4[ni2] = boff4(warp_n * 32 + ni2 * 16, lane);

    const int NK = K >> 6;
    {
#pragma unroll
        for (int i = 0; i < 4; i++) {
            cpa16(sb + gdst[i], asrc[i]);
            cpa16(sb + 16384 + gdst[i], bsrc[i]);
        }
        cpa_commit();
    }

    float c[4][4][4];
#pragma unroll
    for (int mi = 0; mi < 4; mi++)
#pragma unroll
        for (int ni = 0; ni < 4; ni++)
#pragma unroll
            for (int k = 0; k < 4; k++) c[mi][ni][k] = 0.f;

    int s = 0;
    for (int kt = 0; kt < NK; ++kt) {
        if (kt + 1 < NK) {
            int sn = (s + 1 == 3) ? 0 : s + 1;
            uint32_t base = sb + sn * 32768;
            size_t koff = (size_t)(kt + 1) * 128;
#pragma unroll
            for (int i = 0; i < 4; i++) {
                cpa16(base + gdst[i], asrc[i] + koff);
                cpa16(base + 16384 + gdst[i], bsrc[i] + koff);
            }
            cpa_commit();
            cpa_wait1();
        } else {
            cpa_wait0();
        }
        __syncthreads();

        uint32_t Ab = sb + s * 32768;
        uint32_t Bb = Ab + 16384;
#pragma unroll
        for (int ch = 0; ch < 2; ch++)
#pragma unroll
            for (int ks = 0; ks < 2; ks++) {
                uint32_t kx = ks * 32;
                uint32_t a[4][4], b[2][4];
#pragma unroll
                for (int mi = 0; mi < 4; mi++)
                    ldmx4(a[mi], Ab + ch * 8192 + (aaddr[mi] ^ kx));
#pragma unroll
                for (int ni2 = 0; ni2 < 2; ni2++)
                    ldmx4(b[ni2], Bb + ch * 8192 + (baddr4[ni2] ^ kx));
#pragma unroll
                for (int mi = 0; mi < 4; mi++)
#pragma unroll
                    for (int ni = 0; ni < 4; ni++)
                        mma16816(c[mi][ni], a[mi], &b[ni >> 1][(ni & 1) * 2]);
            }
        s = (s + 1 == 3) ? 0 : s + 1;
    }

    float ws = ga.cmul * (ga.wsp ? *ga.wsp : 1.0f);
    int g = lane >> 2, tg = lane & 3;
#pragma unroll
    for (int mi = 0; mi < 4; mi++) {
        int mA = m0 + warp_m * 64 + mi * 16 + g;
        int mB = mA + 8;
        float fA = ga.rowscale ? (ws / ga.rowscale[mA]) : ws;
        float fB = ga.rowscale ? (ws / ga.rowscale[mB]) : ws;
        int oA = (mA / ga.rbi) * ga.rbo + ga.roff + (mA % ga.rbi);
        int oB = (mB / ga.rbi) * ga.rbo + ga.roff + (mB % ga.rbi);
        if (ga.Hout) {
            __nv_bfloat16* hA = ga.Hout + (size_t)oA * ga.Nout;
            __nv_bfloat16* hB = ga.Hout + (size_t)oB * ga.Nout;
            __nv_bfloat16* lA = ga.Lout + (size_t)oA * ga.Nout;
            __nv_bfloat16* lB = ga.Lout + (size_t)oB * ga.Nout;
#pragma unroll
            for (int ni = 0; ni < 4; ni++) {
                int col = n0 + warp_n * 32 + ni * 8 + tg * 2;
                uint32_t h0, l0v, h1, l1v;
                hl2(c[mi][ni][0] * fA, c[mi][ni][1] * fA, h0, l0v);
                hl2(c[mi][ni][2] * fB, c[mi][ni][3] * fB, h1, l1v);
                *(uint32_t*)&hA[col] = h0;
                *(uint32_t*)&lA[col] = l0v;
                *(uint32_t*)&hB[col] = h1;
                *(uint32_t*)&lB[col] = l1v;
            }
        } else {
            float* crA = ga.C + (size_t)oA * ga.Nout;
            float* crB = ga.C + (size_t)oB * ga.Nout;
#pragma unroll
            for (int ni = 0; ni < 4; ni++) {
                int col = n0 + warp_n * 32 + ni * 8 + tg * 2;
                float b0 = 0.f, b1 = 0.f;
                if (ga.bias) { b0 = ga.bias[col]; b1 = ga.bias[col + 1]; }
                float2 vA, vB;
                vA.x = c[mi][ni][0] * fA + b0;
                vA.y = c[mi][ni][1] * fA + b1;
                vB.x = c[mi][ni][2] * fB + b0;
                vB.y = c[mi][ni][3] * fB + b1;
                *(float2*)&crA[col] = vA;
                *(float2*)&crB[col] = vB;
            }
        }
    }
}

// ---------------- FA2-style HMMA flash attention, 3-stage KV, Q in registers ----------------
// Q is PRE-SCALED by 1/sqrt(D) in the projection epilogue -> no scale loop here.
// smem: 3 stages x 64K (KH 16K | KL 16K | VH 16K | VL 16K). Q preloaded via stage 2.
#define SMEM_ATTN4 (3 * 65536)   // 196608

__global__ __launch_bounds__(256, 1) void attn_mma3(
    const __nv_bfloat16* __restrict__ Qh, const __nv_bfloat16* __restrict__ Ql,
    const __nv_bfloat16* __restrict__ Kh, const __nv_bfloat16* __restrict__ Kl,
    const __nv_bfloat16* __restrict__ Vth, const __nv_bfloat16* __restrict__ Vtl,
    __nv_bfloat16* __restrict__ O3) {
    extern __shared__ char smg[];
    uint32_t sb = smem_u32(smg);
    int t = threadIdx.x;
    int lane = t & 31, wid = t >> 5;
    int qb = blockIdx.x * 128;
    int h = blockIdx.y;
    int b = blockIdx.z;

    const int wm = wid;
    const uint32_t a_off = swoff(wm * 16 + (lane & 15), lane >> 4);
    uint32_t k4[4], v4[8];
#pragma unroll
    for (int ni2 = 0; ni2 < 4; ni2++) k4[ni2] = boff4(ni2 * 16, lane);
#pragma unroll
    for (int ni2 = 0; ni2 < 8; ni2++) v4[ni2] = boff4(ni2 * 16, lane);
    const int g4 = lane >> 2, tg = lane & 3;

    // ---- issue Q into stage 2 (group 0) ----
    uint32_t qbase = sb + 2 * 65536;
    {
        const __nv_bfloat16* Qhg = Qh + ((size_t)(b * Sq + qb)) * Eq + h * Dq;
        const __nv_bfloat16* Qlg = Ql + ((size_t)(b * Sq + qb)) * Eq + h * Dq;
#pragma unroll
        for (int i = 0; i < 8; i++) {
            int idx = t + i * 256;
            int r = idx >> 4, g = idx & 15;
            uint32_t dst = (g >> 2) * 8192 + swoff(r, g & 3);
            cpa16(qbase + dst, Qhg + (size_t)r * Eq + g * 8);
            cpa16(qbase + 32768 + dst, Qlg + (size_t)r * Eq + g * 8);
        }
        cpa_commit();
    }

    const __nv_bfloat16* Khb = Kh + ((size_t)(b * Lq)) * Eq + h * Dq;
    const __nv_bfloat16* Klb = Kl + ((size_t)(b * Lq)) * Eq + h * Dq;
    const __nv_bfloat16* Vhb = Vth + ((size_t)((b * Hq + h) * Dq)) * Lq;
    const __nv_bfloat16* Vlb = Vtl + ((size_t)((b * Hq + h) * Dq)) * Lq;

    auto issueKV = [&](int kt) {
        uint32_t base = sb + (kt % 3) * 65536;
        const __nv_bfloat16* KhT = Khb + (size_t)(kt * 64) * Eq;
        const __nv_bfloat16* KlT = Klb + (size_t)(kt * 64) * Eq;
#pragma unroll
        for (int i = 0; i < 4; i++) {
            int idx = t + i * 256;
            int r = idx >> 4, g = idx & 15;
            uint32_t dst = (g >> 2) * 4096 + swoff(r, g & 3);
            cpa16(base + dst, KhT + (size_t)r * Eq + g * 8);
            cpa16(base + 16384 + dst, KlT + (size_t)r * Eq + g * 8);
        }
        const __nv_bfloat16* VhT = Vhb + kt * 64;
        const __nv_bfloat16* VlT = Vlb + kt * 64;
#pragma unroll
        for (int i = 0; i < 4; i++) {
            int idx = t + i * 256;
            int r = idx >> 3, g = idx & 7;
            uint32_t dst = (g >> 2) * 8192 + swoff(r, g & 3);
            cpa16(base + 32768 + dst, VhT + (size_t)r * Lq + g * 8);
            cpa16(base + 49152 + dst, VlT + (size_t)r * Lq + g * 8);
        }
        cpa_commit();
    };
    issueKV(0);          // group 1
    cpa_wait1();         // Q (group 0) complete
    __syncthreads();

    // ---- Q hi/lo fragments -> registers (freed stage 2 for KV tile 2) ----
    uint32_t qfh[4][2][4], qfl[4][2][4];
#pragma unroll
    for (int ch = 0; ch < 4; ch++)
#pragma unroll
        for (int ks = 0; ks < 2; ks++) {
            ldmx4(qfh[ch][ks], qbase + ch * 8192 + (a_off ^ (ks * 32)));
            ldmx4(qfl[ch][ks], qbase + 32768 + ch * 8192 + (a_off ^ (ks * 32)));
        }

    float m0 = -1e30f, m1 = -1e30f, l0 = 0.f, l1 = 0.f;
    float co[16][4];
#pragma unroll
    for (int i = 0; i < 16; i++)
#pragma unroll
        for (int j = 0; j < 4; j++) co[i][j] = 0.f;

    const int NT = Lq / 64;  // 34
    for (int kt = 0; kt < NT; ++kt) {
        if (kt + 1 < NT) { issueKV(kt + 1); cpa_wait1(); }
        else cpa_wait0();
        __syncthreads();   // the ONLY sync per iteration
        uint32_t kvb = sb + (kt % 3) * 65536;

        // ---- S = Qh.Kh + Qh.Kl + Ql.Kh (already scaled via Q) ----
        float cs[8][4];
#pragma unroll
        for (int i = 0; i < 8; i++)
#pragma unroll
            for (int j = 0; j < 4; j++) cs[i][j] = 0.f;
#pragma unroll
        for (int ch = 0; ch < 4; ch++)
#pragma unroll
            for (int ks = 0; ks < 2; ks++) {
                uint32_t kx = ks * 32;
#pragma unroll
                for (int ni2 = 0; ni2 < 4; ni2++) {
                    uint32_t bh[4], bl[4];
                    uint32_t ba = kvb + ch * 4096 + (k4[ni2] ^ kx);
                    ldmx4(bh, ba);
                    ldmx4(bl, ba + 16384);
                    mma16816(cs[2 * ni2], qfh[ch][ks], bh);
                    mma16816(cs[2 * ni2], qfh[ch][ks], bl);
                    mma16816(cs[2 * ni2], qfl[ch][ks], bh);
                    mma16816(cs[2 * ni2 + 1], qfh[ch][ks], bh + 2);
                    mma16816(cs[2 * ni2 + 1], qfh[ch][ks], bl + 2);
                    mma16816(cs[2 * ni2 + 1], qfl[ch][ks], bh + 2);
                }
            }

        // ---- in-register softmax ----
        float tm0 = -1e30f, tm1 = -1e30f;
#pragma unroll
        for (int ni = 0; ni < 8; ni++) {
            tm0 = fmaxf(tm0, fmaxf(cs[ni][0], cs[ni][1]));
            tm1 = fmaxf(tm1, fmaxf(cs[ni][2], cs[ni][3]));
        }
        tm0 = fmaxf(tm0, __shfl_xor_sync(0xffffffffu, tm0, 1));
        tm0 = fmaxf(tm0, __shfl_xor_sync(0xffffffffu, tm0, 2));
        tm1 = fmaxf(tm1, __shfl_xor_sync(0xffffffffu, tm1, 1));
        tm1 = fmaxf(tm1, __shfl_xor_sync(0xffffffffu, tm1, 2));
        float nm0 = fmaxf(m0, tm0), nm1 = fmaxf(m1, tm1);
        float al0 = __expf(m0 - nm0), al1 = __expf(m1 - nm1);
        m0 = nm0; m1 = nm1;

        float rs0 = 0.f, rs1 = 0.f;
#pragma unroll
        for (int ni = 0; ni < 8; ni++) {
            cs[ni][0] = __expf(cs[ni][0] - m0); rs0 += cs[ni][0];
            cs[ni][1] = __expf(cs[ni][1] - m0); rs0 += cs[ni][1];
            cs[ni][2] = __expf(cs[ni][2] - m1); rs1 += cs[ni][2];
            cs[ni][3] = __expf(cs[ni][3] - m1); rs1 += cs[ni][3];
        }
        rs0 += __shfl_xor_sync(0xffffffffu, rs0, 1);
        rs0 += __shfl_xor_sync(0xffffffffu, rs0, 2);
        rs1 += __shfl_xor_sync(0xffffffffu, rs1, 1);
        rs1 += __shfl_xor_sync(0xffffffffu, rs1, 2);
        l0 = l0 * al0 + rs0;
        l1 = l1 * al1 + rs1;

        // ---- P hi/lo A-fragments ----
        uint32_t phf[4][4], plf[4][4];
#pragma unroll
        for (int ck = 0; ck < 4; ck++) {
            hl2(cs[2 * ck][0], cs[2 * ck][1], phf[ck][0], plf[ck][0]);
            hl2(cs[2 * ck][2], cs[2 * ck][3], phf[ck][1], plf[ck][1]);
            hl2(cs[2 * ck + 1][0], cs[2 * ck + 1][1], phf[ck][2], plf[ck][2]);
            hl2(cs[2 * ck + 1][2], cs[2 * ck + 1][3], phf[ck][3], plf[ck][3]);
        }

        // ---- rescale O ----
#pragma unroll
        for (int ni = 0; ni < 16; ni++) {
            co[ni][0] *= al0; co[ni][1] *= al0;
            co[ni][2] *= al1; co[ni][3] *= al1;
        }

        // ---- O += Ph.Vh + Ph.Vl + Pl.Vh ----
#pragma unroll
        for (int ck = 0; ck < 4; ck++) {
#pragma unroll
            for (int ni2 = 0; ni2 < 8; ni2++) {
                uint32_t bh[4], bl[4];
                uint32_t ba = kvb + 32768 + (ck >> 1) * 8192 + (v4[ni2] ^ ((ck & 1) * 32));
                ldmx4(bh, ba);
                ldmx4(bl, ba + 16384);
                mma16816(co[2 * ni2], phf[ck], bh);
                mma16816(co[2 * ni2], phf[ck], bl);
                mma16816(co[2 * ni2], plf[ck], bh);
                mma16816(co[2 * ni2 + 1], phf[ck], bh + 2);
                mma16816(co[2 * ni2 + 1], phf[ck], bl + 2);
                mma16816(co[2 * ni2 + 1], plf[ck], bh + 2);
            }
        }
    }

    // ---- epilogue: write O split [hi|hi|lo] ----
    float il0 = 1.0f / l0, il1 = 1.0f / l1;
    int r0 = wm * 16 + g4, r1 = r0 + 8;
    __nv_bfloat16* O0 = O3 + ((size_t)(b * Sq + qb + r0)) * (3 * Eq) + h * Dq;
    __nv_bfloat16* O1 = O3 + ((size_t)(b * Sq + qb + r1)) * (3 * Eq) + h * Dq;
#pragma unroll
    for (int ni = 0; ni < 16; ni++) {
        int col = ni * 8 + tg * 2;
        uint32_t h0, lo0, h1, lo1;
        hl2(co[ni][0] * il0, co[ni][1] * il0, h0, lo0);
        hl2(co[ni][2] * il1, co[ni][3] * il1, h1, lo1);
        *(uint32_t*)(O0 + col) = h0;
        *(uint32_t*)(O0 + Eq + col) = h0;
        *(uint32_t*)(O0 + 2 * Eq + col) = lo0;
        *(uint32_t*)(O1 + col) = h1;
        *(uint32_t*)(O1 + Eq + col) = h1;
        *(uint32_t*)(O1 + 2 * Eq + col) = lo1;
    }
}

// ---------------- host launcher ----------------
extern "C" void kernel_launch(void* const* d_in, const int* in_sizes, int n_in,
                              void* d_out, int out_size) {
    const float* x  = (const float*)d_in[0];
    const float* rt = (const float*)d_in[1];
    const float* qw = (const float*)d_in[2];
    const float* kw = (const float*)d_in[3];
    const float* vw = (const float*)d_in[4];
    const float* ow = (const float*)d_in[5];
    const float* ob = (const float*)d_in[6];
    float* out = (float*)d_out;

    __nv_bfloat16 *xbf, *wbf, *rt3, *kw3, *vw3, *ow3, *ao3, *qh, *ql, *kh, *kl, *vth, *vtl;
    float *rows, *vb, *part, *scale;
    cudaGetSymbolAddress((void**)&xbf, g_xbf);
    cudaGetSymbolAddress((void**)&wbf, g_wbf);
    cudaGetSymbolAddress((void**)&rt3, g_rt3);
    cudaGetSymbolAddress((void**)&kw3, g_kw3);
    cudaGetSymbolAddress((void**)&vw3, g_vw3);
    cudaGetSymbolAddress((void**)&ow3, g_ow3);
    cudaGetSymbolAddress((void**)&ao3, g_ao3);
    cudaGetSymbolAddress((void**)&qh, g_qh);
    cudaGetSymbolAddress((void**)&ql, g_ql);
    cudaGetSymbolAddress((void**)&kh, g_kh);
    cudaGetSymbolAddress((void**)&kl, g_kl);
    cudaGetSymbolAddress((void**)&vth, g_vth);
    cudaGetSymbolAddress((void**)&vtl, g_vtl);
    cudaGetSymbolAddress((void**)&rows, g_rows);
    cudaGetSymbolAddress((void**)&vb, g_vb);
    cudaGetSymbolAddress((void**)&part, g_part);
    cudaGetSymbolAddress((void**)&scale, g_scale);

    cudaFuncSetAttribute(attn_mma3, cudaFuncAttributeMaxDynamicSharedMemorySize, SMEM_ATTN4);
    cudaFuncSetAttribute(hmma_gemm5, cudaFuncAttributeMaxDynamicSharedMemorySize, SMEM_GEMM5);

    const float SCALE = 0.08838834764831845f;  // 1/sqrt(128), folded into Q epilogue

    // 1) weight scales
    reduce_abs_kernel<<<dim3(1024, 3), 256>>>(qw, kw, vw, part);
    finalize_scale_kernel<<<3, 256>>>(part, scale);
    // 2) merged weight prep (ternary q/k/v + splits k/v/o) + act quant + rt split
    prep_weights<<<dim3(2048, 4), 256>>>(qw, kw, vw, ow, wbf, kw3, vw3, ow3, scale);
    quant_act_bf16<<<(Bq * Sq) / 8, 256>>>(x, xbf, rows);
    split3a<<<(Bq * Rq * Eq) / 256, 256>>>(rt, rt3);
    // 3) QKV + reasoning projections in ONE launch (z = 0..4)
    size_t EE = (size_t)Eq * Eq;
    GArgs gQ = { xbf, wbf + 0 * EE, nullptr, rows, scale + 0, nullptr,
                 Eq, Eq, Sq, Sq, 0, 32, qh, ql, SCALE };
    GArgs gK = { xbf, wbf + 1 * EE, nullptr, rows, scale + 1, nullptr,
                 Eq, Eq, Sq, Lq, 0, 32, kh, kl, 1.0f };
    GArgs gV = { xbf, wbf + 2 * EE, vb, rows, scale + 2, nullptr,
                 Eq, Eq, Sq, Lq, 0, 32, nullptr, nullptr, 1.0f };
    GArgs gRK = { rt3, kw3, nullptr, nullptr, nullptr, nullptr,
                  3 * Eq, Eq, Rq, Lq, Sq, 2, kh, kl, 1.0f };
    GArgs gRV = { rt3, vw3, vb, nullptr, nullptr, nullptr,
                  3 * Eq, Eq, Rq, Lq, Sq, 2, nullptr, nullptr, 1.0f };
    hmma_gemm5<<<dim3(16, 32, 5), 256, SMEM_GEMM5>>>(gQ, gK, gV, gRK, gRV);
    // 4) transpose+split V
    transpose_v<<<dim3(Lq / 32, Eq / 32, Bq), 256>>>(vb, vth, vtl);
    // 5) attention (3-stage KV pipeline, Q in registers, pre-scaled Q)
    attn_mma3<<<dim3(Sq / 128, Hq, Bq), 256, SMEM_ATTN4>>>(qh, ql, kh, kl, vth, vtl, ao3);
    // 6) output projection + bias
    GArgs gO = { ao3, ow3, out, nullptr, nullptr, ob,
                 3 * Eq, Eq, Bq * Sq, Bq * Sq, 0, 32, nullptr, nullptr, 1.0f };
    hmma_gemm5<<<dim3(16, 32, 1), 256, SMEM_GEMM5>>>(gO, gO, gO, gO, gO);
}

// round 12
// speedup vs baseline: 1.0717x; 1.0024x over previous
#include <cuda_runtime.h>
#include <cuda_bf16.h>
#include <cstdint>

#define Bq 2
#define Sq 2048
#define Rq 128
#define Eq 2048
#define Hq 16
#define Dq 128
#define Lq (Sq + Rq)   // 2176

// ---------------- scratch (device globals, no allocations) ----------------
__device__ __nv_bfloat16 g_xbf[(size_t)Bq * Sq * Eq];      // quantized acts as bf16 ints
__device__ __nv_bfloat16 g_wbf[3][(size_t)Eq * Eq];        // ternary weights as bf16
__device__ __nv_bfloat16 g_rt3[(size_t)Bq * Rq * 3 * Eq];  // reasoning tokens split [hi|hi|lo]
__device__ __nv_bfloat16 g_kw3[(size_t)Eq * 3 * Eq];       // k_w split [hi|lo|hi]
__device__ __nv_bfloat16 g_vw3[(size_t)Eq * 3 * Eq];       // v_w split
__device__ __nv_bfloat16 g_ow3[(size_t)Eq * 3 * Eq];       // out_w split
__device__ __nv_bfloat16 g_ao3[(size_t)Bq * Sq * 3 * Eq];  // attn out split [hi|hi|lo]
__device__ __nv_bfloat16 g_qh[(size_t)Bq * Sq * Eq];       // Q hi (pre-scaled by 1/sqrt(D))
__device__ __nv_bfloat16 g_ql[(size_t)Bq * Sq * Eq];       // Q lo
__device__ __nv_bfloat16 g_kh[(size_t)Bq * Lq * Eq];       // K hi
__device__ __nv_bfloat16 g_kl[(size_t)Bq * Lq * Eq];       // K lo
__device__ __nv_bfloat16 g_vh[(size_t)Bq * Lq * Eq];       // V hi [B,L,E]
__device__ __nv_bfloat16 g_vl[(size_t)Bq * Lq * Eq];       // V lo
__device__ float g_rows[(size_t)Bq * Sq];                  // per-row act scale s
__device__ float g_part[3 * 1024];
__device__ float g_scale[3];

// ---------------- PTX helpers ----------------
typedef unsigned long long ull;
__device__ __forceinline__ uint32_t smem_u32(const void* p) {
    uint32_t a;
    asm("{ .reg .u64 t; cvta.to.shared.u64 t, %1; cvt.u32.u64 %0, t; }" : "=r"(a) : "l"(p));
    return a;
}
__device__ __forceinline__ void ldmx4(uint32_t* r, uint32_t addr) {
    asm volatile("ldmatrix.sync.aligned.m8n8.x4.shared.b16 {%0,%1,%2,%3}, [%4];"
                 : "=r"(r[0]), "=r"(r[1]), "=r"(r[2]), "=r"(r[3]) : "r"(addr));
}
__device__ __forceinline__ void ldmx4t(uint32_t* r, uint32_t addr) {
    asm volatile("ldmatrix.sync.aligned.m8n8.x4.trans.shared.b16 {%0,%1,%2,%3}, [%4];"
                 : "=r"(r[0]), "=r"(r[1]), "=r"(r[2]), "=r"(r[3]) : "r"(addr));
}
__device__ __forceinline__ void mma16816(float* c, const uint32_t* a, const uint32_t* b) {
    asm volatile("mma.sync.aligned.m16n8k16.row.col.f32.bf16.bf16.f32 "
                 "{%0,%1,%2,%3}, {%4,%5,%6,%7}, {%8,%9}, {%0,%1,%2,%3};"
                 : "+f"(c[0]), "+f"(c[1]), "+f"(c[2]), "+f"(c[3])
                 : "r"(a[0]), "r"(a[1]), "r"(a[2]), "r"(a[3]), "r"(b[0]), "r"(b[1]));
}
__device__ __forceinline__ void cpa16(uint32_t dst, const void* src) {
    asm volatile("cp.async.cg.shared.global [%0], [%1], 16;" :: "r"(dst), "l"(src) : "memory");
}
__device__ __forceinline__ void cpa_commit() {
    asm volatile("cp.async.commit_group;" ::: "memory");
}
__device__ __forceinline__ void cpa_wait0() {
    asm volatile("cp.async.wait_group 0;" ::: "memory");
}
__device__ __forceinline__ void cpa_wait1() {
    asm volatile("cp.async.wait_group 1;" ::: "memory");
}
// smem rows of 32 bf16 (64B); 16B group g stored at g ^ ((row>>1)&3)
__device__ __forceinline__ uint32_t swoff(int r, int g) {
    return (uint32_t)(r * 64 + ((g ^ ((r >> 1) & 3)) << 4));
}
// per-lane address offset for B-side ldmatrix.x4 (2 consecutive n-frags of 8 rows)
__device__ __forceinline__ uint32_t boff4(int base_row, int lane) {
    int r = base_row + ((lane >> 4) << 3) + (lane & 7);
    int g = (lane >> 3) & 1;
    return swoff(r, g);
}
// pack two fp32 into bf16x2 hi + residual lo
__device__ __forceinline__ void hl2(float x, float y, uint32_t& h, uint32_t& l) {
    __nv_bfloat162 hh, ll;
    hh.x = __float2bfloat16(x);
    hh.y = __float2bfloat16(y);
    ll.x = __float2bfloat16(x - __bfloat162float(hh.x));
    ll.y = __float2bfloat16(y - __bfloat162float(hh.y));
    h = *(uint32_t*)&hh;
    l = *(uint32_t*)&ll;
}

// ---------------- weight mean(|w|) : stage 1 ----------------
__global__ void reduce_abs_kernel(const float* __restrict__ w0, const float* __restrict__ w1,
                                  const float* __restrict__ w2, float* __restrict__ part) {
    const float* w = (blockIdx.y == 0) ? w0 : ((blockIdx.y == 1) ? w1 : w2);
    int t = threadIdx.x;
    size_t base = (size_t)blockIdx.x * 4096;
    float s = 0.f;
#pragma unroll
    for (int i = 0; i < 16; i++) s += fabsf(w[base + t + i * 256]);
    __shared__ float red[256];
    red[t] = s;
    __syncthreads();
    for (int o = 128; o > 0; o >>= 1) {
        if (t < o) red[t] += red[t + o];
        __syncthreads();
    }
    if (t == 0) part[blockIdx.y * 1024 + blockIdx.x] = red[0];
}

__global__ void finalize_scale_kernel(const float* __restrict__ part, float* __restrict__ scale) {
    int w = blockIdx.x;
    int t = threadIdx.x;
    float s = part[w * 1024 + t] + part[w * 1024 + t + 256] +
              part[w * 1024 + t + 512] + part[w * 1024 + t + 768];
    __shared__ float red[256];
    red[t] = s;
    __syncthreads();
    for (int o = 128; o > 0; o >>= 1) {
        if (t < o) red[t] += red[t + o];
        __syncthreads();
    }
    if (t == 0) {
        float mean = red[0] * (1.0f / ((float)Eq * (float)Eq));
        scale[w] = fmaxf(mean, 1e-5f);
    }
}

// ---------------- merged weight prep: ternary (q/k/v) + split3 mode-1 (k/v/o) ----------------
__global__ void prep_weights(const float* __restrict__ qw, const float* __restrict__ kw,
                             const float* __restrict__ vw, const float* __restrict__ ow,
                             __nv_bfloat16* __restrict__ wq,
                             __nv_bfloat16* __restrict__ kw3, __nv_bfloat16* __restrict__ vw3,
                             __nv_bfloat16* __restrict__ ow3,
                             const float* __restrict__ scale) {
    int wi = blockIdx.y;
    const float* w = (wi == 0) ? qw : ((wi == 1) ? kw : ((wi == 2) ? vw : ow));
    float inv = (wi < 3) ? __frcp_rn(scale[wi]) : 0.f;
    size_t e0 = ((size_t)blockIdx.x * 256 + threadIdx.x) * 8;
    size_t row = e0 >> 11, col = e0 & 2047;
    __nv_bfloat16* wo = (wi < 3) ? (wq + (size_t)wi * Eq * Eq + e0) : nullptr;
    __nv_bfloat16* y = (wi == 1) ? kw3 : ((wi == 2) ? vw3 : ((wi == 3) ? ow3 : nullptr));
    __nv_bfloat16* yr = y ? (y + row * (size_t)(3 * Eq)) : nullptr;
#pragma unroll
    for (int i = 0; i < 8; i += 4) {
        float4 v = *(const float4*)&w[e0 + i];
        float f[4] = {v.x, v.y, v.z, v.w};
#pragma unroll
        for (int j = 0; j < 4; j++) {
            if (wo)
                wo[i + j] = __float2bfloat16(fminf(fmaxf(rintf(f[j] * inv), -1.f), 1.f));
            if (yr) {
                __nv_bfloat16 hi = __float2bfloat16(f[j]);
                __nv_bfloat16 lo = __float2bfloat16(f[j] - __bfloat162float(hi));
                yr[col + i + j] = hi;
                yr[Eq + col + i + j] = lo;
                yr[2 * Eq + col + i + j] = hi;
            }
        }
    }
}

// ---------------- per-token absmax quantization (warp per row, no syncs) ----------------
__global__ void quant_act_bf16(const float* __restrict__ x, __nv_bfloat16* __restrict__ xq,
                               float* __restrict__ rows) {
    int w = (blockIdx.x * blockDim.x + threadIdx.x) >> 5;  // one warp per row
    int lane = threadIdx.x & 31;
    const float* xr = x + (size_t)w * Eq;
    float4 v[16];
    float mx = 0.f;
#pragma unroll
    for (int i = 0; i < 16; i++) {
        v[i] = *(const float4*)&xr[i * 128 + lane * 4];
        mx = fmaxf(mx, fmaxf(fmaxf(fabsf(v[i].x), fabsf(v[i].y)),
                             fmaxf(fabsf(v[i].z), fabsf(v[i].w))));
    }
#pragma unroll
    for (int o = 16; o > 0; o >>= 1) mx = fmaxf(mx, __shfl_xor_sync(0xffffffffu, mx, o));
    float s = __fdiv_rn(127.0f, fmaxf(mx, 1e-5f));
    if (lane == 0) rows[w] = s;
    __nv_bfloat16* xo = xq + (size_t)w * Eq;
#pragma unroll
    for (int i = 0; i < 16; i++) {
        __nv_bfloat162 p0, p1;
        p0.x = __float2bfloat16(fminf(fmaxf(rintf(v[i].x * s), -128.f), 127.f));
        p0.y = __float2bfloat16(fminf(fmaxf(rintf(v[i].y * s), -128.f), 127.f));
        p1.x = __float2bfloat16(fminf(fmaxf(rintf(v[i].z * s), -128.f), 127.f));
        p1.y = __float2bfloat16(fminf(fmaxf(rintf(v[i].w * s), -128.f), 127.f));
        *(__nv_bfloat162*)&xo[i * 128 + lane * 4] = p0;
        *(__nv_bfloat162*)&xo[i * 128 + lane * 4 + 2] = p1;
    }
}

// ---------------- fp32 -> split-bf16 K-tripling, A side [hi|hi|lo] ----------------
__global__ void split3a(const float* __restrict__ X, __nv_bfloat16* __restrict__ Y) {
    size_t i = (size_t)blockIdx.x * 256 + threadIdx.x;
    size_t row = i >> 11, col = i & 2047;
    float x = X[i];
    __nv_bfloat16 hi = __float2bfloat16(x);
    __nv_bfloat16 lo = __float2bfloat16(x - __bfloat162float(hi));
    __nv_bfloat16* yr = Y + row * (size_t)(3 * Eq);
    yr[col] = hi;
    yr[Eq + col] = hi;
    yr[2 * Eq + col] = lo;
}

// ---------------- HMMA bf16 GEMM: cp.async 3-stage, BK=64, 2 CTAs/SM, z-batched ----------------
struct GArgs {
    const __nv_bfloat16* A;
    const __nv_bfloat16* B;
    float* C;
    const float* rowscale;
    const float* wsp;
    const float* bias;
    int K, Nout, rbi, rbo, roff, ylim;
    __nv_bfloat16* Hout;
    __nv_bfloat16* Lout;
    float cmul;   // extra constant multiplier folded into the epilogue
};

// dynamic smem: 3 stages x (A 16K | B 16K) = 96 KB
#define SMEM_GEMM5 98304

__global__ __launch_bounds__(256, 2) void hmma_gemm5(GArgs ga0, GArgs ga1, GArgs ga2,
                                                     GArgs ga3, GArgs ga4) {
    int z = blockIdx.z;
    GArgs ga = (z == 0) ? ga0 : ((z == 1) ? ga1 : ((z == 2) ? ga2 : ((z == 3) ? ga3 : ga4)));
    if ((int)blockIdx.y >= ga.ylim) return;
    extern __shared__ __align__(128) uint8_t dsm[];
    uint32_t sb = smem_u32(dsm);
    int t = threadIdx.x;
    int lane = t & 31, wid = t >> 5;
    int m0 = blockIdx.y * 128, n0 = blockIdx.x * 128;
    int warp_m = wid & 1, warp_n = wid >> 1;
    const int K = ga.K;

    // cp.async mapping: tile 128 rows x 128 B (2 chunks of 64 B); 1024 groups of 16 B
    const uint8_t* asrc[4];
    const uint8_t* bsrc[4];
    uint32_t gdst[4];
#pragma unroll
    for (int i = 0; i < 4; i++) {
        int idx = t + i * 256;
        int r = idx >> 3, g = idx & 7;
        gdst[i] = (g >> 2) * 8192 + swoff(r, g & 3);
        asrc[i] = (const uint8_t*)(ga.A + (size_t)(m0 + r) * K) + g * 16;
        bsrc[i] = (const uint8_t*)(ga.B + (size_t)(n0 + r) * K) + g * 16;
    }

    uint32_t aaddr[4], baddr4[2];
#pragma unroll
    for (int mi = 0; mi < 4; mi++)
        aaddr[mi] = swoff(warp_m * 64 + mi * 16 + (lane & 15), lane >> 4);
#pragma unroll
    for (int ni2 = 0; ni2 < 2; ni2++)
        baddr4[ni2] = boff4(warp_n * 32 + ni2 * 16, lane);

    const int NK = K >> 6;
    {
#pragma unroll
        for (int i = 0; i < 4; i++) {
            cpa16(sb + gdst[i], asrc[i]);
            cpa16(sb + 16384 + gdst[i], bsrc[i]);
        }
        cpa_commit();
    }

    float c[4][4][4];
#pragma unroll
    for (int mi = 0; mi < 4; mi++)
#pragma unroll
        for (int ni = 0; ni < 4; ni++)
#pragma unroll
            for (int k = 0; k < 4; k++) c[mi][ni][k] = 0.f;

    int s = 0;
    for (int kt = 0; kt < NK; ++kt) {
        if (kt + 1 < NK) {
            int sn = (s + 1 == 3) ? 0 : s + 1;
            uint32_t base = sb + sn * 32768;
            size_t koff = (size_t)(kt + 1) * 128;
#pragma unroll
            for (int i = 0; i < 4; i++) {
                cpa16(base + gdst[i], asrc[i] + koff);
                cpa16(base + 16384 + gdst[i], bsrc[i] + koff);
            }
            cpa_commit();
            cpa_wait1();
        } else {
            cpa_wait0();
        }
        __syncthreads();

        uint32_t Ab = sb + s * 32768;
        uint32_t Bb = Ab + 16384;
#pragma unroll
        for (int ch = 0; ch < 2; ch++)
#pragma unroll
            for (int ks = 0; ks < 2; ks++) {
                uint32_t kx = ks * 32;
                uint32_t a[4][4], b[2][4];
#pragma unroll
                for (int mi = 0; mi < 4; mi++)
                    ldmx4(a[mi], Ab + ch * 8192 + (aaddr[mi] ^ kx));
#pragma unroll
                for (int ni2 = 0; ni2 < 2; ni2++)
                    ldmx4(b[ni2], Bb + ch * 8192 + (baddr4[ni2] ^ kx));
#pragma unroll
                for (int mi = 0; mi < 4; mi++)
#pragma unroll
                    for (int ni = 0; ni < 4; ni++)
                        mma16816(c[mi][ni], a[mi], &b[ni >> 1][(ni & 1) * 2]);
            }
        s = (s + 1 == 3) ? 0 : s + 1;
    }

    float ws = ga.cmul * (ga.wsp ? *ga.wsp : 1.0f);
    int g = lane >> 2, tg = lane & 3;
#pragma unroll
    for (int mi = 0; mi < 4; mi++) {
        int mA = m0 + warp_m * 64 + mi * 16 + g;
        int mB = mA + 8;
        float fA = ga.rowscale ? (ws / ga.rowscale[mA]) : ws;
        float fB = ga.rowscale ? (ws / ga.rowscale[mB]) : ws;
        int oA = (mA / ga.rbi) * ga.rbo + ga.roff + (mA % ga.rbi);
        int oB = (mB / ga.rbi) * ga.rbo + ga.roff + (mB % ga.rbi);
        if (ga.Hout) {
            __nv_bfloat16* hA = ga.Hout + (size_t)oA * ga.Nout;
            __nv_bfloat16* hB = ga.Hout + (size_t)oB * ga.Nout;
            __nv_bfloat16* lA = ga.Lout + (size_t)oA * ga.Nout;
            __nv_bfloat16* lB = ga.Lout + (size_t)oB * ga.Nout;
#pragma unroll
            for (int ni = 0; ni < 4; ni++) {
                int col = n0 + warp_n * 32 + ni * 8 + tg * 2;
                uint32_t h0, l0v, h1, l1v;
                hl2(c[mi][ni][0] * fA, c[mi][ni][1] * fA, h0, l0v);
                hl2(c[mi][ni][2] * fB, c[mi][ni][3] * fB, h1, l1v);
                *(uint32_t*)&hA[col] = h0;
                *(uint32_t*)&lA[col] = l0v;
                *(uint32_t*)&hB[col] = h1;
                *(uint32_t*)&lB[col] = l1v;
            }
        } else {
            float* crA = ga.C + (size_t)oA * ga.Nout;
            float* crB = ga.C + (size_t)oB * ga.Nout;
#pragma unroll
            for (int ni = 0; ni < 4; ni++) {
                int col = n0 + warp_n * 32 + ni * 8 + tg * 2;
                float b0 = 0.f, b1 = 0.f;
                if (ga.bias) { b0 = ga.bias[col]; b1 = ga.bias[col + 1]; }
                float2 vA, vB;
                vA.x = c[mi][ni][0] * fA + b0;
                vA.y = c[mi][ni][1] * fA + b1;
                vB.x = c[mi][ni][2] * fB + b0;
                vB.y = c[mi][ni][3] * fB + b1;
                *(float2*)&crA[col] = vA;
                *(float2*)&crB[col] = vB;
            }
        }
    }
}

// ---------------- FA2-style HMMA flash attention, 3-stage KV, Q in registers ----------------
// Q pre-scaled by 1/sqrt(D). V stored [B,L,E] like K; PV uses ldmatrix.trans.
// smem: 3 stages x 64K (KH 16K | KL 16K | VH 16K | VL 16K). Q preloaded via stage 2.
#define SMEM_ATTN4 (3 * 65536)   // 196608

__global__ __launch_bounds__(256, 1) void attn_mma3(
    const __nv_bfloat16* __restrict__ Qh, const __nv_bfloat16* __restrict__ Ql,
    const __nv_bfloat16* __restrict__ Kh, const __nv_bfloat16* __restrict__ Kl,
    const __nv_bfloat16* __restrict__ Vh, const __nv_bfloat16* __restrict__ Vl,
    __nv_bfloat16* __restrict__ O3) {
    extern __shared__ char smg[];
    uint32_t sb = smem_u32(smg);
    int t = threadIdx.x;
    int lane = t & 31, wid = t >> 5;
    int qb = blockIdx.x * 128;
    int h = blockIdx.y;
    int b = blockIdx.z;

    const int wm = wid;
    const uint32_t a_off = swoff(wm * 16 + (lane & 15), lane >> 4);
    uint32_t k4[4];
#pragma unroll
    for (int ni2 = 0; ni2 < 4; ni2++) k4[ni2] = boff4(ni2 * 16, lane);
    // trans-V per-lane address components: row within 16-key chunk, col-group parts
    const int vrow = (lane & 7) + ((lane >> 3) & 1) * 8;
    const uint32_t vbase = (uint32_t)(vrow * 64);
    const uint32_t vrx = (uint32_t)((vrow >> 1) & 3);
    const uint32_t vg = (uint32_t)((lane >> 4) & 1);
    const uint32_t ge = ((vg ^ vrx) << 4);          // ni2 even: group = vg
    const uint32_t go = (((2 + vg) ^ vrx) << 4);    // ni2 odd: group = 2+vg
    const int g4 = lane >> 2, tg = lane & 3;

    // ---- issue Q into stage 2 (group 0) ----
    uint32_t qbase = sb + 2 * 65536;
    {
        const __nv_bfloat16* Qhg = Qh + ((size_t)(b * Sq + qb)) * Eq + h * Dq;
        const __nv_bfloat16* Qlg = Ql + ((size_t)(b * Sq + qb)) * Eq + h * Dq;
#pragma unroll
        for (int i = 0; i < 8; i++) {
            int idx = t + i * 256;
            int r = idx >> 4, g = idx & 15;
            uint32_t dst = (g >> 2) * 8192 + swoff(r, g & 3);
            cpa16(qbase + dst, Qhg + (size_t)r * Eq + g * 8);
            cpa16(qbase + 32768 + dst, Qlg + (size_t)r * Eq + g * 8);
        }
        cpa_commit();
    }

    const __nv_bfloat16* Khb = Kh + ((size_t)(b * Lq)) * Eq + h * Dq;
    const __nv_bfloat16* Klb = Kl + ((size_t)(b * Lq)) * Eq + h * Dq;
    const __nv_bfloat16* Vhb = Vh + ((size_t)(b * Lq)) * Eq + h * Dq;
    const __nv_bfloat16* Vlb = Vl + ((size_t)(b * Lq)) * Eq + h * Dq;

    auto issueKV = [&](int kt) {
        uint32_t base = sb + (kt % 3) * 65536;
        const __nv_bfloat16* KhT = Khb + (size_t)(kt * 64) * Eq;
        const __nv_bfloat16* KlT = Klb + (size_t)(kt * 64) * Eq;
        const __nv_bfloat16* VhT = Vhb + (size_t)(kt * 64) * Eq;
        const __nv_bfloat16* VlT = Vlb + (size_t)(kt * 64) * Eq;
#pragma unroll
        for (int i = 0; i < 4; i++) {
            int idx = t + i * 256;
            int r = idx >> 4, g = idx & 15;
            uint32_t dst = (g >> 2) * 4096 + swoff(r, g & 3);
            size_t src = (size_t)r * Eq + g * 8;
            cpa16(base + dst, KhT + src);
            cpa16(base + 16384 + dst, KlT + src);
            cpa16(base + 32768 + dst, VhT + src);
            cpa16(base + 49152 + dst, VlT + src);
        }
        cpa_commit();
    };
    issueKV(0);          // group 1
    cpa_wait1();         // Q (group 0) complete
    __syncthreads();

    // ---- Q hi/lo fragments -> registers (freed stage 2 for KV tile 2) ----
    uint32_t qfh[4][2][4], qfl[4][2][4];
#pragma unroll
    for (int ch = 0; ch < 4; ch++)
#pragma unroll
        for (int ks = 0; ks < 2; ks++) {
            ldmx4(qfh[ch][ks], qbase + ch * 8192 + (a_off ^ (ks * 32)));
            ldmx4(qfl[ch][ks], qbase + 32768 + ch * 8192 + (a_off ^ (ks * 32)));
        }

    float m0 = -1e30f, m1 = -1e30f, l0 = 0.f, l1 = 0.f;
    float co[16][4];
#pragma unroll
    for (int i = 0; i < 16; i++)
#pragma unroll
        for (int j = 0; j < 4; j++) co[i][j] = 0.f;

    const int NT = Lq / 64;  // 34
    for (int kt = 0; kt < NT; ++kt) {
        if (kt + 1 < NT) { issueKV(kt + 1); cpa_wait1(); }
        else cpa_wait0();
        __syncthreads();   // the ONLY sync per iteration
        uint32_t kvb = sb + (kt % 3) * 65536;

        // ---- S = Qh.Kh + Qh.Kl + Ql.Kh (already scaled via Q) ----
        float cs[8][4];
#pragma unroll
        for (int i = 0; i < 8; i++)
#pragma unroll
            for (int j = 0; j < 4; j++) cs[i][j] = 0.f;
#pragma unroll
        for (int ch = 0; ch < 4; ch++)
#pragma unroll
            for (int ks = 0; ks < 2; ks++) {
                uint32_t kx = ks * 32;
#pragma unroll
                for (int ni2 = 0; ni2 < 4; ni2++) {
                    uint32_t bh[4], bl[4];
                    uint32_t ba = kvb + ch * 4096 + (k4[ni2] ^ kx);
                    ldmx4(bh, ba);
                    ldmx4(bl, ba + 16384);
                    mma16816(cs[2 * ni2], qfh[ch][ks], bh);
                    mma16816(cs[2 * ni2], qfh[ch][ks], bl);
                    mma16816(cs[2 * ni2], qfl[ch][ks], bh);
                    mma16816(cs[2 * ni2 + 1], qfh[ch][ks], bh + 2);
                    mma16816(cs[2 * ni2 + 1], qfh[ch][ks], bl + 2);
                    mma16816(cs[2 * ni2 + 1], qfl[ch][ks], bh + 2);
                }
            }

        // ---- in-register softmax ----
        float tm0 = -1e30f, tm1 = -1e30f;
#pragma unroll
        for (int ni = 0; ni < 8; ni++) {
            tm0 = fmaxf(tm0, fmaxf(cs[ni][0], cs[ni][1]));
            tm1 = fmaxf(tm1, fmaxf(cs[ni][2], cs[ni][3]));
        }
        tm0 = fmaxf(tm0, __shfl_xor_sync(0xffffffffu, tm0, 1));
        tm0 = fmaxf(tm0, __shfl_xor_sync(0xffffffffu, tm0, 2));
        tm1 = fmaxf(tm1, __shfl_xor_sync(0xffffffffu, tm1, 1));
        tm1 = fmaxf(tm1, __shfl_xor_sync(0xffffffffu, tm1, 2));
        float nm0 = fmaxf(m0, tm0), nm1 = fmaxf(m1, tm1);
        float al0 = __expf(m0 - nm0), al1 = __expf(m1 - nm1);
        m0 = nm0; m1 = nm1;

        float rs0 = 0.f, rs1 = 0.f;
#pragma unroll
        for (int ni = 0; ni < 8; ni++) {
            cs[ni][0] = __expf(cs[ni][0] - m0); rs0 += cs[ni][0];
            cs[ni][1] = __expf(cs[ni][1] - m0); rs0 += cs[ni][1];
            cs[ni][2] = __expf(cs[ni][2] - m1); rs1 += cs[ni][2];
            cs[ni][3] = __expf(cs[ni][3] - m1); rs1 += cs[ni][3];
        }
        rs0 += __shfl_xor_sync(0xffffffffu, rs0, 1);
        rs0 += __shfl_xor_sync(0xffffffffu, rs0, 2);
        rs1 += __shfl_xor_sync(0xffffffffu, rs1, 1);
        rs1 += __shfl_xor_sync(0xffffffffu, rs1, 2);
        l0 = l0 * al0 + rs0;
        l1 = l1 * al1 + rs1;

        // ---- P hi/lo A-fragments ----
        uint32_t phf[4][4], plf[4][4];
#pragma unroll
        for (int ck = 0; ck < 4; ck++) {
            hl2(cs[2 * ck][0], cs[2 * ck][1], phf[ck][0], plf[ck][0]);
            hl2(cs[2 * ck][2], cs[2 * ck][3], phf[ck][1], plf[ck][1]);
            hl2(cs[2 * ck + 1][0], cs[2 * ck + 1][1], phf[ck][2], plf[ck][2]);
            hl2(cs[2 * ck + 1][2], cs[2 * ck + 1][3], phf[ck][3], plf[ck][3]);
        }

        // ---- rescale O ----
#pragma unroll
        for (int ni = 0; ni < 16; ni++) {
            co[ni][0] *= al0; co[ni][1] *= al0;
            co[ni][2] *= al1; co[ni][3] *= al1;
        }

        // ---- O += Ph.Vh + Ph.Vl + Pl.Vh (trans-loaded V) ----
#pragma unroll
        for (int ck = 0; ck < 4; ck++) {
            uint32_t rofs = kvb + 32768 + (uint32_t)(ck * 1024) + vbase;
#pragma unroll
            for (int ni2 = 0; ni2 < 8; ni2++) {
                uint32_t bh[4], bl[4];
                uint32_t ba = rofs + (uint32_t)((ni2 >> 1) * 4096) + ((ni2 & 1) ? go : ge);
                ldmx4t(bh, ba);
                ldmx4t(bl, ba + 16384);
                mma16816(co[2 * ni2], phf[ck], bh);
                mma16816(co[2 * ni2], phf[ck], bl);
                mma16816(co[2 * ni2], plf[ck], bh);
                mma16816(co[2 * ni2 + 1], phf[ck], bh + 2);
                mma16816(co[2 * ni2 + 1], phf[ck], bl + 2);
                mma16816(co[2 * ni2 + 1], plf[ck], bh + 2);
            }
        }
    }

    // ---- epilogue: write O split [hi|hi|lo] ----
    float il0 = 1.0f / l0, il1 = 1.0f / l1;
    int r0 = wm * 16 + g4, r1 = r0 + 8;
    __nv_bfloat16* O0 = O3 + ((size_t)(b * Sq + qb + r0)) * (3 * Eq) + h * Dq;
    __nv_bfloat16* O1 = O3 + ((size_t)(b * Sq + qb + r1)) * (3 * Eq) + h * Dq;
#pragma unroll
    for (int ni = 0; ni < 16; ni++) {
        int col = ni * 8 + tg * 2;
        uint32_t h0, lo0, h1, lo1;
        hl2(co[ni][0] * il0, co[ni][1] * il0, h0, lo0);
        hl2(co[ni][2] * il1, co[ni][3] * il1, h1, lo1);
        *(uint32_t*)(O0 + col) = h0;
        *(uint32_t*)(O0 + Eq + col) = h0;
        *(uint32_t*)(O0 + 2 * Eq + col) = lo0;
        *(uint32_t*)(O1 + col) = h1;
        *(uint32_t*)(O1 + Eq + col) = h1;
        *(uint32_t*)(O1 + 2 * Eq + col) = lo1;
    }
}

// ---------------- host launcher ----------------
extern "C" void kernel_launch(void* const* d_in, const int* in_sizes, int n_in,
                              void* d_out, int out_size) {
    const float* x  = (const float*)d_in[0];
    const float* rt = (const float*)d_in[1];
    const float* qw = (const float*)d_in[2];
    const float* kw = (const float*)d_in[3];
    const float* vw = (const float*)d_in[4];
    const float* ow = (const float*)d_in[5];
    const float* ob = (const float*)d_in[6];
    float* out = (float*)d_out;

    __nv_bfloat16 *xbf, *wbf, *rt3, *kw3, *vw3, *ow3, *ao3, *qh, *ql, *kh, *kl, *vh, *vl;
    float *rows, *part, *scale;
    cudaGetSymbolAddress((void**)&xbf, g_xbf);
    cudaGetSymbolAddress((void**)&wbf, g_wbf);
    cudaGetSymbolAddress((void**)&rt3, g_rt3);
    cudaGetSymbolAddress((void**)&kw3, g_kw3);
    cudaGetSymbolAddress((void**)&vw3, g_vw3);
    cudaGetSymbolAddress((void**)&ow3, g_ow3);
    cudaGetSymbolAddress((void**)&ao3, g_ao3);
    cudaGetSymbolAddress((void**)&qh, g_qh);
    cudaGetSymbolAddress((void**)&ql, g_ql);
    cudaGetSymbolAddress((void**)&kh, g_kh);
    cudaGetSymbolAddress((void**)&kl, g_kl);
    cudaGetSymbolAddress((void**)&vh, g_vh);
    cudaGetSymbolAddress((void**)&vl, g_vl);
    cudaGetSymbolAddress((void**)&rows, g_rows);
    cudaGetSymbolAddress((void**)&part, g_part);
    cudaGetSymbolAddress((void**)&scale, g_scale);

    cudaFuncSetAttribute(attn_mma3, cudaFuncAttributeMaxDynamicSharedMemorySize, SMEM_ATTN4);
    cudaFuncSetAttribute(hmma_gemm5, cudaFuncAttributeMaxDynamicSharedMemorySize, SMEM_GEMM5);

    const float SCALE = 0.08838834764831845f;  // 1/sqrt(128), folded into Q epilogue

    // 1) weight scales
    reduce_abs_kernel<<<dim3(1024, 3), 256>>>(qw, kw, vw, part);
    finalize_scale_kernel<<<3, 256>>>(part, scale);
    // 2) merged weight prep (ternary q/k/v + splits k/v/o) + act quant + rt split
    prep_weights<<<dim3(2048, 4), 256>>>(qw, kw, vw, ow, wbf, kw3, vw3, ow3, scale);
    quant_act_bf16<<<(Bq * Sq) / 8, 256>>>(x, xbf, rows);
    split3a<<<(Bq * Rq * Eq) / 256, 256>>>(rt, rt3);
    // 3) QKV + reasoning projections in ONE launch (z = 0..4); all write split bf16
    size_t EE = (size_t)Eq * Eq;
    GArgs gQ = { xbf, wbf + 0 * EE, nullptr, rows, scale + 0, nullptr,
                 Eq, Eq, Sq, Sq, 0, 32, qh, ql, SCALE };
    GArgs gK = { xbf, wbf + 1 * EE, nullptr, rows, scale + 1, nullptr,
                 Eq, Eq, Sq, Lq, 0, 32, kh, kl, 1.0f };
    GArgs gV = { xbf, wbf + 2 * EE, nullptr, rows, scale + 2, nullptr,
                 Eq, Eq, Sq, Lq, 0, 32, vh, vl, 1.0f };
    GArgs gRK = { rt3, kw3, nullptr, nullptr, nullptr, nullptr,
                  3 * Eq, Eq, Rq, Lq, Sq, 2, kh, kl, 1.0f };
    GArgs gRV = { rt3, vw3, nullptr, nullptr, nullptr, nullptr,
                  3 * Eq, Eq, Rq, Lq, Sq, 2, vh, vl, 1.0f };
    hmma_gemm5<<<dim3(16, 32, 5), 256, SMEM_GEMM5>>>(gQ, gK, gV, gRK, gRV);
    // 4) attention (3-stage KV pipeline, Q in registers, trans-V) -> writes [hi|hi|lo]
    attn_mma3<<<dim3(Sq / 128, Hq, Bq), 256, SMEM_ATTN4>>>(qh, ql, kh, kl, vh, vl, ao3);
    // 5) output projection + bias
    GArgs gO = { ao3, ow3, out, nullptr, nullptr, ob,
                 3 * Eq, Eq, Bq * Sq, Bq * Sq, 0, 32, nullptr, nullptr, 1.0f };
    hmma_gemm5<<<dim3(16, 32, 1), 256, SMEM_GEMM5>>>(gO, gO, gO, gO, gO);
}

// round 13
// speedup vs baseline: 1.1130x; 1.0385x over previous
#include <cuda_runtime.h>
#include <cuda_bf16.h>
#include <cstdint>

#define Bq 2
#define Sq 2048
#define Rq 128
#define Eq 2048
#define Hq 16
#define Dq 128
#define Lq (Sq + Rq)   // 2176

// ---------------- scratch (device globals, no allocations) ----------------
__device__ __nv_bfloat16 g_xbf[(size_t)Bq * Sq * Eq];      // quantized acts as bf16 ints
__device__ __nv_bfloat16 g_wbf[3][(size_t)Eq * Eq];        // ternary weights as bf16
__device__ __nv_bfloat16 g_rt3[(size_t)Bq * Rq * 3 * Eq];  // reasoning tokens split [hi|hi|lo]
__device__ __nv_bfloat16 g_kw3[(size_t)Eq * 3 * Eq];       // k_w split [hi|lo|hi]
__device__ __nv_bfloat16 g_vw3[(size_t)Eq * 3 * Eq];       // v_w split
__device__ __nv_bfloat16 g_ow3[(size_t)Eq * 3 * Eq];       // out_w split
__device__ __nv_bfloat16 g_ao3[(size_t)Bq * Sq * 3 * Eq];  // attn out split [hi|hi|lo]
__device__ __nv_bfloat16 g_qh[(size_t)Bq * Sq * Eq];       // Q hi (pre-scaled by 1/sqrt(D))
__device__ __nv_bfloat16 g_ql[(size_t)Bq * Sq * Eq];       // Q lo
__device__ __nv_bfloat16 g_kh[(size_t)Bq * Lq * Eq];       // K hi
__device__ __nv_bfloat16 g_kl[(size_t)Bq * Lq * Eq];       // K lo
__device__ __nv_bfloat16 g_vh[(size_t)Bq * Lq * Eq];       // V hi [B,L,E]
__device__ __nv_bfloat16 g_vl[(size_t)Bq * Lq * Eq];       // V lo
__device__ float g_rows[(size_t)Bq * Sq];                  // per-row act scale s
__device__ float g_part[3 * 1024];
__device__ float g_scale[3];

// ---------------- PTX helpers ----------------
typedef unsigned long long ull;
__device__ __forceinline__ uint32_t smem_u32(const void* p) {
    uint32_t a;
    asm("{ .reg .u64 t; cvta.to.shared.u64 t, %1; cvt.u32.u64 %0, t; }" : "=r"(a) : "l"(p));
    return a;
}
__device__ __forceinline__ void ldmx4(uint32_t* r, uint32_t addr) {
    asm volatile("ldmatrix.sync.aligned.m8n8.x4.shared.b16 {%0,%1,%2,%3}, [%4];"
                 : "=r"(r[0]), "=r"(r[1]), "=r"(r[2]), "=r"(r[3]) : "r"(addr));
}
__device__ __forceinline__ void ldmx4t(uint32_t* r, uint32_t addr) {
    asm volatile("ldmatrix.sync.aligned.m8n8.x4.trans.shared.b16 {%0,%1,%2,%3}, [%4];"
                 : "=r"(r[0]), "=r"(r[1]), "=r"(r[2]), "=r"(r[3]) : "r"(addr));
}
__device__ __forceinline__ void mma16816(float* c, const uint32_t* a, const uint32_t* b) {
    asm volatile("mma.sync.aligned.m16n8k16.row.col.f32.bf16.bf16.f32 "
                 "{%0,%1,%2,%3}, {%4,%5,%6,%7}, {%8,%9}, {%0,%1,%2,%3};"
                 : "+f"(c[0]), "+f"(c[1]), "+f"(c[2]), "+f"(c[3])
                 : "r"(a[0]), "r"(a[1]), "r"(a[2]), "r"(a[3]), "r"(b[0]), "r"(b[1]));
}
__device__ __forceinline__ void cpa16(uint32_t dst, const void* src) {
    asm volatile("cp.async.cg.shared.global [%0], [%1], 16;" :: "r"(dst), "l"(src) : "memory");
}
__device__ __forceinline__ void cpa_commit() {
    asm volatile("cp.async.commit_group;" ::: "memory");
}
__device__ __forceinline__ void cpa_wait0() {
    asm volatile("cp.async.wait_group 0;" ::: "memory");
}
__device__ __forceinline__ void cpa_wait1() {
    asm volatile("cp.async.wait_group 1;" ::: "memory");
}
// smem rows of 32 bf16 (64B); 16B group g stored at g ^ ((row>>1)&3)
__device__ __forceinline__ uint32_t swoff(int r, int g) {
    return (uint32_t)(r * 64 + ((g ^ ((r >> 1) & 3)) << 4));
}
// per-lane address offset for B-side ldmatrix.x4 (2 consecutive n-frags of 8 rows)
__device__ __forceinline__ uint32_t boff4(int base_row, int lane) {
    int r = base_row + ((lane >> 4) << 3) + (lane & 7);
    int g = (lane >> 3) & 1;
    return swoff(r, g);
}
// pack two fp32 into bf16x2 hi + residual lo
__device__ __forceinline__ void hl2(float x, float y, uint32_t& h, uint32_t& l) {
    __nv_bfloat162 hh, ll;
    hh.x = __float2bfloat16(x);
    hh.y = __float2bfloat16(y);
    ll.x = __float2bfloat16(x - __bfloat162float(hh.x));
    ll.y = __float2bfloat16(y - __bfloat162float(hh.y));
    h = *(uint32_t*)&hh;
    l = *(uint32_t*)&ll;
}

// ---------------- weight mean(|w|) : stage 1 ----------------
__global__ void reduce_abs_kernel(const float* __restrict__ w0, const float* __restrict__ w1,
                                  const float* __restrict__ w2, float* __restrict__ part) {
    const float* w = (blockIdx.y == 0) ? w0 : ((blockIdx.y == 1) ? w1 : w2);
    int t = threadIdx.x;
    size_t base = (size_t)blockIdx.x * 4096;
    float s = 0.f;
#pragma unroll
    for (int i = 0; i < 16; i++) s += fabsf(w[base + t + i * 256]);
    __shared__ float red[256];
    red[t] = s;
    __syncthreads();
    for (int o = 128; o > 0; o >>= 1) {
        if (t < o) red[t] += red[t + o];
        __syncthreads();
    }
    if (t == 0) part[blockIdx.y * 1024 + blockIdx.x] = red[0];
}

__global__ void finalize_scale_kernel(const float* __restrict__ part, float* __restrict__ scale) {
    int w = blockIdx.x;
    int t = threadIdx.x;
    float s = part[w * 1024 + t] + part[w * 1024 + t + 256] +
              part[w * 1024 + t + 512] + part[w * 1024 + t + 768];
    __shared__ float red[256];
    red[t] = s;
    __syncthreads();
    for (int o = 128; o > 0; o >>= 1) {
        if (t < o) red[t] += red[t + o];
        __syncthreads();
    }
    if (t == 0) {
        float mean = red[0] * (1.0f / ((float)Eq * (float)Eq));
        scale[w] = fmaxf(mean, 1e-5f);
    }
}

// ---------------- merged weight prep: ternary (q/k/v) + split3 mode-1 (k/v/o) ----------------
__global__ void prep_weights(const float* __restrict__ qw, const float* __restrict__ kw,
                             const float* __restrict__ vw, const float* __restrict__ ow,
                             __nv_bfloat16* __restrict__ wq,
                             __nv_bfloat16* __restrict__ kw3, __nv_bfloat16* __restrict__ vw3,
                             __nv_bfloat16* __restrict__ ow3,
                             const float* __restrict__ scale) {
    int wi = blockIdx.y;
    const float* w = (wi == 0) ? qw : ((wi == 1) ? kw : ((wi == 2) ? vw : ow));
    float inv = (wi < 3) ? __frcp_rn(scale[wi]) : 0.f;
    size_t e0 = ((size_t)blockIdx.x * 256 + threadIdx.x) * 8;
    size_t row = e0 >> 11, col = e0 & 2047;
    __nv_bfloat16* wo = (wi < 3) ? (wq + (size_t)wi * Eq * Eq + e0) : nullptr;
    __nv_bfloat16* y = (wi == 1) ? kw3 : ((wi == 2) ? vw3 : ((wi == 3) ? ow3 : nullptr));
    __nv_bfloat16* yr = y ? (y + row * (size_t)(3 * Eq)) : nullptr;
#pragma unroll
    for (int i = 0; i < 8; i += 4) {
        float4 v = *(const float4*)&w[e0 + i];
        float f[4] = {v.x, v.y, v.z, v.w};
#pragma unroll
        for (int j = 0; j < 4; j++) {
            if (wo)
                wo[i + j] = __float2bfloat16(fminf(fmaxf(rintf(f[j] * inv), -1.f), 1.f));
            if (yr) {
                __nv_bfloat16 hi = __float2bfloat16(f[j]);
                __nv_bfloat16 lo = __float2bfloat16(f[j] - __bfloat162float(hi));
                yr[col + i + j] = hi;
                yr[Eq + col + i + j] = lo;
                yr[2 * Eq + col + i + j] = hi;
            }
        }
    }
}

// ---------------- per-token absmax quantization (warp per row, no syncs) ----------------
__global__ void quant_act_bf16(const float* __restrict__ x, __nv_bfloat16* __restrict__ xq,
                               float* __restrict__ rows) {
    int w = (blockIdx.x * blockDim.x + threadIdx.x) >> 5;  // one warp per row
    int lane = threadIdx.x & 31;
    const float* xr = x + (size_t)w * Eq;
    float4 v[16];
    float mx = 0.f;
#pragma unroll
    for (int i = 0; i < 16; i++) {
        v[i] = *(const float4*)&xr[i * 128 + lane * 4];
        mx = fmaxf(mx, fmaxf(fmaxf(fabsf(v[i].x), fabsf(v[i].y)),
                             fmaxf(fabsf(v[i].z), fabsf(v[i].w))));
    }
#pragma unroll
    for (int o = 16; o > 0; o >>= 1) mx = fmaxf(mx, __shfl_xor_sync(0xffffffffu, mx, o));
    float s = __fdiv_rn(127.0f, fmaxf(mx, 1e-5f));
    if (lane == 0) rows[w] = s;
    __nv_bfloat16* xo = xq + (size_t)w * Eq;
#pragma unroll
    for (int i = 0; i < 16; i++) {
        __nv_bfloat162 p0, p1;
        p0.x = __float2bfloat16(fminf(fmaxf(rintf(v[i].x * s), -128.f), 127.f));
        p0.y = __float2bfloat16(fminf(fmaxf(rintf(v[i].y * s), -128.f), 127.f));
        p1.x = __float2bfloat16(fminf(fmaxf(rintf(v[i].z * s), -128.f), 127.f));
        p1.y = __float2bfloat16(fminf(fmaxf(rintf(v[i].w * s), -128.f), 127.f));
        *(__nv_bfloat162*)&xo[i * 128 + lane * 4] = p0;
        *(__nv_bfloat162*)&xo[i * 128 + lane * 4 + 2] = p1;
    }
}

// ---------------- fp32 -> split-bf16 K-tripling, A side [hi|hi|lo] ----------------
__global__ void split3a(const float* __restrict__ X, __nv_bfloat16* __restrict__ Y) {
    size_t i = (size_t)blockIdx.x * 256 + threadIdx.x;
    size_t row = i >> 11, col = i & 2047;
    float x = X[i];
    __nv_bfloat16 hi = __float2bfloat16(x);
    __nv_bfloat16 lo = __float2bfloat16(x - __bfloat162float(hi));
    __nv_bfloat16* yr = Y + row * (size_t)(3 * Eq);
    yr[col] = hi;
    yr[Eq + col] = hi;
    yr[2 * Eq + col] = lo;
}

// ---------------- HMMA bf16 GEMM: cp.async 3-stage, BK=64, 2 CTAs/SM, z-batched ----------------
struct GArgs {
    const __nv_bfloat16* A;
    const __nv_bfloat16* B;
    float* C;
    const float* rowscale;
    const float* wsp;
    const float* bias;
    int K, Nout, rbi, rbo, roff, ylim;
    __nv_bfloat16* Hout;
    __nv_bfloat16* Lout;
    float cmul;   // extra constant multiplier folded into the epilogue
};

// dynamic smem: 3 stages x (A 16K | B 16K) = 96 KB
#define SMEM_GEMM5 98304

__global__ __launch_bounds__(256, 2) void hmma_gemm5(GArgs ga0, GArgs ga1, GArgs ga2,
                                                     GArgs ga3, GArgs ga4) {
    int z = blockIdx.z;
    GArgs ga = (z == 0) ? ga0 : ((z == 1) ? ga1 : ((z == 2) ? ga2 : ((z == 3) ? ga3 : ga4)));
    if ((int)blockIdx.y >= ga.ylim) return;
    extern __shared__ __align__(128) uint8_t dsm[];
    uint32_t sb = smem_u32(dsm);
    int t = threadIdx.x;
    int lane = t & 31, wid = t >> 5;
    int m0 = blockIdx.y * 128, n0 = blockIdx.x * 128;
    int warp_m = wid & 1, warp_n = wid >> 1;
    const int K = ga.K;

    const uint8_t* asrc[4];
    const uint8_t* bsrc[4];
    uint32_t gdst[4];
#pragma unroll
    for (int i = 0; i < 4; i++) {
        int idx = t + i * 256;
        int r = idx >> 3, g = idx & 7;
        gdst[i] = (g >> 2) * 8192 + swoff(r, g & 3);
        asrc[i] = (const uint8_t*)(ga.A + (size_t)(m0 + r) * K) + g * 16;
        bsrc[i] = (const uint8_t*)(ga.B + (size_t)(n0 + r) * K) + g * 16;
    }

    uint32_t aaddr[4], baddr4[2];
#pragma unroll
    for (int mi = 0; mi < 4; mi++)
        aaddr[mi] = swoff(warp_m * 64 + mi * 16 + (lane & 15), lane >> 4);
#pragma unroll
    for (int ni2 = 0; ni2 < 2; ni2++)
        baddr4[ni2] = boff4(warp_n * 32 + ni2 * 16, lane);

    const int NK = K >> 6;
    {
#pragma unroll
        for (int i = 0; i < 4; i++) {
            cpa16(sb + gdst[i], asrc[i]);
            cpa16(sb + 16384 + gdst[i], bsrc[i]);
        }
        cpa_commit();
    }

    float c[4][4][4];
#pragma unroll
    for (int mi = 0; mi < 4; mi++)
#pragma unroll
        for (int ni = 0; ni < 4; ni++)
#pragma unroll
            for (int k = 0; k < 4; k++) c[mi][ni][k] = 0.f;

    int s = 0;
    for (int kt = 0; kt < NK; ++kt) {
        if (kt + 1 < NK) {
            int sn = (s + 1 == 3) ? 0 : s + 1;
            uint32_t base = sb + sn * 32768;
            size_t koff = (size_t)(kt + 1) * 128;
#pragma unroll
            for (int i = 0; i < 4; i++) {
                cpa16(base + gdst[i], asrc[i] + koff);
                cpa16(base + 16384 + gdst[i], bsrc[i] + koff);
            }
            cpa_commit();
            cpa_wait1();
        } else {
            cpa_wait0();
        }
        __syncthreads();

        uint32_t Ab = sb + s * 32768;
        uint32_t Bb = Ab + 16384;
#pragma unroll
        for (int ch = 0; ch < 2; ch++)
#pragma unroll
            for (int ks = 0; ks < 2; ks++) {
                uint32_t kx = ks * 32;
                uint32_t a[4][4], b[2][4];
#pragma unroll
                for (int mi = 0; mi < 4; mi++)
                    ldmx4(a[mi], Ab + ch * 8192 + (aaddr[mi] ^ kx));
#pragma unroll
                for (int ni2 = 0; ni2 < 2; ni2++)
                    ldmx4(b[ni2], Bb + ch * 8192 + (baddr4[ni2] ^ kx));
#pragma unroll
                for (int mi = 0; mi < 4; mi++)
#pragma unroll
                    for (int ni = 0; ni < 4; ni++)
                        mma16816(c[mi][ni], a[mi], &b[ni >> 1][(ni & 1) * 2]);
            }
        s = (s + 1 == 3) ? 0 : s + 1;
    }

    float ws = ga.cmul * (ga.wsp ? *ga.wsp : 1.0f);
    int g = lane >> 2, tg = lane & 3;
#pragma unroll
    for (int mi = 0; mi < 4; mi++) {
        int mA = m0 + warp_m * 64 + mi * 16 + g;
        int mB = mA + 8;
        float fA = ga.rowscale ? (ws / ga.rowscale[mA]) : ws;
        float fB = ga.rowscale ? (ws / ga.rowscale[mB]) : ws;
        int oA = (mA / ga.rbi) * ga.rbo + ga.roff + (mA % ga.rbi);
        int oB = (mB / ga.rbi) * ga.rbo + ga.roff + (mB % ga.rbi);
        if (ga.Hout) {
            __nv_bfloat16* hA = ga.Hout + (size_t)oA * ga.Nout;
            __nv_bfloat16* hB = ga.Hout + (size_t)oB * ga.Nout;
            __nv_bfloat16* lA = ga.Lout + (size_t)oA * ga.Nout;
            __nv_bfloat16* lB = ga.Lout + (size_t)oB * ga.Nout;
#pragma unroll
            for (int ni = 0; ni < 4; ni++) {
                int col = n0 + warp_n * 32 + ni * 8 + tg * 2;
                uint32_t h0, l0v, h1, l1v;
                hl2(c[mi][ni][0] * fA, c[mi][ni][1] * fA, h0, l0v);
                hl2(c[mi][ni][2] * fB, c[mi][ni][3] * fB, h1, l1v);
                *(uint32_t*)&hA[col] = h0;
                *(uint32_t*)&lA[col] = l0v;
                *(uint32_t*)&hB[col] = h1;
                *(uint32_t*)&lB[col] = l1v;
            }
        } else {
            float* crA = ga.C + (size_t)oA * ga.Nout;
            float* crB = ga.C + (size_t)oB * ga.Nout;
#pragma unroll
            for (int ni = 0; ni < 4; ni++) {
                int col = n0 + warp_n * 32 + ni * 8 + tg * 2;
                float b0 = 0.f, b1 = 0.f;
                if (ga.bias) { b0 = ga.bias[col]; b1 = ga.bias[col + 1]; }
                float2 vA, vB;
                vA.x = c[mi][ni][0] * fA + b0;
                vA.y = c[mi][ni][1] * fA + b1;
                vB.x = c[mi][ni][2] * fB + b0;
                vB.y = c[mi][ni][3] * fB + b1;
                *(float2*)&crA[col] = vA;
                *(float2*)&crB[col] = vB;
            }
        }
    }
}

// ---------------- FA2 HMMA flash attention: 2 CTAs/SM, 64q/CTA, 32-key 3-stage KV ----------------
// Q pre-scaled by 1/sqrt(D). V stored [B,L,E] like K; PV uses ldmatrix.trans.
// smem/CTA: 3 stages x 32K (KH 8K | KL 8K | VH 8K | VL 8K). Q staged via stage 2 then regs.
#define SMEM_ATTN5 (3 * 32768)   // 98304 -> 2 CTAs/SM

__global__ __launch_bounds__(128, 2) void attn_mma4(
    const __nv_bfloat16* __restrict__ Qh, const __nv_bfloat16* __restrict__ Ql,
    const __nv_bfloat16* __restrict__ Kh, const __nv_bfloat16* __restrict__ Kl,
    const __nv_bfloat16* __restrict__ Vh, const __nv_bfloat16* __restrict__ Vl,
    __nv_bfloat16* __restrict__ O3) {
    extern __shared__ char smg[];
    uint32_t sb = smem_u32(smg);
    int t = threadIdx.x;
    int lane = t & 31, wid = t >> 5;   // 4 warps
    int qb = blockIdx.x * 64;
    int h = blockIdx.y;
    int b = blockIdx.z;

    const int wm = wid;
    const uint32_t a_off = swoff(wm * 16 + (lane & 15), lane >> 4);
    uint32_t k4[2];
#pragma unroll
    for (int ni2 = 0; ni2 < 2; ni2++) k4[ni2] = boff4(ni2 * 16, lane);
    // trans-V per-lane address components (verified in round 12)
    const int vrow = (lane & 7) + ((lane >> 3) & 1) * 8;
    const uint32_t vbase = (uint32_t)(vrow * 64);
    const uint32_t vrx = (uint32_t)((vrow >> 1) & 3);
    const uint32_t vg = (uint32_t)((lane >> 4) & 1);
    const uint32_t ge = ((vg ^ vrx) << 4);          // ni2 even: group = vg
    const uint32_t go = (((2 + vg) ^ vrx) << 4);    // ni2 odd: group = 2+vg
    const int g4 = lane >> 2, tg = lane & 3;

    // ---- issue Q (64 rows x 128 d, hi+lo = 32KB) into stage 2 (group 0) ----
    uint32_t qbase = sb + 2 * 32768;
    {
        const __nv_bfloat16* Qhg = Qh + ((size_t)(b * Sq + qb)) * Eq + h * Dq;
        const __nv_bfloat16* Qlg = Ql + ((size_t)(b * Sq + qb)) * Eq + h * Dq;
#pragma unroll
        for (int i = 0; i < 8; i++) {
            int idx = t + i * 128;
            int r = idx >> 4, g = idx & 15;
            uint32_t dst = (g >> 2) * 4096 + swoff(r, g & 3);
            cpa16(qbase + dst, Qhg + (size_t)r * Eq + g * 8);
            cpa16(qbase + 16384 + dst, Qlg + (size_t)r * Eq + g * 8);
        }
        cpa_commit();
    }

    const __nv_bfloat16* Khb = Kh + ((size_t)(b * Lq)) * Eq + h * Dq;
    const __nv_bfloat16* Klb = Kl + ((size_t)(b * Lq)) * Eq + h * Dq;
    const __nv_bfloat16* Vhb = Vh + ((size_t)(b * Lq)) * Eq + h * Dq;
    const __nv_bfloat16* Vlb = Vl + ((size_t)(b * Lq)) * Eq + h * Dq;

    auto issueKV = [&](int kt) {
        uint32_t base = sb + (kt % 3) * 32768;
        const __nv_bfloat16* KhT = Khb + (size_t)(kt * 32) * Eq;
        const __nv_bfloat16* KlT = Klb + (size_t)(kt * 32) * Eq;
        const __nv_bfloat16* VhT = Vhb + (size_t)(kt * 32) * Eq;
        const __nv_bfloat16* VlT = Vlb + (size_t)(kt * 32) * Eq;
#pragma unroll
        for (int i = 0; i < 4; i++) {
            int idx = t + i * 128;
            int r = idx >> 4, g = idx & 15;
            uint32_t dst = (g >> 2) * 2048 + swoff(r, g & 3);
            size_t src = (size_t)r * Eq + g * 8;
            cpa16(base + dst, KhT + src);
            cpa16(base + 8192 + dst, KlT + src);
            cpa16(base + 16384 + dst, VhT + src);
            cpa16(base + 24576 + dst, VlT + src);
        }
        cpa_commit();
    };
    issueKV(0);          // group 1
    cpa_wait1();         // Q (group 0) complete
    __syncthreads();

    // ---- Q hi/lo fragments -> registers (frees stage 2 for KV tile 2) ----
    uint32_t qfh[4][2][4], qfl[4][2][4];
#pragma unroll
    for (int ch = 0; ch < 4; ch++)
#pragma unroll
        for (int ks = 0; ks < 2; ks++) {
            ldmx4(qfh[ch][ks], qbase + ch * 4096 + (a_off ^ (ks * 32)));
            ldmx4(qfl[ch][ks], qbase + 16384 + ch * 4096 + (a_off ^ (ks * 32)));
        }

    float m0 = -1e30f, m1 = -1e30f, l0 = 0.f, l1 = 0.f;
    float co[16][4];
#pragma unroll
    for (int i = 0; i < 16; i++)
#pragma unroll
        for (int j = 0; j < 4; j++) co[i][j] = 0.f;

    const int NT = Lq / 32;  // 68
    for (int kt = 0; kt < NT; ++kt) {
        if (kt + 1 < NT) { issueKV(kt + 1); cpa_wait1(); }
        else cpa_wait0();
        __syncthreads();   // the ONLY sync per iteration (gates 4 warps only)
        uint32_t kvb = sb + (kt % 3) * 32768;

        // ---- S = Qh.Kh + Qh.Kl + Ql.Kh (already scaled via Q) ----
        float cs[4][4];
#pragma unroll
        for (int i = 0; i < 4; i++)
#pragma unroll
            for (int j = 0; j < 4; j++) cs[i][j] = 0.f;
#pragma unroll
        for (int ch = 0; ch < 4; ch++)
#pragma unroll
            for (int ks = 0; ks < 2; ks++) {
                uint32_t kx = ks * 32;
#pragma unroll
                for (int ni2 = 0; ni2 < 2; ni2++) {
                    uint32_t bh[4], bl[4];
                    uint32_t ba = kvb + ch * 2048 + (k4[ni2] ^ kx);
                    ldmx4(bh, ba);
                    ldmx4(bl, ba + 8192);
                    mma16816(cs[2 * ni2], qfh[ch][ks], bh);
                    mma16816(cs[2 * ni2], qfh[ch][ks], bl);
                    mma16816(cs[2 * ni2], qfl[ch][ks], bh);
                    mma16816(cs[2 * ni2 + 1], qfh[ch][ks], bh + 2);
                    mma16816(cs[2 * ni2 + 1], qfh[ch][ks], bl + 2);
                    mma16816(cs[2 * ni2 + 1], qfl[ch][ks], bh + 2);
                }
            }

        // ---- in-register softmax (32 keys) ----
        float tm0 = -1e30f, tm1 = -1e30f;
#pragma unroll
        for (int ni = 0; ni < 4; ni++) {
            tm0 = fmaxf(tm0, fmaxf(cs[ni][0], cs[ni][1]));
            tm1 = fmaxf(tm1, fmaxf(cs[ni][2], cs[ni][3]));
        }
        tm0 = fmaxf(tm0, __shfl_xor_sync(0xffffffffu, tm0, 1));
        tm0 = fmaxf(tm0, __shfl_xor_sync(0xffffffffu, tm0, 2));
        tm1 = fmaxf(tm1, __shfl_xor_sync(0xffffffffu, tm1, 1));
        tm1 = fmaxf(tm1, __shfl_xor_sync(0xffffffffu, tm1, 2));
        float nm0 = fmaxf(m0, tm0), nm1 = fmaxf(m1, tm1);
        float al0 = __expf(m0 - nm0), al1 = __expf(m1 - nm1);
        m0 = nm0; m1 = nm1;

        float rs0 = 0.f, rs1 = 0.f;
#pragma unroll
        for (int ni = 0; ni < 4; ni++) {
            cs[ni][0] = __expf(cs[ni][0] - m0); rs0 += cs[ni][0];
            cs[ni][1] = __expf(cs[ni][1] - m0); rs0 += cs[ni][1];
            cs[ni][2] = __expf(cs[ni][2] - m1); rs1 += cs[ni][2];
            cs[ni][3] = __expf(cs[ni][3] - m1); rs1 += cs[ni][3];
        }
        rs0 += __shfl_xor_sync(0xffffffffu, rs0, 1);
        rs0 += __shfl_xor_sync(0xffffffffu, rs0, 2);
        rs1 += __shfl_xor_sync(0xffffffffu, rs1, 1);
        rs1 += __shfl_xor_sync(0xffffffffu, rs1, 2);
        l0 = l0 * al0 + rs0;
        l1 = l1 * al1 + rs1;

        // ---- P hi/lo A-fragments (2 chunks of 16 keys) ----
        uint32_t phf[2][4], plf[2][4];
#pragma unroll
        for (int ck = 0; ck < 2; ck++) {
            hl2(cs[2 * ck][0], cs[2 * ck][1], phf[ck][0], plf[ck][0]);
            hl2(cs[2 * ck][2], cs[2 * ck][3], phf[ck][1], plf[ck][1]);
            hl2(cs[2 * ck + 1][0], cs[2 * ck + 1][1], phf[ck][2], plf[ck][2]);
            hl2(cs[2 * ck + 1][2], cs[2 * ck + 1][3], phf[ck][3], plf[ck][3]);
        }

        // ---- rescale O ----
#pragma unroll
        for (int ni = 0; ni < 16; ni++) {
            co[ni][0] *= al0; co[ni][1] *= al0;
            co[ni][2] *= al1; co[ni][3] *= al1;
        }

        // ---- O += Ph.Vh + Ph.Vl + Pl.Vh (trans-loaded V) ----
#pragma unroll
        for (int ck = 0; ck < 2; ck++) {
            uint32_t rofs = kvb + 16384 + (uint32_t)(ck * 1024) + vbase;
#pragma unroll
            for (int ni2 = 0; ni2 < 8; ni2++) {
                uint32_t bh[4], bl[4];
                uint32_t ba = rofs + (uint32_t)((ni2 >> 1) * 2048) + ((ni2 & 1) ? go : ge);
                ldmx4t(bh, ba);
                ldmx4t(bl, ba + 8192);
                mma16816(co[2 * ni2], phf[ck], bh);
                mma16816(co[2 * ni2], phf[ck], bl);
                mma16816(co[2 * ni2], plf[ck], bh);
                mma16816(co[2 * ni2 + 1], phf[ck], bh + 2);
                mma16816(co[2 * ni2 + 1], phf[ck], bl + 2);
                mma16816(co[2 * ni2 + 1], plf[ck], bh + 2);
            }
        }
    }

    // ---- epilogue: write O split [hi|hi|lo] ----
    float il0 = 1.0f / l0, il1 = 1.0f / l1;
    int r0 = wm * 16 + g4, r1 = r0 + 8;
    __nv_bfloat16* O0 = O3 + ((size_t)(b * Sq + qb + r0)) * (3 * Eq) + h * Dq;
    __nv_bfloat16* O1 = O3 + ((size_t)(b * Sq + qb + r1)) * (3 * Eq) + h * Dq;
#pragma unroll
    for (int ni = 0; ni < 16; ni++) {
        int col = ni * 8 + tg * 2;
        uint32_t h0, lo0, h1, lo1;
        hl2(co[ni][0] * il0, co[ni][1] * il0, h0, lo0);
        hl2(co[ni][2] * il1, co[ni][3] * il1, h1, lo1);
        *(uint32_t*)(O0 + col) = h0;
        *(uint32_t*)(O0 + Eq + col) = h0;
        *(uint32_t*)(O0 + 2 * Eq + col) = lo0;
        *(uint32_t*)(O1 + col) = h1;
        *(uint32_t*)(O1 + Eq + col) = h1;
        *(uint32_t*)(O1 + 2 * Eq + col) = lo1;
    }
}

// ---------------- host launcher ----------------
extern "C" void kernel_launch(void* const* d_in, const int* in_sizes, int n_in,
                              void* d_out, int out_size) {
    const float* x  = (const float*)d_in[0];
    const float* rt = (const float*)d_in[1];
    const float* qw = (const float*)d_in[2];
    const float* kw = (const float*)d_in[3];
    const float* vw = (const float*)d_in[4];
    const float* ow = (const float*)d_in[5];
    const float* ob = (const float*)d_in[6];
    float* out = (float*)d_out;

    __nv_bfloat16 *xbf, *wbf, *rt3, *kw3, *vw3, *ow3, *ao3, *qh, *ql, *kh, *kl, *vh, *vl;
    float *rows, *part, *scale;
    cudaGetSymbolAddress((void**)&xbf, g_xbf);
    cudaGetSymbolAddress((void**)&wbf, g_wbf);
    cudaGetSymbolAddress((void**)&rt3, g_rt3);
    cudaGetSymbolAddress((void**)&kw3, g_kw3);
    cudaGetSymbolAddress((void**)&vw3, g_vw3);
    cudaGetSymbolAddress((void**)&ow3, g_ow3);
    cudaGetSymbolAddress((void**)&ao3, g_ao3);
    cudaGetSymbolAddress((void**)&qh, g_qh);
    cudaGetSymbolAddress((void**)&ql, g_ql);
    cudaGetSymbolAddress((void**)&kh, g_kh);
    cudaGetSymbolAddress((void**)&kl, g_kl);
    cudaGetSymbolAddress((void**)&vh, g_vh);
    cudaGetSymbolAddress((void**)&vl, g_vl);
    cudaGetSymbolAddress((void**)&rows, g_rows);
    cudaGetSymbolAddress((void**)&part, g_part);
    cudaGetSymbolAddress((void**)&scale, g_scale);

    cudaFuncSetAttribute(attn_mma4, cudaFuncAttributeMaxDynamicSharedMemorySize, SMEM_ATTN5);
    cudaFuncSetAttribute(hmma_gemm5, cudaFuncAttributeMaxDynamicSharedMemorySize, SMEM_GEMM5);

    const float SCALE = 0.08838834764831845f;  // 1/sqrt(128), folded into Q epilogue

    // 1) weight scales
    reduce_abs_kernel<<<dim3(1024, 3), 256>>>(qw, kw, vw, part);
    finalize_scale_kernel<<<3, 256>>>(part, scale);
    // 2) merged weight prep (ternary q/k/v + splits k/v/o) + act quant + rt split
    prep_weights<<<dim3(2048, 4), 256>>>(qw, kw, vw, ow, wbf, kw3, vw3, ow3, scale);
    quant_act_bf16<<<(Bq * Sq) / 8, 256>>>(x, xbf, rows);
    split3a<<<(Bq * Rq * Eq) / 256, 256>>>(rt, rt3);
    // 3) QKV + reasoning projections in ONE launch (z = 0..4); all write split bf16
    size_t EE = (size_t)Eq * Eq;
    GArgs gQ = { xbf, wbf + 0 * EE, nullptr, rows, scale + 0, nullptr,
                 Eq, Eq, Sq, Sq, 0, 32, qh, ql, SCALE };
    GArgs gK = { xbf, wbf + 1 * EE, nullptr, rows, scale + 1, nullptr,
                 Eq, Eq, Sq, Lq, 0, 32, kh, kl, 1.0f };
    GArgs gV = { xbf, wbf + 2 * EE, nullptr, rows, scale + 2, nullptr,
                 Eq, Eq, Sq, Lq, 0, 32, vh, vl, 1.0f };
    GArgs gRK = { rt3, kw3, nullptr, nullptr, nullptr, nullptr,
                  3 * Eq, Eq, Rq, Lq, Sq, 2, kh, kl, 1.0f };
    GArgs gRV = { rt3, vw3, nullptr, nullptr, nullptr, nullptr,
                  3 * Eq, Eq, Rq, Lq, Sq, 2, vh, vl, 1.0f };
    hmma_gemm5<<<dim3(16, 32, 5), 256, SMEM_GEMM5>>>(gQ, gK, gV, gRK, gRV);
    // 4) attention (2 CTAs/SM, 64q/CTA, 32-key 3-stage pipeline) -> writes [hi|hi|lo]
    attn_mma4<<<dim3(Sq / 64, Hq, Bq), 128, SMEM_ATTN5>>>(qh, ql, kh, kl, vh, vl, ao3);
    // 5) output projection + bias
    GArgs gO = { ao3, ow3, out, nullptr, nullptr, ob,
                 3 * Eq, Eq, Bq * Sq, Bq * Sq, 0, 32, nullptr, nullptr, 1.0f };
    hmma_gemm5<<<dim3(16, 32, 1), 256, SMEM_GEMM5>>>(gO, gO, gO, gO, gO);
}

// round 14
// speedup vs baseline: 1.2027x; 1.0806x over previous
#include <cuda_runtime.h>
#include <cuda_bf16.h>
#include <cuda_fp16.h>
#include <cstdint>

#define Bq 2
#define Sq 2048
#define Rq 128
#define Eq 2048
#define Hq 16
#define Dq 128
#define Lq (Sq + Rq)   // 2176

// ---------------- scratch (device globals, no allocations) ----------------
__device__ __nv_bfloat16 g_xbf[(size_t)Bq * Sq * Eq];      // quantized acts as bf16 ints
__device__ __nv_bfloat16 g_wbf[3][(size_t)Eq * Eq];        // ternary weights as bf16
__device__ __nv_bfloat16 g_rt3[(size_t)Bq * Rq * 3 * Eq];  // reasoning tokens split [hi|hi|lo]
__device__ __nv_bfloat16 g_kw3[(size_t)Eq * 3 * Eq];       // k_w split [hi|lo|hi]
__device__ __nv_bfloat16 g_vw3[(size_t)Eq * 3 * Eq];       // v_w split
__device__ __nv_bfloat16 g_ow3[(size_t)Eq * 3 * Eq];       // out_w split
__device__ __nv_bfloat16 g_ao3[(size_t)Bq * Sq * 3 * Eq];  // attn out split [hi|hi|lo]
__device__ __nv_bfloat16 g_qh[(size_t)Bq * Sq * Eq];       // Q hi (pre-scaled by 1/sqrt(D))
__device__ __nv_bfloat16 g_ql[(size_t)Bq * Sq * Eq];       // Q lo
__device__ __nv_bfloat16 g_kh[(size_t)Bq * Lq * Eq];       // K hi
__device__ __nv_bfloat16 g_kl[(size_t)Bq * Lq * Eq];       // K lo
__device__ __half        g_v16[(size_t)Bq * Lq * Eq];      // V fp16 [B,L,E]
__device__ float g_rows[(size_t)Bq * Sq];                  // per-row act scale s
__device__ float g_part[3 * 1024];
__device__ float g_scale[3];

// ---------------- PTX helpers ----------------
typedef unsigned long long ull;
__device__ __forceinline__ uint32_t smem_u32(const void* p) {
    uint32_t a;
    asm("{ .reg .u64 t; cvta.to.shared.u64 t, %1; cvt.u32.u64 %0, t; }" : "=r"(a) : "l"(p));
    return a;
}
__device__ __forceinline__ void ldmx4(uint32_t* r, uint32_t addr) {
    asm volatile("ldmatrix.sync.aligned.m8n8.x4.shared.b16 {%0,%1,%2,%3}, [%4];"
                 : "=r"(r[0]), "=r"(r[1]), "=r"(r[2]), "=r"(r[3]) : "r"(addr));
}
__device__ __forceinline__ void ldmx4t(uint32_t* r, uint32_t addr) {
    asm volatile("ldmatrix.sync.aligned.m8n8.x4.trans.shared.b16 {%0,%1,%2,%3}, [%4];"
                 : "=r"(r[0]), "=r"(r[1]), "=r"(r[2]), "=r"(r[3]) : "r"(addr));
}
__device__ __forceinline__ void mma16816(float* c, const uint32_t* a, const uint32_t* b) {
    asm volatile("mma.sync.aligned.m16n8k16.row.col.f32.bf16.bf16.f32 "
                 "{%0,%1,%2,%3}, {%4,%5,%6,%7}, {%8,%9}, {%0,%1,%2,%3};"
                 : "+f"(c[0]), "+f"(c[1]), "+f"(c[2]), "+f"(c[3])
                 : "r"(a[0]), "r"(a[1]), "r"(a[2]), "r"(a[3]), "r"(b[0]), "r"(b[1]));
}
__device__ __forceinline__ void mma16816h(float* c, const uint32_t* a, const uint32_t* b) {
    asm volatile("mma.sync.aligned.m16n8k16.row.col.f32.f16.f16.f32 "
                 "{%0,%1,%2,%3}, {%4,%5,%6,%7}, {%8,%9}, {%0,%1,%2,%3};"
                 : "+f"(c[0]), "+f"(c[1]), "+f"(c[2]), "+f"(c[3])
                 : "r"(a[0]), "r"(a[1]), "r"(a[2]), "r"(a[3]), "r"(b[0]), "r"(b[1]));
}
__device__ __forceinline__ void cpa16(uint32_t dst, const void* src) {
    asm volatile("cp.async.cg.shared.global [%0], [%1], 16;" :: "r"(dst), "l"(src) : "memory");
}
__device__ __forceinline__ void cpa_commit() {
    asm volatile("cp.async.commit_group;" ::: "memory");
}
__device__ __forceinline__ void cpa_wait0() {
    asm volatile("cp.async.wait_group 0;" ::: "memory");
}
__device__ __forceinline__ void cpa_wait1() {
    asm volatile("cp.async.wait_group 1;" ::: "memory");
}
// smem rows of 32 x 16-bit (64B); 16B group g stored at g ^ ((row>>1)&3)
__device__ __forceinline__ uint32_t swoff(int r, int g) {
    return (uint32_t)(r * 64 + ((g ^ ((r >> 1) & 3)) << 4));
}
// per-lane address offset for B-side ldmatrix.x4 (2 consecutive n-frags of 8 rows)
__device__ __forceinline__ uint32_t boff4(int base_row, int lane) {
    int r = base_row + ((lane >> 4) << 3) + (lane & 7);
    int g = (lane >> 3) & 1;
    return swoff(r, g);
}
// pack two fp32 into bf16x2 hi + residual lo
__device__ __forceinline__ void hl2(float x, float y, uint32_t& h, uint32_t& l) {
    __nv_bfloat162 hh, ll;
    hh.x = __float2bfloat16(x);
    hh.y = __float2bfloat16(y);
    ll.x = __float2bfloat16(x - __bfloat162float(hh.x));
    ll.y = __float2bfloat16(y - __bfloat162float(hh.y));
    h = *(uint32_t*)&hh;
    l = *(uint32_t*)&ll;
}
__device__ __forceinline__ uint32_t h2pack(float x, float y) {
    __half2 p = __floats2half2_rn(x, y);
    return *(uint32_t*)&p;
}

// ---------------- weight mean(|w|) : stage 1 ----------------
__global__ void reduce_abs_kernel(const float* __restrict__ w0, const float* __restrict__ w1,
                                  const float* __restrict__ w2, float* __restrict__ part) {
    const float* w = (blockIdx.y == 0) ? w0 : ((blockIdx.y == 1) ? w1 : w2);
    int t = threadIdx.x;
    size_t base = (size_t)blockIdx.x * 4096;
    float s = 0.f;
#pragma unroll
    for (int i = 0; i < 16; i++) s += fabsf(w[base + t + i * 256]);
    __shared__ float red[256];
    red[t] = s;
    __syncthreads();
    for (int o = 128; o > 0; o >>= 1) {
        if (t < o) red[t] += red[t + o];
        __syncthreads();
    }
    if (t == 0) part[blockIdx.y * 1024 + blockIdx.x] = red[0];
}

__global__ void finalize_scale_kernel(const float* __restrict__ part, float* __restrict__ scale) {
    int w = blockIdx.x;
    int t = threadIdx.x;
    float s = part[w * 1024 + t] + part[w * 1024 + t + 256] +
              part[w * 1024 + t + 512] + part[w * 1024 + t + 768];
    __shared__ float red[256];
    red[t] = s;
    __syncthreads();
    for (int o = 128; o > 0; o >>= 1) {
        if (t < o) red[t] += red[t + o];
        __syncthreads();
    }
    if (t == 0) {
        float mean = red[0] * (1.0f / ((float)Eq * (float)Eq));
        scale[w] = fmaxf(mean, 1e-5f);
    }
}

// ---------------- merged weight prep: ternary (q/k/v) + split3 mode-1 (k/v/o) ----------------
__global__ void prep_weights(const float* __restrict__ qw, const float* __restrict__ kw,
                             const float* __restrict__ vw, const float* __restrict__ ow,
                             __nv_bfloat16* __restrict__ wq,
                             __nv_bfloat16* __restrict__ kw3, __nv_bfloat16* __restrict__ vw3,
                             __nv_bfloat16* __restrict__ ow3,
                             const float* __restrict__ scale) {
    int wi = blockIdx.y;
    const float* w = (wi == 0) ? qw : ((wi == 1) ? kw : ((wi == 2) ? vw : ow));
    float inv = (wi < 3) ? __frcp_rn(scale[wi]) : 0.f;
    size_t e0 = ((size_t)blockIdx.x * 256 + threadIdx.x) * 8;
    size_t row = e0 >> 11, col = e0 & 2047;
    __nv_bfloat16* wo = (wi < 3) ? (wq + (size_t)wi * Eq * Eq + e0) : nullptr;
    __nv_bfloat16* y = (wi == 1) ? kw3 : ((wi == 2) ? vw3 : ((wi == 3) ? ow3 : nullptr));
    __nv_bfloat16* yr = y ? (y + row * (size_t)(3 * Eq)) : nullptr;
#pragma unroll
    for (int i = 0; i < 8; i += 4) {
        float4 v = *(const float4*)&w[e0 + i];
        float f[4] = {v.x, v.y, v.z, v.w};
#pragma unroll
        for (int j = 0; j < 4; j++) {
            if (wo)
                wo[i + j] = __float2bfloat16(fminf(fmaxf(rintf(f[j] * inv), -1.f), 1.f));
            if (yr) {
                __nv_bfloat16 hi = __float2bfloat16(f[j]);
                __nv_bfloat16 lo = __float2bfloat16(f[j] - __bfloat162float(hi));
                yr[col + i + j] = hi;
                yr[Eq + col + i + j] = lo;
                yr[2 * Eq + col + i + j] = hi;
            }
        }
    }
}

// ---------------- per-token absmax quantization (warp per row, no syncs) ----------------
__global__ void quant_act_bf16(const float* __restrict__ x, __nv_bfloat16* __restrict__ xq,
                               float* __restrict__ rows) {
    int w = (blockIdx.x * blockDim.x + threadIdx.x) >> 5;  // one warp per row
    int lane = threadIdx.x & 31;
    const float* xr = x + (size_t)w * Eq;
    float4 v[16];
    float mx = 0.f;
#pragma unroll
    for (int i = 0; i < 16; i++) {
        v[i] = *(const float4*)&xr[i * 128 + lane * 4];
        mx = fmaxf(mx, fmaxf(fmaxf(fabsf(v[i].x), fabsf(v[i].y)),
                             fmaxf(fabsf(v[i].z), fabsf(v[i].w))));
    }
#pragma unroll
    for (int o = 16; o > 0; o >>= 1) mx = fmaxf(mx, __shfl_xor_sync(0xffffffffu, mx, o));
    float s = __fdiv_rn(127.0f, fmaxf(mx, 1e-5f));
    if (lane == 0) rows[w] = s;
    __nv_bfloat16* xo = xq + (size_t)w * Eq;
#pragma unroll
    for (int i = 0; i < 16; i++) {
        __nv_bfloat162 p0, p1;
        p0.x = __float2bfloat16(fminf(fmaxf(rintf(v[i].x * s), -128.f), 127.f));
        p0.y = __float2bfloat16(fminf(fmaxf(rintf(v[i].y * s), -128.f), 127.f));
        p1.x = __float2bfloat16(fminf(fmaxf(rintf(v[i].z * s), -128.f), 127.f));
        p1.y = __float2bfloat16(fminf(fmaxf(rintf(v[i].w * s), -128.f), 127.f));
        *(__nv_bfloat162*)&xo[i * 128 + lane * 4] = p0;
        *(__nv_bfloat162*)&xo[i * 128 + lane * 4 + 2] = p1;
    }
}

// ---------------- fp32 -> split-bf16 K-tripling, A side [hi|hi|lo] ----------------
__global__ void split3a(const float* __restrict__ X, __nv_bfloat16* __restrict__ Y) {
    size_t i = (size_t)blockIdx.x * 256 + threadIdx.x;
    size_t row = i >> 11, col = i & 2047;
    float x = X[i];
    __nv_bfloat16 hi = __float2bfloat16(x);
    __nv_bfloat16 lo = __float2bfloat16(x - __bfloat162float(hi));
    __nv_bfloat16* yr = Y + row * (size_t)(3 * Eq);
    yr[col] = hi;
    yr[Eq + col] = hi;
    yr[2 * Eq + col] = lo;
}

// ---------------- HMMA bf16 GEMM: cp.async 3-stage, BK=64, 2 CTAs/SM, z-batched ----------------
// Output modes: Hout&&Lout -> split bf16; Hout only -> fp16; else fp32 (+bias)
struct GArgs {
    const __nv_bfloat16* A;
    const __nv_bfloat16* B;
    float* C;
    const float* rowscale;
    const float* wsp;
    const float* bias;
    int K, Nout, rbi, rbo, roff, ylim;
    __nv_bfloat16* Hout;
    __nv_bfloat16* Lout;
    float cmul;   // extra constant multiplier folded into the epilogue
};

// dynamic smem: 3 stages x (A 16K | B 16K) = 96 KB
#define SMEM_GEMM5 98304

__global__ __launch_bounds__(256, 2) void hmma_gemm5(GArgs ga0, GArgs ga1, GArgs ga2,
                                                     GArgs ga3, GArgs ga4) {
    int z = blockIdx.z;
    GArgs ga = (z == 0) ? ga0 : ((z == 1) ? ga1 : ((z == 2) ? ga2 : ((z == 3) ? ga3 : ga4)));
    if ((int)blockIdx.y >= ga.ylim) return;
    extern __shared__ __align__(128) uint8_t dsm[];
    uint32_t sb = smem_u32(dsm);
    int t = threadIdx.x;
    int lane = t & 31, wid = t >> 5;
    int m0 = blockIdx.y * 128, n0 = blockIdx.x * 128;
    int warp_m = wid & 1, warp_n = wid >> 1;
    const int K = ga.K;

    const uint8_t* asrc[4];
    const uint8_t* bsrc[4];
    uint32_t gdst[4];
#pragma unroll
    for (int i = 0; i < 4; i++) {
        int idx = t + i * 256;
        int r = idx >> 3, g = idx & 7;
        gdst[i] = (g >> 2) * 8192 + swoff(r, g & 3);
        asrc[i] = (const uint8_t*)(ga.A + (size_t)(m0 + r) * K) + g * 16;
        bsrc[i] = (const uint8_t*)(ga.B + (size_t)(n0 + r) * K) + g * 16;
    }

    uint32_t aaddr[4], baddr4[2];
#pragma unroll
    for (int mi = 0; mi < 4; mi++)
        aaddr[mi] = swoff(warp_m * 64 + mi * 16 + (lane & 15), lane >> 4);
#pragma unroll
    for (int ni2 = 0; ni2 < 2; ni2++)
        baddr4[ni2] = boff4(warp_n * 32 + ni2 * 16, lane);

    const int NK = K >> 6;
    {
#pragma unroll
        for (int i = 0; i < 4; i++) {
            cpa16(sb + gdst[i], asrc[i]);
            cpa16(sb + 16384 + gdst[i], bsrc[i]);
        }
        cpa_commit();
    }

    float c[4][4][4];
#pragma unroll
    for (int mi = 0; mi < 4; mi++)
#pragma unroll
        for (int ni = 0; ni < 4; ni++)
#pragma unroll
            for (int k = 0; k < 4; k++) c[mi][ni][k] = 0.f;

    int s = 0;
    for (int kt = 0; kt < NK; ++kt) {
        if (kt + 1 < NK) {
            int sn = (s + 1 == 3) ? 0 : s + 1;
            uint32_t base = sb + sn * 32768;
            size_t koff = (size_t)(kt + 1) * 128;
#pragma unroll
            for (int i = 0; i < 4; i++) {
                cpa16(base + gdst[i], asrc[i] + koff);
                cpa16(base + 16384 + gdst[i], bsrc[i] + koff);
            }
            cpa_commit();
            cpa_wait1();
        } else {
            cpa_wait0();
        }
        __syncthreads();

        uint32_t Ab = sb + s * 32768;
        uint32_t Bb = Ab + 16384;
#pragma unroll
        for (int ch = 0; ch < 2; ch++)
#pragma unroll
            for (int ks = 0; ks < 2; ks++) {
                uint32_t kx = ks * 32;
                uint32_t a[4][4], b[2][4];
#pragma unroll
                for (int mi = 0; mi < 4; mi++)
                    ldmx4(a[mi], Ab + ch * 8192 + (aaddr[mi] ^ kx));
#pragma unroll
                for (int ni2 = 0; ni2 < 2; ni2++)
                    ldmx4(b[ni2], Bb + ch * 8192 + (baddr4[ni2] ^ kx));
#pragma unroll
                for (int mi = 0; mi < 4; mi++)
#pragma unroll
                    for (int ni = 0; ni < 4; ni++)
                        mma16816(c[mi][ni], a[mi], &b[ni >> 1][(ni & 1) * 2]);
            }
        s = (s + 1 == 3) ? 0 : s + 1;
    }

    float ws = ga.cmul * (ga.wsp ? *ga.wsp : 1.0f);
    int g = lane >> 2, tg = lane & 3;
#pragma unroll
    for (int mi = 0; mi < 4; mi++) {
        int mA = m0 + warp_m * 64 + mi * 16 + g;
        int mB = mA + 8;
        float fA = ga.rowscale ? (ws / ga.rowscale[mA]) : ws;
        float fB = ga.rowscale ? (ws / ga.rowscale[mB]) : ws;
        int oA = (mA / ga.rbi) * ga.rbo + ga.roff + (mA % ga.rbi);
        int oB = (mB / ga.rbi) * ga.rbo + ga.roff + (mB % ga.rbi);
        if (ga.Hout && ga.Lout) {
            __nv_bfloat16* hA = ga.Hout + (size_t)oA * ga.Nout;
            __nv_bfloat16* hB = ga.Hout + (size_t)oB * ga.Nout;
            __nv_bfloat16* lA = ga.Lout + (size_t)oA * ga.Nout;
            __nv_bfloat16* lB = ga.Lout + (size_t)oB * ga.Nout;
#pragma unroll
            for (int ni = 0; ni < 4; ni++) {
                int col = n0 + warp_n * 32 + ni * 8 + tg * 2;
                uint32_t h0, l0v, h1, l1v;
                hl2(c[mi][ni][0] * fA, c[mi][ni][1] * fA, h0, l0v);
                hl2(c[mi][ni][2] * fB, c[mi][ni][3] * fB, h1, l1v);
                *(uint32_t*)&hA[col] = h0;
                *(uint32_t*)&lA[col] = l0v;
                *(uint32_t*)&hB[col] = h1;
                *(uint32_t*)&lB[col] = l1v;
            }
        } else if (ga.Hout) {
            __half* hA = (__half*)ga.Hout + (size_t)oA * ga.Nout;
            __half* hB = (__half*)ga.Hout + (size_t)oB * ga.Nout;
#pragma unroll
            for (int ni = 0; ni < 4; ni++) {
                int col = n0 + warp_n * 32 + ni * 8 + tg * 2;
                *(uint32_t*)&hA[col] = h2pack(c[mi][ni][0] * fA, c[mi][ni][1] * fA);
                *(uint32_t*)&hB[col] = h2pack(c[mi][ni][2] * fB, c[mi][ni][3] * fB);
            }
        } else {
            float* crA = ga.C + (size_t)oA * ga.Nout;
            float* crB = ga.C + (size_t)oB * ga.Nout;
#pragma unroll
            for (int ni = 0; ni < 4; ni++) {
                int col = n0 + warp_n * 32 + ni * 8 + tg * 2;
                float b0 = 0.f, b1 = 0.f;
                if (ga.bias) { b0 = ga.bias[col]; b1 = ga.bias[col + 1]; }
                float2 vA, vB;
                vA.x = c[mi][ni][0] * fA + b0;
                vA.y = c[mi][ni][1] * fA + b1;
                vB.x = c[mi][ni][2] * fB + b0;
                vB.y = c[mi][ni][3] * fB + b1;
                *(float2*)&crA[col] = vA;
                *(float2*)&crB[col] = vB;
            }
        }
    }
}

// ---------------- FA2 HMMA flash attention: 2 CTAs/SM, 64q/CTA, 32-key 3-stage KV ----------------
// Q pre-scaled by 1/sqrt(D). QK^T: split-bf16 3-pass (exact-ish). PV: single-pass fp16.
// smem/CTA: 3 stages x 24K (KH 8K | KL 8K | V16 8K) = 72 KB. Q staged at sb+0 before loop.
#define ATT_STAGE 24576
#define SMEM_ATTN6 (3 * ATT_STAGE)   // 73728 -> 2 CTAs/SM

__global__ __launch_bounds__(128, 2) void attn_mma5(
    const __nv_bfloat16* __restrict__ Qh, const __nv_bfloat16* __restrict__ Ql,
    const __nv_bfloat16* __restrict__ Kh, const __nv_bfloat16* __restrict__ Kl,
    const __half* __restrict__ V16, __nv_bfloat16* __restrict__ O3) {
    extern __shared__ char smg[];
    uint32_t sb = smem_u32(smg);
    int t = threadIdx.x;
    int lane = t & 31, wid = t >> 5;   // 4 warps
    int qb = blockIdx.x * 64;
    int h = blockIdx.y;
    int b = blockIdx.z;

    const int wm = wid;
    const uint32_t a_off = swoff(wm * 16 + (lane & 15), lane >> 4);
    uint32_t k4[2];
#pragma unroll
    for (int ni2 = 0; ni2 < 2; ni2++) k4[ni2] = boff4(ni2 * 16, lane);
    // trans-V per-lane address components (verified in rounds 12-13)
    const int vrow = (lane & 7) + ((lane >> 3) & 1) * 8;
    const uint32_t vbase = (uint32_t)(vrow * 64);
    const uint32_t vrx = (uint32_t)((vrow >> 1) & 3);
    const uint32_t vg = (uint32_t)((lane >> 4) & 1);
    const uint32_t ge = ((vg ^ vrx) << 4);          // ni2 even: group = vg
    const uint32_t go = (((2 + vg) ^ vrx) << 4);    // ni2 odd: group = 2+vg
    const int g4 = lane >> 2, tg = lane & 3;

    // ---- stage Q (64 rows x 128 d, hi+lo = 32KB) at sb+0, consume to regs, then start ring ----
    {
        const __nv_bfloat16* Qhg = Qh + ((size_t)(b * Sq + qb)) * Eq + h * Dq;
        const __nv_bfloat16* Qlg = Ql + ((size_t)(b * Sq + qb)) * Eq + h * Dq;
#pragma unroll
        for (int i = 0; i < 8; i++) {
            int idx = t + i * 128;
            int r = idx >> 4, g = idx & 15;
            uint32_t dst = (g >> 2) * 4096 + swoff(r, g & 3);
            cpa16(sb + dst, Qhg + (size_t)r * Eq + g * 8);
            cpa16(sb + 16384 + dst, Qlg + (size_t)r * Eq + g * 8);
        }
        cpa_commit();
    }
    cpa_wait0();
    __syncthreads();

    uint32_t qfh[4][2][4], qfl[4][2][4];
#pragma unroll
    for (int ch = 0; ch < 4; ch++)
#pragma unroll
        for (int ks = 0; ks < 2; ks++) {
            ldmx4(qfh[ch][ks], sb + ch * 4096 + (a_off ^ (ks * 32)));
            ldmx4(qfl[ch][ks], sb + 16384 + ch * 4096 + (a_off ^ (ks * 32)));
        }
    __syncthreads();   // all warps done reading Q staging before stage 0 overwrite

    const __nv_bfloat16* Khb = Kh + ((size_t)(b * Lq)) * Eq + h * Dq;
    const __nv_bfloat16* Klb = Kl + ((size_t)(b * Lq)) * Eq + h * Dq;
    const __half* Vb = V16 + ((size_t)(b * Lq)) * Eq + h * Dq;

    auto issueKV = [&](int kt) {
        uint32_t base = sb + (kt % 3) * ATT_STAGE;
        const __nv_bfloat16* KhT = Khb + (size_t)(kt * 32) * Eq;
        const __nv_bfloat16* KlT = Klb + (size_t)(kt * 32) * Eq;
        const __half* VT = Vb + (size_t)(kt * 32) * Eq;
#pragma unroll
        for (int i = 0; i < 4; i++) {
            int idx = t + i * 128;
            int r = idx >> 4, g = idx & 15;
            uint32_t dst = (g >> 2) * 2048 + swoff(r, g & 3);
            size_t src = (size_t)r * Eq + g * 8;
            cpa16(base + dst, KhT + src);
            cpa16(base + 8192 + dst, KlT + src);
            cpa16(base + 16384 + dst, VT + src);
        }
        cpa_commit();
    };
    issueKV(0);

    float m0 = -1e30f, m1 = -1e30f, l0 = 0.f, l1 = 0.f;
    float co[16][4];
#pragma unroll
    for (int i = 0; i < 16; i++)
#pragma unroll
        for (int j = 0; j < 4; j++) co[i][j] = 0.f;

    const int NT = Lq / 32;  // 68
    for (int kt = 0; kt < NT; ++kt) {
        if (kt + 1 < NT) { issueKV(kt + 1); cpa_wait1(); }
        else cpa_wait0();
        __syncthreads();   // the ONLY sync per iteration (gates 4 warps only)
        uint32_t kvb = sb + (kt % 3) * ATT_STAGE;

        // ---- S = Qh.Kh + Qh.Kl + Ql.Kh (already scaled via Q) ----
        float cs[4][4];
#pragma unroll
        for (int i = 0; i < 4; i++)
#pragma unroll
            for (int j = 0; j < 4; j++) cs[i][j] = 0.f;
#pragma unroll
        for (int ch = 0; ch < 4; ch++)
#pragma unroll
            for (int ks = 0; ks < 2; ks++) {
                uint32_t kx = ks * 32;
#pragma unroll
                for (int ni2 = 0; ni2 < 2; ni2++) {
                    uint32_t bh[4], bl[4];
                    uint32_t ba = kvb + ch * 2048 + (k4[ni2] ^ kx);
                    ldmx4(bh, ba);
                    ldmx4(bl, ba + 8192);
                    mma16816(cs[2 * ni2], qfh[ch][ks], bh);
                    mma16816(cs[2 * ni2], qfh[ch][ks], bl);
                    mma16816(cs[2 * ni2], qfl[ch][ks], bh);
                    mma16816(cs[2 * ni2 + 1], qfh[ch][ks], bh + 2);
                    mma16816(cs[2 * ni2 + 1], qfh[ch][ks], bl + 2);
                    mma16816(cs[2 * ni2 + 1], qfl[ch][ks], bh + 2);
                }
            }

        // ---- in-register softmax (32 keys) ----
        float tm0 = -1e30f, tm1 = -1e30f;
#pragma unroll
        for (int ni = 0; ni < 4; ni++) {
            tm0 = fmaxf(tm0, fmaxf(cs[ni][0], cs[ni][1]));
            tm1 = fmaxf(tm1, fmaxf(cs[ni][2], cs[ni][3]));
        }
        tm0 = fmaxf(tm0, __shfl_xor_sync(0xffffffffu, tm0, 1));
        tm0 = fmaxf(tm0, __shfl_xor_sync(0xffffffffu, tm0, 2));
        tm1 = fmaxf(tm1, __shfl_xor_sync(0xffffffffu, tm1, 1));
        tm1 = fmaxf(tm1, __shfl_xor_sync(0xffffffffu, tm1, 2));
        float nm0 = fmaxf(m0, tm0), nm1 = fmaxf(m1, tm1);
        float al0 = __expf(m0 - nm0), al1 = __expf(m1 - nm1);
        m0 = nm0; m1 = nm1;

        float rs0 = 0.f, rs1 = 0.f;
#pragma unroll
        for (int ni = 0; ni < 4; ni++) {
            cs[ni][0] = __expf(cs[ni][0] - m0); rs0 += cs[ni][0];
            cs[ni][1] = __expf(cs[ni][1] - m0); rs0 += cs[ni][1];
            cs[ni][2] = __expf(cs[ni][2] - m1); rs1 += cs[ni][2];
            cs[ni][3] = __expf(cs[ni][3] - m1); rs1 += cs[ni][3];
        }
        rs0 += __shfl_xor_sync(0xffffffffu, rs0, 1);
        rs0 += __shfl_xor_sync(0xffffffffu, rs0, 2);
        rs1 += __shfl_xor_sync(0xffffffffu, rs1, 1);
        rs1 += __shfl_xor_sync(0xffffffffu, rs1, 2);
        l0 = l0 * al0 + rs0;
        l1 = l1 * al1 + rs1;

        // ---- P fp16 A-fragments (2 chunks of 16 keys) ----
        uint32_t pf[2][4];
#pragma unroll
        for (int ck = 0; ck < 2; ck++) {
            pf[ck][0] = h2pack(cs[2 * ck][0], cs[2 * ck][1]);
            pf[ck][1] = h2pack(cs[2 * ck][2], cs[2 * ck][3]);
            pf[ck][2] = h2pack(cs[2 * ck + 1][0], cs[2 * ck + 1][1]);
            pf[ck][3] = h2pack(cs[2 * ck + 1][2], cs[2 * ck + 1][3]);
        }

        // ---- rescale O ----
#pragma unroll
        for (int ni = 0; ni < 16; ni++) {
            co[ni][0] *= al0; co[ni][1] *= al0;
            co[ni][2] *= al1; co[ni][3] *= al1;
        }

        // ---- O += P.V (single-pass fp16, trans-loaded V) ----
#pragma unroll
        for (int ck = 0; ck < 2; ck++) {
            uint32_t rofs = kvb + 16384 + (uint32_t)(ck * 1024) + vbase;
#pragma unroll
            for (int ni2 = 0; ni2 < 8; ni2++) {
                uint32_t bv[4];
                ldmx4t(bv, rofs + (uint32_t)((ni2 >> 1) * 2048) + ((ni2 & 1) ? go : ge));
                mma16816h(co[2 * ni2], pf[ck], bv);
                mma16816h(co[2 * ni2 + 1], pf[ck], bv + 2);
            }
        }
    }

    // ---- epilogue: write O split [hi|hi|lo] ----
    float il0 = 1.0f / l0, il1 = 1.0f / l1;
    int r0 = wm * 16 + g4, r1 = r0 + 8;
    __nv_bfloat16* O0 = O3 + ((size_t)(b * Sq + qb + r0)) * (3 * Eq) + h * Dq;
    __nv_bfloat16* O1 = O3 + ((size_t)(b * Sq + qb + r1)) * (3 * Eq) + h * Dq;
#pragma unroll
    for (int ni = 0; ni < 16; ni++) {
        int col = ni * 8 + tg * 2;
        uint32_t h0, lo0, h1, lo1;
        hl2(co[ni][0] * il0, co[ni][1] * il0, h0, lo0);
        hl2(co[ni][2] * il1, co[ni][3] * il1, h1, lo1);
        *(uint32_t*)(O0 + col) = h0;
        *(uint32_t*)(O0 + Eq + col) = h0;
        *(uint32_t*)(O0 + 2 * Eq + col) = lo0;
        *(uint32_t*)(O1 + col) = h1;
        *(uint32_t*)(O1 + Eq + col) = h1;
        *(uint32_t*)(O1 + 2 * Eq + col) = lo1;
    }
}

// ---------------- host launcher ----------------
extern "C" void kernel_launch(void* const* d_in, const int* in_sizes, int n_in,
                              void* d_out, int out_size) {
    const float* x  = (const float*)d_in[0];
    const float* rt = (const float*)d_in[1];
    const float* qw = (const float*)d_in[2];
    const float* kw = (const float*)d_in[3];
    const float* vw = (const float*)d_in[4];
    const float* ow = (const float*)d_in[5];
    const float* ob = (const float*)d_in[6];
    float* out = (float*)d_out;

    __nv_bfloat16 *xbf, *wbf, *rt3, *kw3, *vw3, *ow3, *ao3, *qh, *ql, *kh, *kl;
    __half* v16;
    float *rows, *part, *scale;
    cudaGetSymbolAddress((void**)&xbf, g_xbf);
    cudaGetSymbolAddress((void**)&wbf, g_wbf);
    cudaGetSymbolAddress((void**)&rt3, g_rt3);
    cudaGetSymbolAddress((void**)&kw3, g_kw3);
    cudaGetSymbolAddress((void**)&vw3, g_vw3);
    cudaGetSymbolAddress((void**)&ow3, g_ow3);
    cudaGetSymbolAddress((void**)&ao3, g_ao3);
    cudaGetSymbolAddress((void**)&qh, g_qh);
    cudaGetSymbolAddress((void**)&ql, g_ql);
    cudaGetSymbolAddress((void**)&kh, g_kh);
    cudaGetSymbolAddress((void**)&kl, g_kl);
    cudaGetSymbolAddress((void**)&v16, g_v16);
    cudaGetSymbolAddress((void**)&rows, g_rows);
    cudaGetSymbolAddress((void**)&part, g_part);
    cudaGetSymbolAddress((void**)&scale, g_scale);

    cudaFuncSetAttribute(attn_mma5, cudaFuncAttributeMaxDynamicSharedMemorySize, SMEM_ATTN6);
    cudaFuncSetAttribute(hmma_gemm5, cudaFuncAttributeMaxDynamicSharedMemorySize, SMEM_GEMM5);

    const float SCALE = 0.08838834764831845f;  // 1/sqrt(128), folded into Q epilogue

    // 1) weight scales
    reduce_abs_kernel<<<dim3(1024, 3), 256>>>(qw, kw, vw, part);
    finalize_scale_kernel<<<3, 256>>>(part, scale);
    // 2) merged weight prep (ternary q/k/v + splits k/v/o) + act quant + rt split
    prep_weights<<<dim3(2048, 4), 256>>>(qw, kw, vw, ow, wbf, kw3, vw3, ow3, scale);
    quant_act_bf16<<<(Bq * Sq) / 8, 256>>>(x, xbf, rows);
    split3a<<<(Bq * Rq * Eq) / 256, 256>>>(rt, rt3);
    // 3) QKV + reasoning projections in ONE launch (z = 0..4)
    //    Q/K write split bf16; V writes single fp16.
    size_t EE = (size_t)Eq * Eq;
    GArgs gQ = { xbf, wbf + 0 * EE, nullptr, rows, scale + 0, nullptr,
                 Eq, Eq, Sq, Sq, 0, 32, qh, ql, SCALE };
    GArgs gK = { xbf, wbf + 1 * EE, nullptr, rows, scale + 1, nullptr,
                 Eq, Eq, Sq, Lq, 0, 32, kh, kl, 1.0f };
    GArgs gV = { xbf, wbf + 2 * EE, nullptr, rows, scale + 2, nullptr,
                 Eq, Eq, Sq, Lq, 0, 32, (__nv_bfloat16*)v16, nullptr, 1.0f };
    GArgs gRK = { rt3, kw3, nullptr, nullptr, nullptr, nullptr,
                  3 * Eq, Eq, Rq, Lq, Sq, 2, kh, kl, 1.0f };
    GArgs gRV = { rt3, vw3, nullptr, nullptr, nullptr, nullptr,
                  3 * Eq, Eq, Rq, Lq, Sq, 2, (__nv_bfloat16*)v16, nullptr, 1.0f };
    hmma_gemm5<<<dim3(16, 32, 5), 256, SMEM_GEMM5>>>(gQ, gK, gV, gRK, gRV);
    // 4) attention (2 CTAs/SM, 32-key 3-stage pipeline, fp16 PV) -> writes [hi|hi|lo]
    attn_mma5<<<dim3(Sq / 64, Hq, Bq), 128, SMEM_ATTN6>>>(qh, ql, kh, kl, v16, ao3);
    // 5) output projection + bias
    GArgs gO = { ao3, ow3, out, nullptr, nullptr, ob,
                 3 * Eq, Eq, Bq * Sq, Bq * Sq, 0, 32, nullptr, nullptr, 1.0f };
    hmma_gemm5<<<dim3(16, 32, 1), 256, SMEM_GEMM5>>>(gO, gO, gO, gO, gO);
}

// round 15
// speedup vs baseline: 1.4630x; 1.2164x over previous
#include <cuda_runtime.h>
#include <cuda_bf16.h>
#include <cuda_fp16.h>
#include <cstdint>

#define Bq 2
#define Sq 2048
#define Rq 128
#define Eq 2048
#define Hq 16
#define Dq 128
#define Lq (Sq + Rq)   // 2176

// ---------------- scratch (device globals, no allocations) ----------------
__device__ __nv_bfloat16 g_xbf[(size_t)Bq * Sq * Eq];      // quantized acts as bf16 ints
__device__ __nv_bfloat16 g_wbf[3][(size_t)Eq * Eq];        // ternary weights as bf16
__device__ __nv_bfloat16 g_rt3[(size_t)Bq * Rq * 3 * Eq];  // reasoning tokens split [hi|hi|lo]
__device__ __half        g_rt16[(size_t)Bq * Rq * Eq];     // reasoning tokens fp16
__device__ __nv_bfloat16 g_kw3[(size_t)Eq * 3 * Eq];       // k_w split [hi|lo|hi]
__device__ __half        g_vw16[(size_t)Eq * Eq];          // v_w fp16
__device__ __half        g_ow16[(size_t)Eq * Eq];          // out_w fp16
__device__ __half        g_o16[(size_t)Bq * Sq * Eq];      // attention output fp16
__device__ __nv_bfloat16 g_qh[(size_t)Bq * Sq * Eq];       // Q hi (pre-scaled by 1/sqrt(D))
__device__ __nv_bfloat16 g_ql[(size_t)Bq * Sq * Eq];       // Q lo
__device__ __nv_bfloat16 g_kh[(size_t)Bq * Lq * Eq];       // K hi
__device__ __nv_bfloat16 g_kl[(size_t)Bq * Lq * Eq];       // K lo
__device__ __half        g_v16[(size_t)Bq * Lq * Eq];      // V fp16 [B,L,E]
__device__ float g_rows[(size_t)Bq * Sq];                  // per-row act scale s
__device__ float g_part[3 * 1024];
__device__ float g_scale[3];

// ---------------- PTX helpers ----------------
typedef unsigned long long ull;
__device__ __forceinline__ uint32_t smem_u32(const void* p) {
    uint32_t a;
    asm("{ .reg .u64 t; cvta.to.shared.u64 t, %1; cvt.u32.u64 %0, t; }" : "=r"(a) : "l"(p));
    return a;
}
__device__ __forceinline__ void ldmx4(uint32_t* r, uint32_t addr) {
    asm volatile("ldmatrix.sync.aligned.m8n8.x4.shared.b16 {%0,%1,%2,%3}, [%4];"
                 : "=r"(r[0]), "=r"(r[1]), "=r"(r[2]), "=r"(r[3]) : "r"(addr));
}
__device__ __forceinline__ void ldmx4t(uint32_t* r, uint32_t addr) {
    asm volatile("ldmatrix.sync.aligned.m8n8.x4.trans.shared.b16 {%0,%1,%2,%3}, [%4];"
                 : "=r"(r[0]), "=r"(r[1]), "=r"(r[2]), "=r"(r[3]) : "r"(addr));
}
__device__ __forceinline__ void mma16816(float* c, const uint32_t* a, const uint32_t* b) {
    asm volatile("mma.sync.aligned.m16n8k16.row.col.f32.bf16.bf16.f32 "
                 "{%0,%1,%2,%3}, {%4,%5,%6,%7}, {%8,%9}, {%0,%1,%2,%3};"
                 : "+f"(c[0]), "+f"(c[1]), "+f"(c[2]), "+f"(c[3])
                 : "r"(a[0]), "r"(a[1]), "r"(a[2]), "r"(a[3]), "r"(b[0]), "r"(b[1]));
}
__device__ __forceinline__ void mma16816h(float* c, const uint32_t* a, const uint32_t* b) {
    asm volatile("mma.sync.aligned.m16n8k16.row.col.f32.f16.f16.f32 "
                 "{%0,%1,%2,%3}, {%4,%5,%6,%7}, {%8,%9}, {%0,%1,%2,%3};"
                 : "+f"(c[0]), "+f"(c[1]), "+f"(c[2]), "+f"(c[3])
                 : "r"(a[0]), "r"(a[1]), "r"(a[2]), "r"(a[3]), "r"(b[0]), "r"(b[1]));
}
__device__ __forceinline__ void cpa16(uint32_t dst, const void* src) {
    asm volatile("cp.async.cg.shared.global [%0], [%1], 16;" :: "r"(dst), "l"(src) : "memory");
}
__device__ __forceinline__ void cpa_commit() {
    asm volatile("cp.async.commit_group;" ::: "memory");
}
__device__ __forceinline__ void cpa_wait0() {
    asm volatile("cp.async.wait_group 0;" ::: "memory");
}
__device__ __forceinline__ void cpa_wait1() {
    asm volatile("cp.async.wait_group 1;" ::: "memory");
}
// smem rows of 32 x 16-bit (64B); 16B group g stored at g ^ ((row>>1)&3)
__device__ __forceinline__ uint32_t swoff(int r, int g) {
    return (uint32_t)(r * 64 + ((g ^ ((r >> 1) & 3)) << 4));
}
// per-lane address offset for B-side ldmatrix.x4 (2 consecutive n-frags of 8 rows)
__device__ __forceinline__ uint32_t boff4(int base_row, int lane) {
    int r = base_row + ((lane >> 4) << 3) + (lane & 7);
    int g = (lane >> 3) & 1;
    return swoff(r, g);
}
// pack two fp32 into bf16x2 hi + residual lo
__device__ __forceinline__ void hl2(float x, float y, uint32_t& h, uint32_t& l) {
    __nv_bfloat162 hh, ll;
    hh.x = __float2bfloat16(x);
    hh.y = __float2bfloat16(y);
    ll.x = __float2bfloat16(x - __bfloat162float(hh.x));
    ll.y = __float2bfloat16(y - __bfloat162float(hh.y));
    h = *(uint32_t*)&hh;
    l = *(uint32_t*)&ll;
}
__device__ __forceinline__ uint32_t h2pack(float x, float y) {
    __half2 p = __floats2half2_rn(x, y);
    return *(uint32_t*)&p;
}

// ---------------- weight mean(|w|) : stage 1 ----------------
__global__ void reduce_abs_kernel(const float* __restrict__ w0, const float* __restrict__ w1,
                                  const float* __restrict__ w2, float* __restrict__ part) {
    const float* w = (blockIdx.y == 0) ? w0 : ((blockIdx.y == 1) ? w1 : w2);
    int t = threadIdx.x;
    size_t base = (size_t)blockIdx.x * 4096;
    float s = 0.f;
#pragma unroll
    for (int i = 0; i < 16; i++) s += fabsf(w[base + t + i * 256]);
    __shared__ float red[256];
    red[t] = s;
    __syncthreads();
    for (int o = 128; o > 0; o >>= 1) {
        if (t < o) red[t] += red[t + o];
        __syncthreads();
    }
    if (t == 0) part[blockIdx.y * 1024 + blockIdx.x] = red[0];
}

__global__ void finalize_scale_kernel(const float* __restrict__ part, float* __restrict__ scale) {
    int w = blockIdx.x;
    int t = threadIdx.x;
    float s = part[w * 1024 + t] + part[w * 1024 + t + 256] +
              part[w * 1024 + t + 512] + part[w * 1024 + t + 768];
    __shared__ float red[256];
    red[t] = s;
    __syncthreads();
    for (int o = 128; o > 0; o >>= 1) {
        if (t < o) red[t] += red[t + o];
        __syncthreads();
    }
    if (t == 0) {
        float mean = red[0] * (1.0f / ((float)Eq * (float)Eq));
        scale[w] = fmaxf(mean, 1e-5f);
    }
}

// ---------------- merged weight prep ----------------
// wi 0..2: ternary bf16 (q/k/v). wi==1: also kw3 split [hi|lo|hi].
// wi==2: also vw16 fp16. wi==3: ow16 fp16.
__global__ void prep_weights(const float* __restrict__ qw, const float* __restrict__ kw,
                             const float* __restrict__ vw, const float* __restrict__ ow,
                             __nv_bfloat16* __restrict__ wq,
                             __nv_bfloat16* __restrict__ kw3, __half* __restrict__ vw16,
                             __half* __restrict__ ow16,
                             const float* __restrict__ scale) {
    int wi = blockIdx.y;
    const float* w = (wi == 0) ? qw : ((wi == 1) ? kw : ((wi == 2) ? vw : ow));
    float inv = (wi < 3) ? __frcp_rn(scale[wi]) : 0.f;
    size_t e0 = ((size_t)blockIdx.x * 256 + threadIdx.x) * 8;
    size_t row = e0 >> 11, col = e0 & 2047;
    __nv_bfloat16* wo = (wi < 3) ? (wq + (size_t)wi * Eq * Eq + e0) : nullptr;
    __nv_bfloat16* yr = (wi == 1) ? (kw3 + row * (size_t)(3 * Eq)) : nullptr;
    __half* h16 = (wi == 2) ? (vw16 + e0) : ((wi == 3) ? (ow16 + e0) : nullptr);
#pragma unroll
    for (int i = 0; i < 8; i += 4) {
        float4 v = *(const float4*)&w[e0 + i];
        float f[4] = {v.x, v.y, v.z, v.w};
#pragma unroll
        for (int j = 0; j < 4; j++) {
            if (wo)
                wo[i + j] = __float2bfloat16(fminf(fmaxf(rintf(f[j] * inv), -1.f), 1.f));
            if (yr) {
                __nv_bfloat16 hi = __float2bfloat16(f[j]);
                __nv_bfloat16 lo = __float2bfloat16(f[j] - __bfloat162float(hi));
                yr[col + i + j] = hi;
                yr[Eq + col + i + j] = lo;
                yr[2 * Eq + col + i + j] = hi;
            }
            if (h16) h16[i + j] = __float2half(f[j]);
        }
    }
}

// ---------------- per-token absmax quantization (warp per row, no syncs) ----------------
__global__ void quant_act_bf16(const float* __restrict__ x, __nv_bfloat16* __restrict__ xq,
                               float* __restrict__ rows) {
    int w = (blockIdx.x * blockDim.x + threadIdx.x) >> 5;  // one warp per row
    int lane = threadIdx.x & 31;
    const float* xr = x + (size_t)w * Eq;
    float4 v[16];
    float mx = 0.f;
#pragma unroll
    for (int i = 0; i < 16; i++) {
        v[i] = *(const float4*)&xr[i * 128 + lane * 4];
        mx = fmaxf(mx, fmaxf(fmaxf(fabsf(v[i].x), fabsf(v[i].y)),
                             fmaxf(fabsf(v[i].z), fabsf(v[i].w))));
    }
#pragma unroll
    for (int o = 16; o > 0; o >>= 1) mx = fmaxf(mx, __shfl_xor_sync(0xffffffffu, mx, o));
    float s = __fdiv_rn(127.0f, fmaxf(mx, 1e-5f));
    if (lane == 0) rows[w] = s;
    __nv_bfloat16* xo = xq + (size_t)w * Eq;
#pragma unroll
    for (int i = 0; i < 16; i++) {
        __nv_bfloat162 p0, p1;
        p0.x = __float2bfloat16(fminf(fmaxf(rintf(v[i].x * s), -128.f), 127.f));
        p0.y = __float2bfloat16(fminf(fmaxf(rintf(v[i].y * s), -128.f), 127.f));
        p1.x = __float2bfloat16(fminf(fmaxf(rintf(v[i].z * s), -128.f), 127.f));
        p1.y = __float2bfloat16(fminf(fmaxf(rintf(v[i].w * s), -128.f), 127.f));
        *(__nv_bfloat162*)&xo[i * 128 + lane * 4] = p0;
        *(__nv_bfloat162*)&xo[i * 128 + lane * 4 + 2] = p1;
    }
}

// ---------------- rt: split-bf16 [hi|hi|lo] (for reasoning-K) + fp16 copy (for reasoning-V) ----
__global__ void split3a(const float* __restrict__ X, __nv_bfloat16* __restrict__ Y,
                        __half* __restrict__ Y16) {
    size_t i = (size_t)blockIdx.x * 256 + threadIdx.x;
    size_t row = i >> 11, col = i & 2047;
    float x = X[i];
    __nv_bfloat16 hi = __float2bfloat16(x);
    __nv_bfloat16 lo = __float2bfloat16(x - __bfloat162float(hi));
    __nv_bfloat16* yr = Y + row * (size_t)(3 * Eq);
    yr[col] = hi;
    yr[Eq + col] = hi;
    yr[2 * Eq + col] = lo;
    Y16[i] = __float2half(x);
}

// ---------------- HMMA GEMM: cp.async 3-stage, BK=64, 2 CTAs/SM, z-batched ----------------
// fp16in: inputs are fp16 (else bf16). Output: Hout&&Lout -> split bf16; Hout -> fp16; else fp32+bias
struct GArgs {
    const __nv_bfloat16* A;
    const __nv_bfloat16* B;
    float* C;
    const float* rowscale;
    const float* wsp;
    const float* bias;
    int K, Nout, rbi, rbo, roff, ylim;
    __nv_bfloat16* Hout;
    __nv_bfloat16* Lout;
    float cmul;
    int fp16in;
};

// dynamic smem: 3 stages x (A 16K | B 16K) = 96 KB
#define SMEM_GEMM5 98304

__global__ __launch_bounds__(256, 2) void hmma_gemm5(GArgs ga0, GArgs ga1, GArgs ga2,
                                                     GArgs ga3, GArgs ga4) {
    int z = blockIdx.z;
    GArgs ga = (z == 0) ? ga0 : ((z == 1) ? ga1 : ((z == 2) ? ga2 : ((z == 3) ? ga3 : ga4)));
    if ((int)blockIdx.y >= ga.ylim) return;
    extern __shared__ __align__(128) uint8_t dsm[];
    uint32_t sb = smem_u32(dsm);
    int t = threadIdx.x;
    int lane = t & 31, wid = t >> 5;
    int m0 = blockIdx.y * 128, n0 = blockIdx.x * 128;
    int warp_m = wid & 1, warp_n = wid >> 1;
    const int K = ga.K;

    const uint8_t* asrc[4];
    const uint8_t* bsrc[4];
    uint32_t gdst[4];
#pragma unroll
    for (int i = 0; i < 4; i++) {
        int idx = t + i * 256;
        int r = idx >> 3, g = idx & 7;
        gdst[i] = (g >> 2) * 8192 + swoff(r, g & 3);
        asrc[i] = (const uint8_t*)(ga.A + (size_t)(m0 + r) * K) + g * 16;
        bsrc[i] = (const uint8_t*)(ga.B + (size_t)(n0 + r) * K) + g * 16;
    }

    uint32_t aaddr[4], baddr4[2];
#pragma unroll
    for (int mi = 0; mi < 4; mi++)
        aaddr[mi] = swoff(warp_m * 64 + mi * 16 + (lane & 15), lane >> 4);
#pragma unroll
    for (int ni2 = 0; ni2 < 2; ni2++)
        baddr4[ni2] = boff4(warp_n * 32 + ni2 * 16, lane);

    const int NK = K >> 6;
    {
#pragma unroll
        for (int i = 0; i < 4; i++) {
            cpa16(sb + gdst[i], asrc[i]);
            cpa16(sb + 16384 + gdst[i], bsrc[i]);
        }
        cpa_commit();
    }

    float c[4][4][4];
#pragma unroll
    for (int mi = 0; mi < 4; mi++)
#pragma unroll
        for (int ni = 0; ni < 4; ni++)
#pragma unroll
            for (int k = 0; k < 4; k++) c[mi][ni][k] = 0.f;

    int s = 0;
    for (int kt = 0; kt < NK; ++kt) {
        if (kt + 1 < NK) {
            int sn = (s + 1 == 3) ? 0 : s + 1;
            uint32_t base = sb + sn * 32768;
            size_t koff = (size_t)(kt + 1) * 128;
#pragma unroll
            for (int i = 0; i < 4; i++) {
                cpa16(base + gdst[i], asrc[i] + koff);
                cpa16(base + 16384 + gdst[i], bsrc[i] + koff);
            }
            cpa_commit();
            cpa_wait1();
        } else {
            cpa_wait0();
        }
        __syncthreads();

        uint32_t Ab = sb + s * 32768;
        uint32_t Bb = Ab + 16384;
        if (ga.fp16in) {
#pragma unroll
            for (int ch = 0; ch < 2; ch++)
#pragma unroll
                for (int ks = 0; ks < 2; ks++) {
                    uint32_t kx = ks * 32;
                    uint32_t a[4][4], b[2][4];
#pragma unroll
                    for (int mi = 0; mi < 4; mi++)
                        ldmx4(a[mi], Ab + ch * 8192 + (aaddr[mi] ^ kx));
#pragma unroll
                    for (int ni2 = 0; ni2 < 2; ni2++)
                        ldmx4(b[ni2], Bb + ch * 8192 + (baddr4[ni2] ^ kx));
#pragma unroll
                    for (int mi = 0; mi < 4; mi++)
#pragma unroll
                        for (int ni = 0; ni < 4; ni++)
                            mma16816h(c[mi][ni], a[mi], &b[ni >> 1][(ni & 1) * 2]);
                }
        } else {
#pragma unroll
            for (int ch = 0; ch < 2; ch++)
#pragma unroll
                for (int ks = 0; ks < 2; ks++) {
                    uint32_t kx = ks * 32;
                    uint32_t a[4][4], b[2][4];
#pragma unroll
                    for (int mi = 0; mi < 4; mi++)
                        ldmx4(a[mi], Ab + ch * 8192 + (aaddr[mi] ^ kx));
#pragma unroll
                    for (int ni2 = 0; ni2 < 2; ni2++)
                        ldmx4(b[ni2], Bb + ch * 8192 + (baddr4[ni2] ^ kx));
#pragma unroll
                    for (int mi = 0; mi < 4; mi++)
#pragma unroll
                        for (int ni = 0; ni < 4; ni++)
                            mma16816(c[mi][ni], a[mi], &b[ni >> 1][(ni & 1) * 2]);
                }
        }
        s = (s + 1 == 3) ? 0 : s + 1;
    }

    float ws = ga.cmul * (ga.wsp ? *ga.wsp : 1.0f);
    int g = lane >> 2, tg = lane & 3;
#pragma unroll
    for (int mi = 0; mi < 4; mi++) {
        int mA = m0 + warp_m * 64 + mi * 16 + g;
        int mB = mA + 8;
        float fA = ga.rowscale ? (ws / ga.rowscale[mA]) : ws;
        float fB = ga.rowscale ? (ws / ga.rowscale[mB]) : ws;
        int oA = (mA / ga.rbi) * ga.rbo + ga.roff + (mA % ga.rbi);
        int oB = (mB / ga.rbi) * ga.rbo + ga.roff + (mB % ga.rbi);
        if (ga.Hout && ga.Lout) {
            __nv_bfloat16* hA = ga.Hout + (size_t)oA * ga.Nout;
            __nv_bfloat16* hB = ga.Hout + (size_t)oB * ga.Nout;
            __nv_bfloat16* lA = ga.Lout + (size_t)oA * ga.Nout;
            __nv_bfloat16* lB = ga.Lout + (size_t)oB * ga.Nout;
#pragma unroll
            for (int ni = 0; ni < 4; ni++) {
                int col = n0 + warp_n * 32 + ni * 8 + tg * 2;
                uint32_t h0, l0v, h1, l1v;
                hl2(c[mi][ni][0] * fA, c[mi][ni][1] * fA, h0, l0v);
                hl2(c[mi][ni][2] * fB, c[mi][ni][3] * fB, h1, l1v);
                *(uint32_t*)&hA[col] = h0;
                *(uint32_t*)&lA[col] = l0v;
                *(uint32_t*)&hB[col] = h1;
                *(uint32_t*)&lB[col] = l1v;
            }
        } else if (ga.Hout) {
            __half* hA = (__half*)ga.Hout + (size_t)oA * ga.Nout;
            __half* hB = (__half*)ga.Hout + (size_t)oB * ga.Nout;
#pragma unroll
            for (int ni = 0; ni < 4; ni++) {
                int col = n0 + warp_n * 32 + ni * 8 + tg * 2;
                *(uint32_t*)&hA[col] = h2pack(c[mi][ni][0] * fA, c[mi][ni][1] * fA);
                *(uint32_t*)&hB[col] = h2pack(c[mi][ni][2] * fB, c[mi][ni][3] * fB);
            }
        } else {
            float* crA = ga.C + (size_t)oA * ga.Nout;
            float* crB = ga.C + (size_t)oB * ga.Nout;
#pragma unroll
            for (int ni = 0; ni < 4; ni++) {
                int col = n0 + warp_n * 32 + ni * 8 + tg * 2;
                float b0 = 0.f, b1 = 0.f;
                if (ga.bias) { b0 = ga.bias[col]; b1 = ga.bias[col + 1]; }
                float2 vA, vB;
                vA.x = c[mi][ni][0] * fA + b0;
                vA.y = c[mi][ni][1] * fA + b1;
                vB.x = c[mi][ni][2] * fB + b0;
                vB.y = c[mi][ni][3] * fB + b1;
                *(float2*)&crA[col] = vA;
                *(float2*)&crB[col] = vB;
            }
        }
    }
}

// ---------------- FA2 HMMA flash attention: 2 CTAs/SM, 64q/CTA, 32-key 3-stage KV ----------------
// Q pre-scaled by 1/sqrt(D). QK^T: split-bf16 3-pass. PV: single-pass fp16. O -> fp16.
#define ATT_STAGE 24576
#define SMEM_ATTN6 (3 * ATT_STAGE)   // 73728 -> 2 CTAs/SM

__global__ __launch_bounds__(128, 2) void attn_mma5(
    const __nv_bfloat16* __restrict__ Qh, const __nv_bfloat16* __restrict__ Ql,
    const __nv_bfloat16* __restrict__ Kh, const __nv_bfloat16* __restrict__ Kl,
    const __half* __restrict__ V16, __half* __restrict__ O16) {
    extern __shared__ char smg[];
    uint32_t sb = smem_u32(smg);
    int t = threadIdx.x;
    int lane = t & 31, wid = t >> 5;   // 4 warps
    int qb = blockIdx.x * 64;
    int h = blockIdx.y;
    int b = blockIdx.z;

    const int wm = wid;
    const uint32_t a_off = swoff(wm * 16 + (lane & 15), lane >> 4);
    uint32_t k4[2];
#pragma unroll
    for (int ni2 = 0; ni2 < 2; ni2++) k4[ni2] = boff4(ni2 * 16, lane);
    // trans-V per-lane address components (verified in rounds 12-14)
    const int vrow = (lane & 7) + ((lane >> 3) & 1) * 8;
    const uint32_t vbase = (uint32_t)(vrow * 64);
    const uint32_t vrx = (uint32_t)((vrow >> 1) & 3);
    const uint32_t vg = (uint32_t)((lane >> 4) & 1);
    const uint32_t ge = ((vg ^ vrx) << 4);
    const uint32_t go = (((2 + vg) ^ vrx) << 4);
    const int g4 = lane >> 2, tg = lane & 3;

    // ---- stage Q at sb+0, consume to regs, then start ring ----
    {
        const __nv_bfloat16* Qhg = Qh + ((size_t)(b * Sq + qb)) * Eq + h * Dq;
        const __nv_bfloat16* Qlg = Ql + ((size_t)(b * Sq + qb)) * Eq + h * Dq;
#pragma unroll
        for (int i = 0; i < 8; i++) {
            int idx = t + i * 128;
            int r = idx >> 4, g = idx & 15;
            uint32_t dst = (g >> 2) * 4096 + swoff(r, g & 3);
            cpa16(sb + dst, Qhg + (size_t)r * Eq + g * 8);
            cpa16(sb + 16384 + dst, Qlg + (size_t)r * Eq + g * 8);
        }
        cpa_commit();
    }
    cpa_wait0();
    __syncthreads();

    uint32_t qfh[4][2][4], qfl[4][2][4];
#pragma unroll
    for (int ch = 0; ch < 4; ch++)
#pragma unroll
        for (int ks = 0; ks < 2; ks++) {
            ldmx4(qfh[ch][ks], sb + ch * 4096 + (a_off ^ (ks * 32)));
            ldmx4(qfl[ch][ks], sb + 16384 + ch * 4096 + (a_off ^ (ks * 32)));
        }
    __syncthreads();

    const __nv_bfloat16* Khb = Kh + ((size_t)(b * Lq)) * Eq + h * Dq;
    const __nv_bfloat16* Klb = Kl + ((size_t)(b * Lq)) * Eq + h * Dq;
    const __half* Vb = V16 + ((size_t)(b * Lq)) * Eq + h * Dq;

    auto issueKV = [&](int kt) {
        uint32_t base = sb + (kt % 3) * ATT_STAGE;
        const __nv_bfloat16* KhT = Khb + (size_t)(kt * 32) * Eq;
        const __nv_bfloat16* KlT = Klb + (size_t)(kt * 32) * Eq;
        const __half* VT = Vb + (size_t)(kt * 32) * Eq;
#pragma unroll
        for (int i = 0; i < 4; i++) {
            int idx = t + i * 128;
            int r = idx >> 4, g = idx & 15;
            uint32_t dst = (g >> 2) * 2048 + swoff(r, g & 3);
            size_t src = (size_t)r * Eq + g * 8;
            cpa16(base + dst, KhT + src);
            cpa16(base + 8192 + dst, KlT + src);
            cpa16(base + 16384 + dst, VT + src);
        }
        cpa_commit();
    };
    issueKV(0);

    float m0 = -1e30f, m1 = -1e30f, l0 = 0.f, l1 = 0.f;
    float co[16][4];
#pragma unroll
    for (int i = 0; i < 16; i++)
#pragma unroll
        for (int j = 0; j < 4; j++) co[i][j] = 0.f;

    const int NT = Lq / 32;  // 68
    for (int kt = 0; kt < NT; ++kt) {
        if (kt + 1 < NT) { issueKV(kt + 1); cpa_wait1(); }
        else cpa_wait0();
        __syncthreads();
        uint32_t kvb = sb + (kt % 3) * ATT_STAGE;

        // ---- S = Qh.Kh + Qh.Kl + Ql.Kh ----
        float cs[4][4];
#pragma unroll
        for (int i = 0; i < 4; i++)
#pragma unroll
            for (int j = 0; j < 4; j++) cs[i][j] = 0.f;
#pragma unroll
        for (int ch = 0; ch < 4; ch++)
#pragma unroll
            for (int ks = 0; ks < 2; ks++) {
                uint32_t kx = ks * 32;
#pragma unroll
                for (int ni2 = 0; ni2 < 2; ni2++) {
                    uint32_t bh[4], bl[4];
                    uint32_t ba = kvb + ch * 2048 + (k4[ni2] ^ kx);
                    ldmx4(bh, ba);
                    ldmx4(bl, ba + 8192);
                    mma16816(cs[2 * ni2], qfh[ch][ks], bh);
                    mma16816(cs[2 * ni2], qfh[ch][ks], bl);
                    mma16816(cs[2 * ni2], qfl[ch][ks], bh);
                    mma16816(cs[2 * ni2 + 1], qfh[ch][ks], bh + 2);
                    mma16816(cs[2 * ni2 + 1], qfh[ch][ks], bl + 2);
                    mma16816(cs[2 * ni2 + 1], qfl[ch][ks], bh + 2);
                }
            }

        // ---- in-register softmax (32 keys) ----
        float tm0 = -1e30f, tm1 = -1e30f;
#pragma unroll
        for (int ni = 0; ni < 4; ni++) {
            tm0 = fmaxf(tm0, fmaxf(cs[ni][0], cs[ni][1]));
            tm1 = fmaxf(tm1, fmaxf(cs[ni][2], cs[ni][3]));
        }
        tm0 = fmaxf(tm0, __shfl_xor_sync(0xffffffffu, tm0, 1));
        tm0 = fmaxf(tm0, __shfl_xor_sync(0xffffffffu, tm0, 2));
        tm1 = fmaxf(tm1, __shfl_xor_sync(0xffffffffu, tm1, 1));
        tm1 = fmaxf(tm1, __shfl_xor_sync(0xffffffffu, tm1, 2));
        float nm0 = fmaxf(m0, tm0), nm1 = fmaxf(m1, tm1);
        float al0 = __expf(m0 - nm0), al1 = __expf(m1 - nm1);
        m0 = nm0; m1 = nm1;

        float rs0 = 0.f, rs1 = 0.f;
#pragma unroll
        for (int ni = 0; ni < 4; ni++) {
            cs[ni][0] = __expf(cs[ni][0] - m0); rs0 += cs[ni][0];
            cs[ni][1] = __expf(cs[ni][1] - m0); rs0 += cs[ni][1];
            cs[ni][2] = __expf(cs[ni][2] - m1); rs1 += cs[ni][2];
            cs[ni][3] = __expf(cs[ni][3] - m1); rs1 += cs[ni][3];
        }
        rs0 += __shfl_xor_sync(0xffffffffu, rs0, 1);
        rs0 += __shfl_xor_sync(0xffffffffu, rs0, 2);
        rs1 += __shfl_xor_sync(0xffffffffu, rs1, 1);
        rs1 += __shfl_xor_sync(0xffffffffu, rs1, 2);
        l0 = l0 * al0 + rs0;
        l1 = l1 * al1 + rs1;

        // ---- P fp16 A-fragments ----
        uint32_t pf[2][4];
#pragma unroll
        for (int ck = 0; ck < 2; ck++) {
            pf[ck][0] = h2pack(cs[2 * ck][0], cs[2 * ck][1]);
            pf[ck][1] = h2pack(cs[2 * ck][2], cs[2 * ck][3]);
            pf[ck][2] = h2pack(cs[2 * ck + 1][0], cs[2 * ck + 1][1]);
            pf[ck][3] = h2pack(cs[2 * ck + 1][2], cs[2 * ck + 1][3]);
        }

        // ---- rescale O ----
#pragma unroll
        for (int ni = 0; ni < 16; ni++) {
            co[ni][0] *= al0; co[ni][1] *= al0;
            co[ni][2] *= al1; co[ni][3] *= al1;
        }

        // ---- O += P.V (single-pass fp16, trans-loaded V) ----
#pragma unroll
        for (int ck = 0; ck < 2; ck++) {
            uint32_t rofs = kvb + 16384 + (uint32_t)(ck * 1024) + vbase;
#pragma unroll
            for (int ni2 = 0; ni2 < 8; ni2++) {
                uint32_t bv[4];
                ldmx4t(bv, rofs + (uint32_t)((ni2 >> 1) * 2048) + ((ni2 & 1) ? go : ge));
                mma16816h(co[2 * ni2], pf[ck], bv);
                mma16816h(co[2 * ni2 + 1], pf[ck], bv + 2);
            }
        }
    }

    // ---- epilogue: write O fp16 (single buffer) ----
    float il0 = 1.0f / l0, il1 = 1.0f / l1;
    int r0 = wm * 16 + g4, r1 = r0 + 8;
    __half* O0 = O16 + ((size_t)(b * Sq + qb + r0)) * Eq + h * Dq;
    __half* O1 = O16 + ((size_t)(b * Sq + qb + r1)) * Eq + h * Dq;
#pragma unroll
    for (int ni = 0; ni < 16; ni++) {
        int col = ni * 8 + tg * 2;
        *(uint32_t*)(O0 + col) = h2pack(co[ni][0] * il0, co[ni][1] * il0);
        *(uint32_t*)(O1 + col) = h2pack(co[ni][2] * il1, co[ni][3] * il1);
    }
}

// ---------------- host launcher ----------------
extern "C" void kernel_launch(void* const* d_in, const int* in_sizes, int n_in,
                              void* d_out, int out_size) {
    const float* x  = (const float*)d_in[0];
    const float* rt = (const float*)d_in[1];
    const float* qw = (const float*)d_in[2];
    const float* kw = (const float*)d_in[3];
    const float* vw = (const float*)d_in[4];
    const float* ow = (const float*)d_in[5];
    const float* ob = (const float*)d_in[6];
    float* out = (float*)d_out;

    __nv_bfloat16 *xbf, *wbf, *rt3, *kw3, *qh, *ql, *kh, *kl;
    __half *rt16, *vw16, *ow16, *o16, *v16;
    float *rows, *part, *scale;
    cudaGetSymbolAddress((void**)&xbf, g_xbf);
    cudaGetSymbolAddress((void**)&wbf, g_wbf);
    cudaGetSymbolAddress((void**)&rt3, g_rt3);
    cudaGetSymbolAddress((void**)&rt16, g_rt16);
    cudaGetSymbolAddress((void**)&kw3, g_kw3);
    cudaGetSymbolAddress((void**)&vw16, g_vw16);
    cudaGetSymbolAddress((void**)&ow16, g_ow16);
    cudaGetSymbolAddress((void**)&o16, g_o16);
    cudaGetSymbolAddress((void**)&qh, g_qh);
    cudaGetSymbolAddress((void**)&ql, g_ql);
    cudaGetSymbolAddress((void**)&kh, g_kh);
    cudaGetSymbolAddress((void**)&kl, g_kl);
    cudaGetSymbolAddress((void**)&v16, g_v16);
    cudaGetSymbolAddress((void**)&rows, g_rows);
    cudaGetSymbolAddress((void**)&part, g_part);
    cudaGetSymbolAddress((void**)&scale, g_scale);

    cudaFuncSetAttribute(attn_mma5, cudaFuncAttributeMaxDynamicSharedMemorySize, SMEM_ATTN6);
    cudaFuncSetAttribute(hmma_gemm5, cudaFuncAttributeMaxDynamicSharedMemorySize, SMEM_GEMM5);

    const float SCALE = 0.08838834764831845f;  // 1/sqrt(128), folded into Q epilogue

    // 1) weight scales
    reduce_abs_kernel<<<dim3(1024, 3), 256>>>(qw, kw, vw, part);
    finalize_scale_kernel<<<3, 256>>>(part, scale);
    // 2) weight prep (ternary q/k/v + kw3 split + vw16/ow16 fp16) + act quant + rt split/fp16
    prep_weights<<<dim3(2048, 4), 256>>>(qw, kw, vw, ow, wbf, kw3, vw16, ow16, scale);
    quant_act_bf16<<<(Bq * Sq) / 8, 256>>>(x, xbf, rows);
    split3a<<<(Bq * Rq * Eq) / 256, 256>>>(rt, rt3, rt16);
    // 3) QKV + reasoning projections in ONE launch (z = 0..4)
    size_t EE = (size_t)Eq * Eq;
    GArgs gQ = { xbf, wbf + 0 * EE, nullptr, rows, scale + 0, nullptr,
                 Eq, Eq, Sq, Sq, 0, 32, qh, ql, SCALE, 0 };
    GArgs gK = { xbf, wbf + 1 * EE, nullptr, rows, scale + 1, nullptr,
                 Eq, Eq, Sq, Lq, 0, 32, kh, kl, 1.0f, 0 };
    GArgs gV = { xbf, wbf + 2 * EE, nullptr, rows, scale + 2, nullptr,
                 Eq, Eq, Sq, Lq, 0, 32, (__nv_bfloat16*)v16, nullptr, 1.0f, 0 };
    GArgs gRK = { rt3, kw3, nullptr, nullptr, nullptr, nullptr,
                  3 * Eq, Eq, Rq, Lq, Sq, 2, kh, kl, 1.0f, 0 };
    GArgs gRV = { (const __nv_bfloat16*)rt16, (const __nv_bfloat16*)vw16, nullptr, nullptr,
                  nullptr, nullptr,
                  Eq, Eq, Rq, Lq, Sq, 2, (__nv_bfloat16*)v16, nullptr, 1.0f, 1 };
    hmma_gemm5<<<dim3(16, 32, 5), 256, SMEM_GEMM5>>>(gQ, gK, gV, gRK, gRV);
    // 4) attention (2 CTAs/SM, 32-key 3-stage, fp16 PV) -> writes fp16 O
    attn_mma5<<<dim3(Sq / 64, Hq, Bq), 128, SMEM_ATTN6>>>(qh, ql, kh, kl, v16, o16);
    // 5) output projection + bias: single-pass fp16, K=2048
    GArgs gO = { (const __nv_bfloat16*)o16, (const __nv_bfloat16*)ow16, out, nullptr, nullptr, ob,
                 Eq, Eq, Bq * Sq, Bq * Sq, 0, 32, nullptr, nullptr, 1.0f, 1 };
    hmma_gemm5<<<dim3(16, 32, 1), 256, SMEM_GEMM5>>>(gO, gO, gO, gO, gO);
}

// round 16
// speedup vs baseline: 2.1179x; 1.4477x over previous
#include <cuda_runtime.h>
#include <cuda_bf16.h>
#include <cuda_fp16.h>
#include <cstdint>

#define Bq 2
#define Sq 2048
#define Rq 128
#define Eq 2048
#define Hq 16
#define Dq 128
#define Lq (Sq + Rq)   // 2176

// ---------------- scratch (device globals, no allocations) ----------------
__device__ __nv_bfloat16 g_xbf[(size_t)Bq * Sq * Eq];      // quantized acts as bf16 ints
__device__ __nv_bfloat16 g_wbf[3][(size_t)Eq * Eq];        // ternary weights as bf16
__device__ __half        g_rt16[(size_t)Bq * Rq * Eq];     // reasoning tokens fp16
__device__ __half        g_kw16[(size_t)Eq * Eq];          // k_w fp16
__device__ __half        g_vw16[(size_t)Eq * Eq];          // v_w fp16
__device__ __half        g_ow16[(size_t)Eq * Eq];          // out_w fp16
__device__ __half        g_o16[(size_t)Bq * Sq * Eq];      // attention output fp16
__device__ __half        g_q16[(size_t)Bq * Sq * Eq];      // Q fp16 (pre-scaled by 1/sqrt(D))
__device__ __half        g_k16[(size_t)Bq * Lq * Eq];      // K fp16
__device__ __half        g_v16[(size_t)Bq * Lq * Eq];      // V fp16 [B,L,E]
__device__ float g_rows[(size_t)Bq * Sq];                  // per-row act scale s
__device__ float g_part[3 * 1024];
__device__ float g_scale[3];

// ---------------- PTX helpers ----------------
typedef unsigned long long ull;
__device__ __forceinline__ uint32_t smem_u32(const void* p) {
    uint32_t a;
    asm("{ .reg .u64 t; cvta.to.shared.u64 t, %1; cvt.u32.u64 %0, t; }" : "=r"(a) : "l"(p));
    return a;
}
__device__ __forceinline__ void ldmx4(uint32_t* r, uint32_t addr) {
    asm volatile("ldmatrix.sync.aligned.m8n8.x4.shared.b16 {%0,%1,%2,%3}, [%4];"
                 : "=r"(r[0]), "=r"(r[1]), "=r"(r[2]), "=r"(r[3]) : "r"(addr));
}
__device__ __forceinline__ void ldmx4t(uint32_t* r, uint32_t addr) {
    asm volatile("ldmatrix.sync.aligned.m8n8.x4.trans.shared.b16 {%0,%1,%2,%3}, [%4];"
                 : "=r"(r[0]), "=r"(r[1]), "=r"(r[2]), "=r"(r[3]) : "r"(addr));
}
__device__ __forceinline__ void mma16816(float* c, const uint32_t* a, const uint32_t* b) {
    asm volatile("mma.sync.aligned.m16n8k16.row.col.f32.bf16.bf16.f32 "
                 "{%0,%1,%2,%3}, {%4,%5,%6,%7}, {%8,%9}, {%0,%1,%2,%3};"
                 : "+f"(c[0]), "+f"(c[1]), "+f"(c[2]), "+f"(c[3])
                 : "r"(a[0]), "r"(a[1]), "r"(a[2]), "r"(a[3]), "r"(b[0]), "r"(b[1]));
}
__device__ __forceinline__ void mma16816h(float* c, const uint32_t* a, const uint32_t* b) {
    asm volatile("mma.sync.aligned.m16n8k16.row.col.f32.f16.f16.f32 "
                 "{%0,%1,%2,%3}, {%4,%5,%6,%7}, {%8,%9}, {%0,%1,%2,%3};"
                 : "+f"(c[0]), "+f"(c[1]), "+f"(c[2]), "+f"(c[3])
                 : "r"(a[0]), "r"(a[1]), "r"(a[2]), "r"(a[3]), "r"(b[0]), "r"(b[1]));
}
__device__ __forceinline__ void cpa16(uint32_t dst, const void* src) {
    asm volatile("cp.async.cg.shared.global [%0], [%1], 16;" :: "r"(dst), "l"(src) : "memory");
}
__device__ __forceinline__ void cpa_commit() {
    asm volatile("cp.async.commit_group;" ::: "memory");
}
__device__ __forceinline__ void cpa_wait0() {
    asm volatile("cp.async.wait_group 0;" ::: "memory");
}
__device__ __forceinline__ void cpa_wait1() {
    asm volatile("cp.async.wait_group 1;" ::: "memory");
}
// smem rows of 32 x 16-bit (64B); 16B group g stored at g ^ ((row>>1)&3)
__device__ __forceinline__ uint32_t swoff(int r, int g) {
    return (uint32_t)(r * 64 + ((g ^ ((r >> 1) & 3)) << 4));
}
// per-lane address offset for B-side ldmatrix.x4 (2 consecutive n-frags of 8 rows)
__device__ __forceinline__ uint32_t boff4(int base_row, int lane) {
    int r = base_row + ((lane >> 4) << 3) + (lane & 7);
    int g = (lane >> 3) & 1;
    return swoff(r, g);
}
// pack two fp32 into bf16x2 hi + residual lo
__device__ __forceinline__ void hl2(float x, float y, uint32_t& h, uint32_t& l) {
    __nv_bfloat162 hh, ll;
    hh.x = __float2bfloat16(x);
    hh.y = __float2bfloat16(y);
    ll.x = __float2bfloat16(x - __bfloat162float(hh.x));
    ll.y = __float2bfloat16(y - __bfloat162float(hh.y));
    h = *(uint32_t*)&hh;
    l = *(uint32_t*)&ll;
}
__device__ __forceinline__ uint32_t h2pack(float x, float y) {
    __half2 p = __floats2half2_rn(x, y);
    return *(uint32_t*)&p;
}

// ---------------- weight mean(|w|) : stage 1 ----------------
__global__ void reduce_abs_kernel(const float* __restrict__ w0, const float* __restrict__ w1,
                                  const float* __restrict__ w2, float* __restrict__ part) {
    const float* w = (blockIdx.y == 0) ? w0 : ((blockIdx.y == 1) ? w1 : w2);
    int t = threadIdx.x;
    size_t base = (size_t)blockIdx.x * 4096;
    float s = 0.f;
#pragma unroll
    for (int i = 0; i < 16; i++) s += fabsf(w[base + t + i * 256]);
    __shared__ float red[256];
    red[t] = s;
    __syncthreads();
    for (int o = 128; o > 0; o >>= 1) {
        if (t < o) red[t] += red[t + o];
        __syncthreads();
    }
    if (t == 0) part[blockIdx.y * 1024 + blockIdx.x] = red[0];
}

__global__ void finalize_scale_kernel(const float* __restrict__ part, float* __restrict__ scale) {
    int w = blockIdx.x;
    int t = threadIdx.x;
    float s = part[w * 1024 + t] + part[w * 1024 + t + 256] +
              part[w * 1024 + t + 512] + part[w * 1024 + t + 768];
    __shared__ float red[256];
    red[t] = s;
    __syncthreads();
    for (int o = 128; o > 0; o >>= 1) {
        if (t < o) red[t] += red[t + o];
        __syncthreads();
    }
    if (t == 0) {
        float mean = red[0] * (1.0f / ((float)Eq * (float)Eq));
        scale[w] = fmaxf(mean, 1e-5f);
    }
}

// ---------------- merged weight prep ----------------
// wi 0..2: ternary bf16 (q/k/v). wi==1: also kw16 fp16. wi==2: also vw16. wi==3: ow16.
__global__ void prep_weights(const float* __restrict__ qw, const float* __restrict__ kw,
                             const float* __restrict__ vw, const float* __restrict__ ow,
                             __nv_bfloat16* __restrict__ wq,
                             __half* __restrict__ kw16, __half* __restrict__ vw16,
                             __half* __restrict__ ow16,
                             const float* __restrict__ scale) {
    int wi = blockIdx.y;
    const float* w = (wi == 0) ? qw : ((wi == 1) ? kw : ((wi == 2) ? vw : ow));
    float inv = (wi < 3) ? __frcp_rn(scale[wi]) : 0.f;
    size_t e0 = ((size_t)blockIdx.x * 256 + threadIdx.x) * 8;
    __nv_bfloat16* wo = (wi < 3) ? (wq + (size_t)wi * Eq * Eq + e0) : nullptr;
    __half* h16 = (wi == 1) ? (kw16 + e0)
                : ((wi == 2) ? (vw16 + e0) : ((wi == 3) ? (ow16 + e0) : nullptr));
#pragma unroll
    for (int i = 0; i < 8; i += 4) {
        float4 v = *(const float4*)&w[e0 + i];
        float f[4] = {v.x, v.y, v.z, v.w};
#pragma unroll
        for (int j = 0; j < 4; j++) {
            if (wo)
                wo[i + j] = __float2bfloat16(fminf(fmaxf(rintf(f[j] * inv), -1.f), 1.f));
            if (h16) h16[i + j] = __float2half(f[j]);
        }
    }
}

// ---------------- per-token absmax quantization (warp per row, no syncs) ----------------
__global__ void quant_act_bf16(const float* __restrict__ x, __nv_bfloat16* __restrict__ xq,
                               float* __restrict__ rows) {
    int w = (blockIdx.x * blockDim.x + threadIdx.x) >> 5;  // one warp per row
    int lane = threadIdx.x & 31;
    const float* xr = x + (size_t)w * Eq;
    float4 v[16];
    float mx = 0.f;
#pragma unroll
    for (int i = 0; i < 16; i++) {
        v[i] = *(const float4*)&xr[i * 128 + lane * 4];
        mx = fmaxf(mx, fmaxf(fmaxf(fabsf(v[i].x), fabsf(v[i].y)),
                             fmaxf(fabsf(v[i].z), fabsf(v[i].w))));
    }
#pragma unroll
    for (int o = 16; o > 0; o >>= 1) mx = fmaxf(mx, __shfl_xor_sync(0xffffffffu, mx, o));
    float s = __fdiv_rn(127.0f, fmaxf(mx, 1e-5f));
    if (lane == 0) rows[w] = s;
    __nv_bfloat16* xo = xq + (size_t)w * Eq;
#pragma unroll
    for (int i = 0; i < 16; i++) {
        __nv_bfloat162 p0, p1;
        p0.x = __float2bfloat16(fminf(fmaxf(rintf(v[i].x * s), -128.f), 127.f));
        p0.y = __float2bfloat16(fminf(fmaxf(rintf(v[i].y * s), -128.f), 127.f));
        p1.x = __float2bfloat16(fminf(fmaxf(rintf(v[i].z * s), -128.f), 127.f));
        p1.y = __float2bfloat16(fminf(fmaxf(rintf(v[i].w * s), -128.f), 127.f));
        *(__nv_bfloat162*)&xo[i * 128 + lane * 4] = p0;
        *(__nv_bfloat162*)&xo[i * 128 + lane * 4 + 2] = p1;
    }
}

// ---------------- fp32 -> fp16 copy (reasoning tokens) ----------------
__global__ void to_fp16(const float* __restrict__ X, __half* __restrict__ Y) {
    size_t i = ((size_t)blockIdx.x * 256 + threadIdx.x) * 4;
    float4 v = *(const float4*)&X[i];
    *(uint32_t*)&Y[i] = h2pack(v.x, v.y);
    *(uint32_t*)&Y[i + 2] = h2pack(v.z, v.w);
}

// ---------------- HMMA GEMM: cp.async 3-stage, BK=64, 2 CTAs/SM, z-batched ----------------
// fp16in: inputs are fp16 (else bf16). Output: Hout&&Lout -> split bf16; Hout -> fp16; else fp32+bias
struct GArgs {
    const __nv_bfloat16* A;
    const __nv_bfloat16* B;
    float* C;
    const float* rowscale;
    const float* wsp;
    const float* bias;
    int K, Nout, rbi, rbo, roff, ylim;
    __nv_bfloat16* Hout;
    __nv_bfloat16* Lout;
    float cmul;
    int fp16in;
};

// dynamic smem: 3 stages x (A 16K | B 16K) = 96 KB
#define SMEM_GEMM5 98304

__global__ __launch_bounds__(256, 2) void hmma_gemm5(GArgs ga0, GArgs ga1, GArgs ga2,
                                                     GArgs ga3, GArgs ga4) {
    int z = blockIdx.z;
    GArgs ga = (z == 0) ? ga0 : ((z == 1) ? ga1 : ((z == 2) ? ga2 : ((z == 3) ? ga3 : ga4)));
    if ((int)blockIdx.y >= ga.ylim) return;
    extern __shared__ __align__(128) uint8_t dsm[];
    uint32_t sb = smem_u32(dsm);
    int t = threadIdx.x;
    int lane = t & 31, wid = t >> 5;
    int m0 = blockIdx.y * 128, n0 = blockIdx.x * 128;
    int warp_m = wid & 1, warp_n = wid >> 1;
    const int K = ga.K;

    const uint8_t* asrc[4];
    const uint8_t* bsrc[4];
    uint32_t gdst[4];
#pragma unroll
    for (int i = 0; i < 4; i++) {
        int idx = t + i * 256;
        int r = idx >> 3, g = idx & 7;
        gdst[i] = (g >> 2) * 8192 + swoff(r, g & 3);
        asrc[i] = (const uint8_t*)(ga.A + (size_t)(m0 + r) * K) + g * 16;
        bsrc[i] = (const uint8_t*)(ga.B + (size_t)(n0 + r) * K) + g * 16;
    }

    uint32_t aaddr[4], baddr4[2];
#pragma unroll
    for (int mi = 0; mi < 4; mi++)
        aaddr[mi] = swoff(warp_m * 64 + mi * 16 + (lane & 15), lane >> 4);
#pragma unroll
    for (int ni2 = 0; ni2 < 2; ni2++)
        baddr4[ni2] = boff4(warp_n * 32 + ni2 * 16, lane);

    const int NK = K >> 6;
    {
#pragma unroll
        for (int i = 0; i < 4; i++) {
            cpa16(sb + gdst[i], asrc[i]);
            cpa16(sb + 16384 + gdst[i], bsrc[i]);
        }
        cpa_commit();
    }

    float c[4][4][4];
#pragma unroll
    for (int mi = 0; mi < 4; mi++)
#pragma unroll
        for (int ni = 0; ni < 4; ni++)
#pragma unroll
            for (int k = 0; k < 4; k++) c[mi][ni][k] = 0.f;

    int s = 0;
    for (int kt = 0; kt < NK; ++kt) {
        if (kt + 1 < NK) {
            int sn = (s + 1 == 3) ? 0 : s + 1;
            uint32_t base = sb + sn * 32768;
            size_t koff = (size_t)(kt + 1) * 128;
#pragma unroll
            for (int i = 0; i < 4; i++) {
                cpa16(base + gdst[i], asrc[i] + koff);
                cpa16(base + 16384 + gdst[i], bsrc[i] + koff);
            }
            cpa_commit();
            cpa_wait1();
        } else {
            cpa_wait0();
        }
        __syncthreads();

        uint32_t Ab = sb + s * 32768;
        uint32_t Bb = Ab + 16384;
        if (ga.fp16in) {
#pragma unroll
            for (int ch = 0; ch < 2; ch++)
#pragma unroll
                for (int ks = 0; ks < 2; ks++) {
                    uint32_t kx = ks * 32;
                    uint32_t a[4][4], b[2][4];
#pragma unroll
                    for (int mi = 0; mi < 4; mi++)
                        ldmx4(a[mi], Ab + ch * 8192 + (aaddr[mi] ^ kx));
#pragma unroll
                    for (int ni2 = 0; ni2 < 2; ni2++)
                        ldmx4(b[ni2], Bb + ch * 8192 + (baddr4[ni2] ^ kx));
#pragma unroll
                    for (int mi = 0; mi < 4; mi++)
#pragma unroll
                        for (int ni = 0; ni < 4; ni++)
                            mma16816h(c[mi][ni], a[mi], &b[ni >> 1][(ni & 1) * 2]);
                }
        } else {
#pragma unroll
            for (int ch = 0; ch < 2; ch++)
#pragma unroll
                for (int ks = 0; ks < 2; ks++) {
                    uint32_t kx = ks * 32;
                    uint32_t a[4][4], b[2][4];
#pragma unroll
                    for (int mi = 0; mi < 4; mi++)
                        ldmx4(a[mi], Ab + ch * 8192 + (aaddr[mi] ^ kx));
#pragma unroll
                    for (int ni2 = 0; ni2 < 2; ni2++)
                        ldmx4(b[ni2], Bb + ch * 8192 + (baddr4[ni2] ^ kx));
#pragma unroll
                    for (int mi = 0; mi < 4; mi++)
#pragma unroll
                        for (int ni = 0; ni < 4; ni++)
                            mma16816(c[mi][ni], a[mi], &b[ni >> 1][(ni & 1) * 2]);
                }
        }
        s = (s + 1 == 3) ? 0 : s + 1;
    }

    float ws = ga.cmul * (ga.wsp ? *ga.wsp : 1.0f);
    int g = lane >> 2, tg = lane & 3;
#pragma unroll
    for (int mi = 0; mi < 4; mi++) {
        int mA = m0 + warp_m * 64 + mi * 16 + g;
        int mB = mA + 8;
        float fA = ga.rowscale ? (ws / ga.rowscale[mA]) : ws;
        float fB = ga.rowscale ? (ws / ga.rowscale[mB]) : ws;
        int oA = (mA / ga.rbi) * ga.rbo + ga.roff + (mA % ga.rbi);
        int oB = (mB / ga.rbi) * ga.rbo + ga.roff + (mB % ga.rbi);
        if (ga.Hout && ga.Lout) {
            __nv_bfloat16* hA = ga.Hout + (size_t)oA * ga.Nout;
            __nv_bfloat16* hB = ga.Hout + (size_t)oB * ga.Nout;
            __nv_bfloat16* lA = ga.Lout + (size_t)oA * ga.Nout;
            __nv_bfloat16* lB = ga.Lout + (size_t)oB * ga.Nout;
#pragma unroll
            for (int ni = 0; ni < 4; ni++) {
                int col = n0 + warp_n * 32 + ni * 8 + tg * 2;
                uint32_t h0, l0v, h1, l1v;
                hl2(c[mi][ni][0] * fA, c[mi][ni][1] * fA, h0, l0v);
                hl2(c[mi][ni][2] * fB, c[mi][ni][3] * fB, h1, l1v);
                *(uint32_t*)&hA[col] = h0;
                *(uint32_t*)&lA[col] = l0v;
                *(uint32_t*)&hB[col] = h1;
                *(uint32_t*)&lB[col] = l1v;
            }
        } else if (ga.Hout) {
            __half* hA = (__half*)ga.Hout + (size_t)oA * ga.Nout;
            __half* hB = (__half*)ga.Hout + (size_t)oB * ga.Nout;
#pragma unroll
            for (int ni = 0; ni < 4; ni++) {
                int col = n0 + warp_n * 32 + ni * 8 + tg * 2;
                *(uint32_t*)&hA[col] = h2pack(c[mi][ni][0] * fA, c[mi][ni][1] * fA);
                *(uint32_t*)&hB[col] = h2pack(c[mi][ni][2] * fB, c[mi][ni][3] * fB);
            }
        } else {
            float* crA = ga.C + (size_t)oA * ga.Nout;
            float* crB = ga.C + (size_t)oB * ga.Nout;
#pragma unroll
            for (int ni = 0; ni < 4; ni++) {
                int col = n0 + warp_n * 32 + ni * 8 + tg * 2;
                float b0 = 0.f, b1 = 0.f;
                if (ga.bias) { b0 = ga.bias[col]; b1 = ga.bias[col + 1]; }
                float2 vA, vB;
                vA.x = c[mi][ni][0] * fA + b0;
                vA.y = c[mi][ni][1] * fA + b1;
                vB.x = c[mi][ni][2] * fB + b0;
                vB.y = c[mi][ni][3] * fB + b1;
                *(float2*)&crA[col] = vA;
                *(float2*)&crB[col] = vB;
            }
        }
    }
}

// ---------------- FA2 HMMA flash attention: 3 CTAs/SM, 64q/CTA, 32-key 3-stage KV ----------------
// Q pre-scaled by 1/sqrt(D). QK^T and PV: single-pass fp16. O -> fp16.
#define ATT_STAGE 16384
#define SMEM_ATTN7 (3 * ATT_STAGE)   // 49152 -> 3 CTAs/SM

__global__ __launch_bounds__(128, 3) void attn_mma6(
    const __half* __restrict__ Q16, const __half* __restrict__ K16,
    const __half* __restrict__ V16, __half* __restrict__ O16) {
    extern __shared__ char smg[];
    uint32_t sb = smem_u32(smg);
    int t = threadIdx.x;
    int lane = t & 31, wid = t >> 5;   // 4 warps
    int qb = blockIdx.x * 64;
    int h = blockIdx.y;
    int b = blockIdx.z;

    const int wm = wid;
    const uint32_t a_off = swoff(wm * 16 + (lane & 15), lane >> 4);
    uint32_t k4[2];
#pragma unroll
    for (int ni2 = 0; ni2 < 2; ni2++) k4[ni2] = boff4(ni2 * 16, lane);
    // trans-V per-lane address components (verified in rounds 12-15)
    const int vrow = (lane & 7) + ((lane >> 3) & 1) * 8;
    const uint32_t vbase = (uint32_t)(vrow * 64);
    const uint32_t vrx = (uint32_t)((vrow >> 1) & 3);
    const uint32_t vg = (uint32_t)((lane >> 4) & 1);
    const uint32_t ge = ((vg ^ vrx) << 4);
    const uint32_t go = (((2 + vg) ^ vrx) << 4);
    const int g4 = lane >> 2, tg = lane & 3;

    // ---- stage Q (64 rows x 128 d fp16 = 16KB) at sb+0, consume to regs, then start ring ----
    {
        const __half* Qg = Q16 + ((size_t)(b * Sq + qb)) * Eq + h * Dq;
#pragma unroll
        for (int i = 0; i < 8; i++) {
            int idx = t + i * 128;
            int r = idx >> 4, g = idx & 15;
            uint32_t dst = (g >> 2) * 4096 + swoff(r, g & 3);
            cpa16(sb + dst, Qg + (size_t)r * Eq + g * 8);
        }
        cpa_commit();
    }
    cpa_wait0();
    __syncthreads();

    uint32_t qf[4][2][4];
#pragma unroll
    for (int ch = 0; ch < 4; ch++)
#pragma unroll
        for (int ks = 0; ks < 2; ks++)
            ldmx4(qf[ch][ks], sb + ch * 4096 + (a_off ^ (ks * 32)));
    __syncthreads();   // all warps done reading Q staging before stage 0 overwrite

    const __half* Kb = K16 + ((size_t)(b * Lq)) * Eq + h * Dq;
    const __half* Vb = V16 + ((size_t)(b * Lq)) * Eq + h * Dq;

    auto issueKV = [&](int kt) {
        uint32_t base = sb + (kt % 3) * ATT_STAGE;
        const __half* KT = Kb + (size_t)(kt * 32) * Eq;
        const __half* VT = Vb + (size_t)(kt * 32) * Eq;
#pragma unroll
        for (int i = 0; i < 4; i++) {
            int idx = t + i * 128;
            int r = idx >> 4, g = idx & 15;
            uint32_t dst = (g >> 2) * 2048 + swoff(r, g & 3);
            size_t src = (size_t)r * Eq + g * 8;
            cpa16(base + dst, KT + src);
            cpa16(base + 8192 + dst, VT + src);
        }
        cpa_commit();
    };
    issueKV(0);

    float m0 = -1e30f, m1 = -1e30f, l0 = 0.f, l1 = 0.f;
    float co[16][4];
#pragma unroll
    for (int i = 0; i < 16; i++)
#pragma unroll
        for (int j = 0; j < 4; j++) co[i][j] = 0.f;

    const int NT = Lq / 32;  // 68
    for (int kt = 0; kt < NT; ++kt) {
        if (kt + 1 < NT) { issueKV(kt + 1); cpa_wait1(); }
        else cpa_wait0();
        __syncthreads();
        uint32_t kvb = sb + (kt % 3) * ATT_STAGE;

        // ---- S = Q.K (single-pass fp16, already scaled via Q) ----
        float cs[4][4];
#pragma unroll
        for (int i = 0; i < 4; i++)
#pragma unroll
            for (int j = 0; j < 4; j++) cs[i][j] = 0.f;
#pragma unroll
        for (int ch = 0; ch < 4; ch++)
#pragma unroll
            for (int ks = 0; ks < 2; ks++) {
                uint32_t kx = ks * 32;
#pragma unroll
                for (int ni2 = 0; ni2 < 2; ni2++) {
                    uint32_t bk[4];
                    ldmx4(bk, kvb + ch * 2048 + (k4[ni2] ^ kx));
                    mma16816h(cs[2 * ni2], qf[ch][ks], bk);
                    mma16816h(cs[2 * ni2 + 1], qf[ch][ks], bk + 2);
                }
            }

        // ---- in-register softmax (32 keys) ----
        float tm0 = -1e30f, tm1 = -1e30f;
#pragma unroll
        for (int ni = 0; ni < 4; ni++) {
            tm0 = fmaxf(tm0, fmaxf(cs[ni][0], cs[ni][1]));
            tm1 = fmaxf(tm1, fmaxf(cs[ni][2], cs[ni][3]));
        }
        tm0 = fmaxf(tm0, __shfl_xor_sync(0xffffffffu, tm0, 1));
        tm0 = fmaxf(tm0, __shfl_xor_sync(0xffffffffu, tm0, 2));
        tm1 = fmaxf(tm1, __shfl_xor_sync(0xffffffffu, tm1, 1));
        tm1 = fmaxf(tm1, __shfl_xor_sync(0xffffffffu, tm1, 2));
        float nm0 = fmaxf(m0, tm0), nm1 = fmaxf(m1, tm1);
        float al0 = __expf(m0 - nm0), al1 = __expf(m1 - nm1);
        m0 = nm0; m1 = nm1;

        float rs0 = 0.f, rs1 = 0.f;
#pragma unroll
        for (int ni = 0; ni < 4; ni++) {
            cs[ni][0] = __expf(cs[ni][0] - m0); rs0 += cs[ni][0];
            cs[ni][1] = __expf(cs[ni][1] - m0); rs0 += cs[ni][1];
            cs[ni][2] = __expf(cs[ni][2] - m1); rs1 += cs[ni][2];
            cs[ni][3] = __expf(cs[ni][3] - m1); rs1 += cs[ni][3];
        }
        rs0 += __shfl_xor_sync(0xffffffffu, rs0, 1);
        rs0 += __shfl_xor_sync(0xffffffffu, rs0, 2);
        rs1 += __shfl_xor_sync(0xffffffffu, rs1, 1);
        rs1 += __shfl_xor_sync(0xffffffffu, rs1, 2);
        l0 = l0 * al0 + rs0;
        l1 = l1 * al1 + rs1;

        // ---- P fp16 A-fragments ----
        uint32_t pf[2][4];
#pragma unroll
        for (int ck = 0; ck < 2; ck++) {
            pf[ck][0] = h2pack(cs[2 * ck][0], cs[2 * ck][1]);
            pf[ck][1] = h2pack(cs[2 * ck][2], cs[2 * ck][3]);
            pf[ck][2] = h2pack(cs[2 * ck + 1][0], cs[2 * ck + 1][1]);
            pf[ck][3] = h2pack(cs[2 * ck + 1][2], cs[2 * ck + 1][3]);
        }

        // ---- rescale O ----
#pragma unroll
        for (int ni = 0; ni < 16; ni++) {
            co[ni][0] *= al0; co[ni][1] *= al0;
            co[ni][2] *= al1; co[ni][3] *= al1;
        }

        // ---- O += P.V (single-pass fp16, trans-loaded V) ----
#pragma unroll
        for (int ck = 0; ck < 2; ck++) {
            uint32_t rofs = kvb + 8192 + (uint32_t)(ck * 1024) + vbase;
#pragma unroll
            for (int ni2 = 0; ni2 < 8; ni2++) {
                uint32_t bv[4];
                ldmx4t(bv, rofs + (uint32_t)((ni2 >> 1) * 2048) + ((ni2 & 1) ? go : ge));
                mma16816h(co[2 * ni2], pf[ck], bv);
                mma16816h(co[2 * ni2 + 1], pf[ck], bv + 2);
            }
        }
    }

    // ---- epilogue: write O fp16 ----
    float il0 = 1.0f / l0, il1 = 1.0f / l1;
    int r0 = wm * 16 + g4, r1 = r0 + 8;
    __half* O0 = O16 + ((size_t)(b * Sq + qb + r0)) * Eq + h * Dq;
    __half* O1 = O16 + ((size_t)(b * Sq + qb + r1)) * Eq + h * Dq;
#pragma unroll
    for (int ni = 0; ni < 16; ni++) {
        int col = ni * 8 + tg * 2;
        *(uint32_t*)(O0 + col) = h2pack(co[ni][0] * il0, co[ni][1] * il0);
        *(uint32_t*)(O1 + col) = h2pack(co[ni][2] * il1, co[ni][3] * il1);
    }
}

// ---------------- host launcher ----------------
extern "C" void kernel_launch(void* const* d_in, const int* in_sizes, int n_in,
                              void* d_out, int out_size) {
    const float* x  = (const float*)d_in[0];
    const float* rt = (const float*)d_in[1];
    const float* qw = (const float*)d_in[2];
    const float* kw = (const float*)d_in[3];
    const float* vw = (const float*)d_in[4];
    const float* ow = (const float*)d_in[5];
    const float* ob = (const float*)d_in[6];
    float* out = (float*)d_out;

    __nv_bfloat16 *xbf, *wbf;
    __half *rt16, *kw16, *vw16, *ow16, *o16, *q16, *k16, *v16;
    float *rows, *part, *scale;
    cudaGetSymbolAddress((void**)&xbf, g_xbf);
    cudaGetSymbolAddress((void**)&wbf, g_wbf);
    cudaGetSymbolAddress((void**)&rt16, g_rt16);
    cudaGetSymbolAddress((void**)&kw16, g_kw16);
    cudaGetSymbolAddress((void**)&vw16, g_vw16);
    cudaGetSymbolAddress((void**)&ow16, g_ow16);
    cudaGetSymbolAddress((void**)&o16, g_o16);
    cudaGetSymbolAddress((void**)&q16, g_q16);
    cudaGetSymbolAddress((void**)&k16, g_k16);
    cudaGetSymbolAddress((void**)&v16, g_v16);
    cudaGetSymbolAddress((void**)&rows, g_rows);
    cudaGetSymbolAddress((void**)&part, g_part);
    cudaGetSymbolAddress((void**)&scale, g_scale);

    cudaFuncSetAttribute(attn_mma6, cudaFuncAttributeMaxDynamicSharedMemorySize, SMEM_ATTN7);
    cudaFuncSetAttribute(hmma_gemm5, cudaFuncAttributeMaxDynamicSharedMemorySize, SMEM_GEMM5);

    const float SCALE = 0.08838834764831845f;  // 1/sqrt(128), folded into Q epilogue

    // 1) weight scales
    reduce_abs_kernel<<<dim3(1024, 3), 256>>>(qw, kw, vw, part);
    finalize_scale_kernel<<<3, 256>>>(part, scale);
    // 2) weight prep (ternary q/k/v + kw16/vw16/ow16 fp16) + act quant + rt fp16
    prep_weights<<<dim3(2048, 4), 256>>>(qw, kw, vw, ow, wbf, kw16, vw16, ow16, scale);
    quant_act_bf16<<<(Bq * Sq) / 8, 256>>>(x, xbf, rows);
    to_fp16<<<(Bq * Rq * Eq) / 1024, 256>>>(rt, rt16);
    // 3) QKV + reasoning projections in ONE launch (z = 0..4); Q/K/V all write fp16
    size_t EE = (size_t)Eq * Eq;
    GArgs gQ = { xbf, wbf + 0 * EE, nullptr, rows, scale + 0, nullptr,
                 Eq, Eq, Sq, Sq, 0, 32, (__nv_bfloat16*)q16, nullptr, SCALE, 0 };
    GArgs gK = { xbf, wbf + 1 * EE, nullptr, rows, scale + 1, nullptr,
                 Eq, Eq, Sq, Lq, 0, 32, (__nv_bfloat16*)k16, nullptr, 1.0f, 0 };
    GArgs gV = { xbf, wbf + 2 * EE, nullptr, rows, scale + 2, nullptr,
                 Eq, Eq, Sq, Lq, 0, 32, (__nv_bfloat16*)v16, nullptr, 1.0f, 0 };
    GArgs gRK = { (const __nv_bfloat16*)rt16, (const __nv_bfloat16*)kw16, nullptr, nullptr,
                  nullptr, nullptr,
                  Eq, Eq, Rq, Lq, Sq, 2, (__nv_bfloat16*)k16, nullptr, 1.0f, 1 };
    GArgs gRV = { (const __nv_bfloat16*)rt16, (const __nv_bfloat16*)vw16, nullptr, nullptr,
                  nullptr, nullptr,
                  Eq, Eq, Rq, Lq, Sq, 2, (__nv_bfloat16*)v16, nullptr, 1.0f, 1 };
    hmma_gemm5<<<dim3(16, 32, 5), 256, SMEM_GEMM5>>>(gQ, gK, gV, gRK, gRV);
    // 4) attention (3 CTAs/SM, 32-key 3-stage, fp16 QK + fp16 PV) -> writes fp16 O
    attn_mma6<<<dim3(Sq / 64, Hq, Bq), 128, SMEM_ATTN7>>>(q16, k16, v16, o16);
    // 5) output projection + bias: single-pass fp16, K=2048
    GArgs gO = { (const __nv_bfloat16*)o16, (const __nv_bfloat16*)ow16, out, nullptr, nullptr, ob,
                 Eq, Eq, Bq * Sq, Bq * Sq, 0, 32, nullptr, nullptr, 1.0f, 1 };
    hmma_gemm5<<<dim3(16, 32, 1), 256, SMEM_GEMM5>>>(gO, gO, gO, gO, gO);
}